// round 6
// baseline (speedup 1.0000x reference)
#include <cuda_runtime.h>
#include <cuda_fp16.h>
#include <cstdint>

// Problem constants
#define Bb 4
#define Cc 256
#define C2v 128
#define Nn 4096

// ---------------------------------------------------------------------------
// Scratch (__device__ globals; allocation-free rule)
// ---------------------------------------------------------------------------
__device__ __half g_qc[(size_t)Bb * Nn * 384];   // [B][n][384] = [qh|ql|qh]
__device__ __half g_kc[(size_t)Bb * Nn * 384];   // [B][n][384] = [kh|kh|kl] (masked)
__device__ __half g_vb[(size_t)Bb * Cc * Nn];    // [B][c][n]  (K-major for AV)
__device__ float  g_att[(size_t)Bb * Nn * Nn];   // energy fp32
__device__ __half g_attb[(size_t)Bb * Nn * Nn];  // attention fp16

// ---------------------------------------------------------------------------
// Helpers
// ---------------------------------------------------------------------------
__device__ __forceinline__ uint32_t smem_u32(const void* p) {
    uint32_t a;
    asm("{ .reg .u64 t; cvta.to.shared.u64 t, %1; cvt.u32.u64 %0, t; }" : "=r"(a) : "l"(p));
    return a;
}
__device__ __forceinline__ void cp_async16(uint32_t dst, const void* src) {
    asm volatile("cp.async.cg.shared.global [%0], [%1], 16;" :: "r"(dst), "l"(src));
}
#define CP_COMMIT() asm volatile("cp.async.commit_group;" ::: "memory")
template <int N>
__device__ __forceinline__ void cp_wait() {
    asm volatile("cp.async.wait_group %0;" :: "n"(N) : "memory");
}
__device__ __forceinline__ void ldmx4(uint32_t* r, uint32_t addr) {
    asm volatile("ldmatrix.sync.aligned.m8n8.x4.shared.b16 {%0,%1,%2,%3}, [%4];"
        : "=r"(r[0]), "=r"(r[1]), "=r"(r[2]), "=r"(r[3]) : "r"(addr));
}
__device__ __forceinline__ void mma16816(float* d, const uint32_t* a, uint32_t b0, uint32_t b1) {
    asm volatile(
        "mma.sync.aligned.m16n8k16.row.col.f32.f16.f16.f32 "
        "{%0,%1,%2,%3},{%4,%5,%6,%7},{%8,%9},{%0,%1,%2,%3};"
        : "+f"(d[0]), "+f"(d[1]), "+f"(d[2]), "+f"(d[3])
        : "r"(a[0]), "r"(a[1]), "r"(a[2]), "r"(a[3]), "r"(b0), "r"(b1));
}

// Fast exp (FFMA-only)
__device__ __forceinline__ float fexp(float x) {
    float t = fmaxf(x * 1.4426950408889634f, -126.0f);
    float fi = floorf(t);
    float f = t - fi;
    float p = 0.0013333558f;
    p = fmaf(p, f, 0.0096181291f);
    p = fmaf(p, f, 0.0555041087f);
    p = fmaf(p, f, 0.2402265069f);
    p = fmaf(p, f, 0.6931471806f);
    p = fmaf(p, f, 1.0f);
    return p * __int_as_float(((int)fi + 127) << 23);
}

// ---------------------------------------------------------------------------
// GEMM tile geometry (both MMA kernels): 128x128 block, BK=32, 8 warps (2x4)
// smem tile: 128 rows x 32 fp16, row stride 40 halves (80B)
// 3-stage cp.async ring in dynamic smem: stage = A(10240) + B(10240)
// ---------------------------------------------------------------------------
#define ROWB 80                 // bytes per smem tile row
#define TILE_B (128 * ROWB)     // 10240 per operand tile
#define STAGE_PAIR (2 * TILE_B) // 20480 per stage (A+B)
#define NSTAGE 3
#define DYN_SMEM (NSTAGE * STAGE_PAIR)  // 61440

// Load one 128x32 fp16 tile (row-major src, stride elems) into smem tile.
__device__ __forceinline__ void load_tile(uint32_t dst, const __half* src,
                                          size_t stride, int tid)
{
    #pragma unroll
    for (int i = 0; i < 2; i++) {
        int idx = tid + i * 256;          // 0..511
        int row = idx >> 2, c16 = idx & 3;
        cp_async16(dst + row * ROWB + c16 * 16, src + (size_t)row * stride + c16 * 8);
    }
}

// One BK=32 compute step for a warp: acc[4][4][4] += A(64x32) * B(32x32)^T
// A tile rows = GEMM M, B tile rows = GEMM N; both [row][k] in smem.
__device__ __forceinline__ void warp_mma_step(float acc[4][4][4], uint32_t abase,
                                              uint32_t bbase, int wy, int wx, int lane)
{
    #pragma unroll
    for (int ks = 0; ks < 2; ks++) {
        uint32_t a[4][4];
        #pragma unroll
        for (int mf = 0; mf < 4; mf++) {
            int row = wy * 64 + mf * 16 + (lane & 15);
            ldmx4(a[mf], abase + row * ROWB + ks * 32 + ((lane >> 4) << 4));
        }
        uint32_t bf[2][4];
        #pragma unroll
        for (int np = 0; np < 2; np++) {
            int row = wx * 32 + np * 16 + (lane & 7) + ((lane >> 4) << 3);
            ldmx4(bf[np], bbase + row * ROWB + ks * 32 + (((lane >> 3) & 1) << 4));
        }
        #pragma unroll
        for (int mf = 0; mf < 4; mf++)
            #pragma unroll
            for (int nf = 0; nf < 4; nf++)
                mma16816(acc[mf][nf], a[mf],
                         bf[nf >> 1][(nf & 1) * 2], bf[nf >> 1][(nf & 1) * 2 + 1]);
    }
}

// Drain-aware wait for ring-3: ensure load group for stage s is complete.
__device__ __forceinline__ void ring_wait(int s, int NK) {
    int rem = NK - 1 - s;
    if (rem >= 2) cp_wait<2>();
    else if (rem == 1) cp_wait<1>();
    else cp_wait<0>();
}

// ---------------------------------------------------------------------------
// Kernel 1: projections (SIMT fp32) -> fp16 operands  (unchanged, passing)
// ---------------------------------------------------------------------------
#define BK 8
#define SSTR 132

__global__ __launch_bounds__(256) void proj_kernel(
    const float* __restrict__ x, const float* __restrict__ mask,
    const float* __restrict__ skin,
    const float* __restrict__ Wq, const float* __restrict__ bq,
    const float* __restrict__ Wk, const float* __restrict__ bk,
    const float* __restrict__ Wv, const float* __restrict__ bv)
{
    __shared__ float As[BK * SSTR];
    __shared__ float Bs[BK * SSTR];

    const int b    = blockIdx.z;
    const int m0   = blockIdx.y * 128;
    const int oblk = blockIdx.x;   // 0:q, 1:k, 2,3:v

    const float* Wp; const float* biasp; int orow0;
    if (oblk == 0)      { Wp = Wq; biasp = bq; orow0 = 0; }
    else if (oblk == 1) { Wp = Wk; biasp = bk; orow0 = 0; }
    else                { Wp = Wv; biasp = bv; orow0 = (oblk - 2) * 128; }

    const int tid = threadIdx.x;
    const int tx = tid & 15, ty = tid >> 4;
    const float* xb = x + (size_t)b * Cc * Nn;

    const int a_k = tid >> 5;
    const int a_m = (tid & 31) * 4;
    const int b_o = tid >> 1;
    const int b_kg = (tid & 1) * 4;

    float acc[8][8] = {};

    for (int k0 = 0; k0 < Cc; k0 += BK) {
        float4 av = *reinterpret_cast<const float4*>(xb + (size_t)(k0 + a_k) * Nn + m0 + a_m);
        *reinterpret_cast<float4*>(&As[a_k * SSTR + a_m]) = av;
        float4 wv = *reinterpret_cast<const float4*>(Wp + (size_t)(orow0 + b_o) * Cc + k0 + b_kg);
        Bs[(b_kg + 0) * SSTR + b_o] = wv.x;
        Bs[(b_kg + 1) * SSTR + b_o] = wv.y;
        Bs[(b_kg + 2) * SSTR + b_o] = wv.z;
        Bs[(b_kg + 3) * SSTR + b_o] = wv.w;
        __syncthreads();
        #pragma unroll
        for (int k = 0; k < BK; k++) {
            float4 a0 = *reinterpret_cast<const float4*>(&As[k * SSTR + ty * 8]);
            float4 a1 = *reinterpret_cast<const float4*>(&As[k * SSTR + ty * 8 + 4]);
            float4 b0 = *reinterpret_cast<const float4*>(&Bs[k * SSTR + tx * 8]);
            float4 b1 = *reinterpret_cast<const float4*>(&Bs[k * SSTR + tx * 8 + 4]);
            float a[8] = {a0.x, a0.y, a0.z, a0.w, a1.x, a1.y, a1.z, a1.w};
            float bb[8] = {b0.x, b0.y, b0.z, b0.w, b1.x, b1.y, b1.z, b1.w};
            #pragma unroll
            for (int i = 0; i < 8; i++)
                #pragma unroll
                for (int j = 0; j < 8; j++)
                    acc[i][j] = fmaf(a[i], bb[j], acc[i][j]);
        }
        __syncthreads();
    }

    const int obase = tx * 8;
    float bias[8];
    #pragma unroll
    for (int j = 0; j < 8; j++) bias[j] = biasp[orow0 + obase + j];

    if (oblk <= 1) {
        #pragma unroll
        for (int i = 0; i < 8; i++) {
            const int m = m0 + ty * 8 + i;
            float f = 1.0f;
            if (oblk == 1) f = (1.0f - mask[b * Nn + m]) * skin[b * Nn + m];
            __half h8[8], l8[8];
            #pragma unroll
            for (int j = 0; j < 8; j++) {
                float r = (acc[i][j] + bias[j]) * f;
                __half h = __float2half(r);
                h8[j] = h;
                l8[j] = __float2half(r - __half2float(h));
            }
            const size_t off = ((size_t)b * Nn + m) * 384 + obase;
            if (oblk == 0) {
                // qc = [qh | ql | qh]
                *reinterpret_cast<float4*>(g_qc + off)       = *reinterpret_cast<float4*>(h8);
                *reinterpret_cast<float4*>(g_qc + off + 128) = *reinterpret_cast<float4*>(l8);
                *reinterpret_cast<float4*>(g_qc + off + 256) = *reinterpret_cast<float4*>(h8);
            } else {
                // kc = [kh | kh | kl]
                *reinterpret_cast<float4*>(g_kc + off)       = *reinterpret_cast<float4*>(h8);
                *reinterpret_cast<float4*>(g_kc + off + 128) = *reinterpret_cast<float4*>(h8);
                *reinterpret_cast<float4*>(g_kc + off + 256) = *reinterpret_cast<float4*>(l8);
            }
        }
    } else {
        // v: [c][n] layout, 8 consecutive n per store
        #pragma unroll
        for (int j = 0; j < 8; j++) {
            const int c = orow0 + obase + j;
            __half h8[8];
            #pragma unroll
            for (int i = 0; i < 8; i++) h8[i] = __float2half(acc[i][j] + bias[j]);
            const size_t off = ((size_t)b * Cc + c) * Nn + m0 + ty * 8;
            *reinterpret_cast<float4*>(g_vb + off) = *reinterpret_cast<float4*>(h8);
        }
    }
}

// ---------------------------------------------------------------------------
// Kernel 2: QK^T energy via mma.sync fp16, K=384 split-fp16; 3-stage ring
// grid (32 ntile, 32 mtile, B), 256 threads, dynamic smem 61440
// ---------------------------------------------------------------------------
__global__ __launch_bounds__(256) void qk_kernel()
{
    extern __shared__ __align__(128) char dynsm[];
    const int b = blockIdx.z, m0 = blockIdx.y * 128, n0 = blockIdx.x * 128;
    const int tid = threadIdx.x, wid = tid >> 5, lane = tid & 31;
    const int wy = wid >> 2, wx = wid & 3;
    const uint32_t sb = smem_u32(dynsm);

    const __half* Asrc = g_qc + ((size_t)b * Nn + m0) * 384;
    const __half* Bsrc = g_kc + ((size_t)b * Nn + n0) * 384;

    const int NK = 384 / 32;   // 12
    #pragma unroll
    for (int s = 0; s < NSTAGE; s++) {
        uint32_t st = sb + s * STAGE_PAIR;
        load_tile(st, Asrc + s * 32, 384, tid);
        load_tile(st + TILE_B, Bsrc + s * 32, 384, tid);
        CP_COMMIT();
    }

    float acc[4][4][4] = {};
    #pragma unroll 1
    for (int s = 0; s < NK; s++) {
        ring_wait(s, NK);
        __syncthreads();
        const uint32_t st = sb + (uint32_t)(s % NSTAGE) * STAGE_PAIR;
        warp_mma_step(acc, st, st + TILE_B, wy, wx, lane);
        __syncthreads();
        if (s + NSTAGE < NK) {
            load_tile(st, Asrc + (s + NSTAGE) * 32, 384, tid);
            load_tile(st + TILE_B, Bsrc + (s + NSTAGE) * 32, 384, tid);
            CP_COMMIT();
        }
    }

    // Epilogue: fp32 energy, float2 stores
    #pragma unroll
    for (int mf = 0; mf < 4; mf++) {
        const int m = m0 + wy * 64 + mf * 16 + (lane >> 2);
        #pragma unroll
        for (int nf = 0; nf < 4; nf++) {
            const int n = n0 + wx * 32 + nf * 8 + (lane & 3) * 2;
            float* p0 = g_att + ((size_t)b * Nn + m) * Nn + n;
            float* p1 = g_att + ((size_t)b * Nn + m + 8) * Nn + n;
            *reinterpret_cast<float2*>(p0) = make_float2(acc[mf][nf][0], acc[mf][nf][1]);
            *reinterpret_cast<float2*>(p1) = make_float2(acc[mf][nf][2], acc[mf][nf][3]);
        }
    }
}

// ---------------------------------------------------------------------------
// Kernel 3: row softmax (fp32 in -> fp16 out)  (unchanged, passing)
// ---------------------------------------------------------------------------
__global__ __launch_bounds__(256) void softmax_kernel()
{
    const size_t row = blockIdx.x;
    const float* p = g_att + row * (size_t)Nn;
    __half* pb = g_attb + row * (size_t)Nn;
    const int t = threadIdx.x;

    float v[16];
    {
        const float4* pr = reinterpret_cast<const float4*>(p + t * 16);
        float4 a0 = pr[0], a1 = pr[1], a2 = pr[2], a3 = pr[3];
        v[0]=a0.x; v[1]=a0.y; v[2]=a0.z; v[3]=a0.w;
        v[4]=a1.x; v[5]=a1.y; v[6]=a1.z; v[7]=a1.w;
        v[8]=a2.x; v[9]=a2.y; v[10]=a2.z; v[11]=a2.w;
        v[12]=a3.x; v[13]=a3.y; v[14]=a3.z; v[15]=a3.w;
    }
    float mx = v[0];
    #pragma unroll
    for (int i = 1; i < 16; i++) mx = fmaxf(mx, v[i]);
    #pragma unroll
    for (int o = 16; o; o >>= 1) mx = fmaxf(mx, __shfl_xor_sync(0xffffffffu, mx, o));

    __shared__ float red[8];
    __shared__ float bmax, binv;
    if ((t & 31) == 0) red[t >> 5] = mx;
    __syncthreads();
    if (t == 0) {
        float m2 = red[0];
        #pragma unroll
        for (int w = 1; w < 8; w++) m2 = fmaxf(m2, red[w]);
        bmax = m2;
    }
    __syncthreads();
    mx = bmax;

    float s = 0.0f;
    #pragma unroll
    for (int i = 0; i < 16; i++) { v[i] = fexp(v[i] - mx); s += v[i]; }
    #pragma unroll
    for (int o = 16; o; o >>= 1) s += __shfl_xor_sync(0xffffffffu, s, o);
    if ((t & 31) == 0) red[t >> 5] = s;
    __syncthreads();
    if (t == 0) {
        float s2 = 0.0f;
        #pragma unroll
        for (int w = 0; w < 8; w++) s2 += red[w];
        binv = 1.0f / s2;
    }
    __syncthreads();
    const float inv = binv;

    __half h[16];
    #pragma unroll
    for (int i = 0; i < 16; i++) h[i] = __float2half(v[i] * inv);
    float4* po = reinterpret_cast<float4*>(pb + t * 16);
    po[0] = reinterpret_cast<float4*>(h)[0];
    po[1] = reinterpret_cast<float4*>(h)[1];
}

// ---------------------------------------------------------------------------
// Kernel 4: AV via mma.sync fp16 + fused epilogue; 3-stage ring
// grid (2 ctile, 32 mtile, B), 256 threads, dynamic smem 61440
// ---------------------------------------------------------------------------
__global__ __launch_bounds__(256) void av_kernel(
    const float* __restrict__ x, const float* __restrict__ mask,
    const float* __restrict__ skin, const float* __restrict__ gamma,
    float* __restrict__ out)
{
    extern __shared__ __align__(128) char dynsm[];
    __shared__ float fmv[128];
    const int b = blockIdx.z, m0 = blockIdx.y * 128, c0 = blockIdx.x * 128;
    const int tid = threadIdx.x, wid = tid >> 5, lane = tid & 31;
    const int wy = wid >> 2, wx = wid & 3;
    const uint32_t sb = smem_u32(dynsm);

    if (tid < 128)
        fmv[tid] = mask[(size_t)b * Nn + m0 + tid] * skin[(size_t)b * Nn + m0 + tid];

    const __half* Asrc = g_attb + ((size_t)b * Nn + m0) * Nn;
    const __half* Bsrc = g_vb + ((size_t)b * Cc + c0) * Nn;

    const int NK = Nn / 32;   // 128
    #pragma unroll
    for (int s = 0; s < NSTAGE; s++) {
        uint32_t st = sb + s * STAGE_PAIR;
        load_tile(st, Asrc + s * 32, Nn, tid);
        load_tile(st + TILE_B, Bsrc + s * 32, Nn, tid);
        CP_COMMIT();
    }

    float acc[4][4][4] = {};
    #pragma unroll 1
    for (int s = 0; s < NK; s++) {
        ring_wait(s, NK);
        __syncthreads();
        const uint32_t st = sb + (uint32_t)(s % NSTAGE) * STAGE_PAIR;
        warp_mma_step(acc, st, st + TILE_B, wy, wx, lane);
        __syncthreads();
        if (s + NSTAGE < NK) {
            load_tile(st, Asrc + (s + NSTAGE) * 32, Nn, tid);
            load_tile(st + TILE_B, Bsrc + (s + NSTAGE) * 32, Nn, tid);
            CP_COMMIT();
        }
    }

    // Fused epilogue: out[c][m] = gamma*fm[m]*D[m][c] + x[c][m]
    const float gm = __ldg(gamma);
    #pragma unroll
    for (int mf = 0; mf < 4; mf++) {
        const int ml = wy * 64 + mf * 16 + (lane >> 2);    // local m (0..127)
        const float f0 = gm * fmv[ml];
        const float f1 = gm * fmv[ml + 8];
        #pragma unroll
        for (int nf = 0; nf < 4; nf++) {
            const int c = c0 + wx * 32 + nf * 8 + (lane & 3) * 2;
            const size_t b0i = ((size_t)b * Cc + c) * Nn + m0 + ml;
            const size_t b1i = b0i + Nn;   // c+1
            out[b0i]     = fmaf(f0, acc[mf][nf][0], x[b0i]);
            out[b1i]     = fmaf(f0, acc[mf][nf][1], x[b1i]);
            out[b0i + 8] = fmaf(f1, acc[mf][nf][2], x[b0i + 8]);
            out[b1i + 8] = fmaf(f1, acc[mf][nf][3], x[b1i + 8]);
        }
    }
}

// ---------------------------------------------------------------------------
extern "C" void kernel_launch(void* const* d_in, const int* in_sizes, int n_in,
                              void* d_out, int out_size)
{
    (void)in_sizes; (void)n_in; (void)out_size;
    const float* x     = (const float*)d_in[0];
    const float* mask  = (const float*)d_in[1];
    const float* skin  = (const float*)d_in[2];
    const float* Wq    = (const float*)d_in[3];
    const float* bq    = (const float*)d_in[4];
    const float* Wk    = (const float*)d_in[5];
    const float* bk    = (const float*)d_in[6];
    const float* Wv    = (const float*)d_in[7];
    const float* bv    = (const float*)d_in[8];
    const float* gamma = (const float*)d_in[9];
    float* out = (float*)d_out;

    cudaFuncSetAttribute(qk_kernel, cudaFuncAttributeMaxDynamicSharedMemorySize, DYN_SMEM);
    cudaFuncSetAttribute(av_kernel, cudaFuncAttributeMaxDynamicSharedMemorySize, DYN_SMEM);

    dim3 gA(4, 32, Bb);
    proj_kernel<<<gA, 256>>>(x, mask, skin, Wq, bq, Wk, bk, Wv, bv);

    dim3 gQK(32, 32, Bb);
    qk_kernel<<<gQK, 256, DYN_SMEM>>>();

    softmax_kernel<<<Bb * Nn, 256>>>();

    dim3 gAV(2, 32, Bb);
    av_kernel<<<gAV, 256, DYN_SMEM>>>(x, mask, skin, gamma, out);
}

// round 7
// speedup vs baseline: 1.1402x; 1.1402x over previous
#include <cuda_runtime.h>
#include <cuda_fp16.h>
#include <cstdint>

// Problem constants
#define Bb 4
#define Cc 256
#define C2v 128
#define Nn 4096

// ---------------------------------------------------------------------------
// Scratch (__device__ globals; allocation-free rule)
// ---------------------------------------------------------------------------
__device__ __half g_qc[(size_t)Bb * Nn * 256];   // [B][n][256] = [qh|ql]
__device__ __half g_kc[(size_t)Bb * Nn * 256];   // [B][n][256] = [kh|kh] (masked)
__device__ __half g_vb[(size_t)Bb * Cc * Nn];    // [B][c][n]  (K-major for AV)
__device__ float  g_att[(size_t)Bb * Nn * Nn];   // energy fp32
__device__ __half g_attb[(size_t)Bb * Nn * Nn];  // attention fp16

// ---------------------------------------------------------------------------
// Helpers
// ---------------------------------------------------------------------------
__device__ __forceinline__ uint32_t smem_u32(const void* p) {
    uint32_t a;
    asm("{ .reg .u64 t; cvta.to.shared.u64 t, %1; cvt.u32.u64 %0, t; }" : "=r"(a) : "l"(p));
    return a;
}
__device__ __forceinline__ void cp_async16(uint32_t dst, const void* src) {
    asm volatile("cp.async.cg.shared.global [%0], [%1], 16;" :: "r"(dst), "l"(src));
}
#define CP_COMMIT() asm volatile("cp.async.commit_group;" ::: "memory")
template <int N>
__device__ __forceinline__ void cp_wait() {
    asm volatile("cp.async.wait_group %0;" :: "n"(N) : "memory");
}
__device__ __forceinline__ void ldmx4(uint32_t* r, uint32_t addr) {
    asm volatile("ldmatrix.sync.aligned.m8n8.x4.shared.b16 {%0,%1,%2,%3}, [%4];"
        : "=r"(r[0]), "=r"(r[1]), "=r"(r[2]), "=r"(r[3]) : "r"(addr));
}
__device__ __forceinline__ void mma16816(float* d, const uint32_t* a, uint32_t b0, uint32_t b1) {
    asm volatile(
        "mma.sync.aligned.m16n8k16.row.col.f32.f16.f16.f32 "
        "{%0,%1,%2,%3},{%4,%5,%6,%7},{%8,%9},{%0,%1,%2,%3};"
        : "+f"(d[0]), "+f"(d[1]), "+f"(d[2]), "+f"(d[3])
        : "r"(a[0]), "r"(a[1]), "r"(a[2]), "r"(a[3]), "r"(b0), "r"(b1));
}

// Fast exp (FFMA-only)
__device__ __forceinline__ float fexp(float x) {
    float t = fmaxf(x * 1.4426950408889634f, -126.0f);
    float fi = floorf(t);
    float f = t - fi;
    float p = 0.0013333558f;
    p = fmaf(p, f, 0.0096181291f);
    p = fmaf(p, f, 0.0555041087f);
    p = fmaf(p, f, 0.2402265069f);
    p = fmaf(p, f, 0.6931471806f);
    p = fmaf(p, f, 1.0f);
    return p * __int_as_float(((int)fi + 127) << 23);
}

// ---------------------------------------------------------------------------
// GEMM tile geometry: 128x128 block, BK=32, 8 warps (2x4)
// smem tile: 128 rows x 32 fp16, row stride 40 halves (80B)
// 3-stage ring, SINGLE barrier per iter, loads issued before compute.
// ---------------------------------------------------------------------------
#define ROWB 80                 // bytes per smem tile row
#define TILE_B (128 * ROWB)     // 10240 per operand tile
#define STAGE_PAIR (2 * TILE_B) // 20480 per stage (A+B)
#define NSTAGE 3
#define DYN_SMEM (NSTAGE * STAGE_PAIR)  // 61440

// Load one 128x32 fp16 tile (row-major src, stride elems) into smem tile.
__device__ __forceinline__ void load_tile(uint32_t dst, const __half* src,
                                          size_t stride, int tid)
{
    #pragma unroll
    for (int i = 0; i < 2; i++) {
        int idx = tid + i * 256;          // 0..511
        int row = idx >> 2, c16 = idx & 3;
        cp_async16(dst + row * ROWB + c16 * 16, src + (size_t)row * stride + c16 * 8);
    }
}

// One BK=32 compute step for a warp: acc[4][4][4] += A(64x32) * B(32x32)^T
__device__ __forceinline__ void warp_mma_step(float acc[4][4][4], uint32_t abase,
                                              uint32_t bbase, int wy, int wx, int lane)
{
    #pragma unroll
    for (int ks = 0; ks < 2; ks++) {
        uint32_t a[4][4];
        #pragma unroll
        for (int mf = 0; mf < 4; mf++) {
            int row = wy * 64 + mf * 16 + (lane & 15);
            ldmx4(a[mf], abase + row * ROWB + ks * 32 + ((lane >> 4) << 4));
        }
        uint32_t bf[2][4];
        #pragma unroll
        for (int np = 0; np < 2; np++) {
            int row = wx * 32 + np * 16 + (lane & 7) + ((lane >> 4) << 3);
            ldmx4(bf[np], bbase + row * ROWB + ks * 32 + (((lane >> 3) & 1) << 4));
        }
        #pragma unroll
        for (int mf = 0; mf < 4; mf++)
            #pragma unroll
            for (int nf = 0; nf < 4; nf++)
                mma16816(acc[mf][nf], a[mf],
                         bf[nf >> 1][(nf & 1) * 2], bf[nf >> 1][(nf & 1) * 2 + 1]);
    }
}

// ---------------------------------------------------------------------------
// Kernel 1: projections (SIMT fp32) -> fp16 operands
// ---------------------------------------------------------------------------
#define BK 8
#define SSTR 132

__global__ __launch_bounds__(256) void proj_kernel(
    const float* __restrict__ x, const float* __restrict__ mask,
    const float* __restrict__ skin,
    const float* __restrict__ Wq, const float* __restrict__ bq,
    const float* __restrict__ Wk, const float* __restrict__ bk,
    const float* __restrict__ Wv, const float* __restrict__ bv)
{
    __shared__ float As[BK * SSTR];
    __shared__ float Bs[BK * SSTR];

    const int b    = blockIdx.z;
    const int m0   = blockIdx.y * 128;
    const int oblk = blockIdx.x;   // 0:q, 1:k, 2,3:v

    const float* Wp; const float* biasp; int orow0;
    if (oblk == 0)      { Wp = Wq; biasp = bq; orow0 = 0; }
    else if (oblk == 1) { Wp = Wk; biasp = bk; orow0 = 0; }
    else                { Wp = Wv; biasp = bv; orow0 = (oblk - 2) * 128; }

    const int tid = threadIdx.x;
    const int tx = tid & 15, ty = tid >> 4;
    const float* xb = x + (size_t)b * Cc * Nn;

    const int a_k = tid >> 5;
    const int a_m = (tid & 31) * 4;
    const int b_o = tid >> 1;
    const int b_kg = (tid & 1) * 4;

    float acc[8][8] = {};

    for (int k0 = 0; k0 < Cc; k0 += BK) {
        float4 av = *reinterpret_cast<const float4*>(xb + (size_t)(k0 + a_k) * Nn + m0 + a_m);
        *reinterpret_cast<float4*>(&As[a_k * SSTR + a_m]) = av;
        float4 wv = *reinterpret_cast<const float4*>(Wp + (size_t)(orow0 + b_o) * Cc + k0 + b_kg);
        Bs[(b_kg + 0) * SSTR + b_o] = wv.x;
        Bs[(b_kg + 1) * SSTR + b_o] = wv.y;
        Bs[(b_kg + 2) * SSTR + b_o] = wv.z;
        Bs[(b_kg + 3) * SSTR + b_o] = wv.w;
        __syncthreads();
        #pragma unroll
        for (int k = 0; k < BK; k++) {
            float4 a0 = *reinterpret_cast<const float4*>(&As[k * SSTR + ty * 8]);
            float4 a1 = *reinterpret_cast<const float4*>(&As[k * SSTR + ty * 8 + 4]);
            float4 b0 = *reinterpret_cast<const float4*>(&Bs[k * SSTR + tx * 8]);
            float4 b1 = *reinterpret_cast<const float4*>(&Bs[k * SSTR + tx * 8 + 4]);
            float a[8] = {a0.x, a0.y, a0.z, a0.w, a1.x, a1.y, a1.z, a1.w};
            float bb[8] = {b0.x, b0.y, b0.z, b0.w, b1.x, b1.y, b1.z, b1.w};
            #pragma unroll
            for (int i = 0; i < 8; i++)
                #pragma unroll
                for (int j = 0; j < 8; j++)
                    acc[i][j] = fmaf(a[i], bb[j], acc[i][j]);
        }
        __syncthreads();
    }

    const int obase = tx * 8;
    float bias[8];
    #pragma unroll
    for (int j = 0; j < 8; j++) bias[j] = biasp[orow0 + obase + j];

    if (oblk <= 1) {
        #pragma unroll
        for (int i = 0; i < 8; i++) {
            const int m = m0 + ty * 8 + i;
            float f = 1.0f;
            if (oblk == 1) f = (1.0f - mask[b * Nn + m]) * skin[b * Nn + m];
            __half h8[8], l8[8];
            #pragma unroll
            for (int j = 0; j < 8; j++) {
                float r = (acc[i][j] + bias[j]) * f;
                __half h = __float2half(r);
                h8[j] = h;
                l8[j] = __float2half(r - __half2float(h));
            }
            const size_t off = ((size_t)b * Nn + m) * 256 + obase;
            if (oblk == 0) {
                // qc = [qh | ql]
                *reinterpret_cast<float4*>(g_qc + off)       = *reinterpret_cast<float4*>(h8);
                *reinterpret_cast<float4*>(g_qc + off + 128) = *reinterpret_cast<float4*>(l8);
            } else {
                // kc = [kh | kh]
                *reinterpret_cast<float4*>(g_kc + off)       = *reinterpret_cast<float4*>(h8);
                *reinterpret_cast<float4*>(g_kc + off + 128) = *reinterpret_cast<float4*>(h8);
            }
        }
    } else {
        // v: [c][n] layout, 8 consecutive n per store
        #pragma unroll
        for (int j = 0; j < 8; j++) {
            const int c = orow0 + obase + j;
            __half h8[8];
            #pragma unroll
            for (int i = 0; i < 8; i++) h8[i] = __float2half(acc[i][j] + bias[j]);
            const size_t off = ((size_t)b * Cc + c) * Nn + m0 + ty * 8;
            *reinterpret_cast<float4*>(g_vb + off) = *reinterpret_cast<float4*>(h8);
        }
    }
}

// ---------------------------------------------------------------------------
// Kernel 2: QK^T energy via mma.sync fp16, K=256 2-term split
//   S = qh·kh + ql·kh
// grid (32 ntile, 32 mtile, B), 256 threads, dynamic smem 61440
// Single barrier per iter; loads for stage s+2 issued before compute of s.
// ---------------------------------------------------------------------------
__global__ __launch_bounds__(256) void qk_kernel()
{
    extern __shared__ __align__(128) char dynsm[];
    const int b = blockIdx.z, m0 = blockIdx.y * 128, n0 = blockIdx.x * 128;
    const int tid = threadIdx.x, wid = tid >> 5, lane = tid & 31;
    const int wy = wid >> 2, wx = wid & 3;
    const uint32_t sb = smem_u32(dynsm);

    const __half* Asrc = g_qc + ((size_t)b * Nn + m0) * 256;
    const __half* Bsrc = g_kc + ((size_t)b * Nn + n0) * 256;

    const int NK = 256 / 32;   // 8
    #pragma unroll
    for (int s = 0; s < 2; s++) {
        uint32_t st = sb + s * STAGE_PAIR;
        load_tile(st, Asrc + s * 32, 256, tid);
        load_tile(st + TILE_B, Bsrc + s * 32, 256, tid);
        CP_COMMIT();
    }

    float acc[4][4][4] = {};
    #pragma unroll 1
    for (int s = 0; s < NK; s++) {
        if (s < NK - 1) cp_wait<1>(); else cp_wait<0>();
        __syncthreads();
        if (s + 2 < NK) {
            uint32_t ld = sb + (uint32_t)((s + 2) % NSTAGE) * STAGE_PAIR;
            load_tile(ld, Asrc + (s + 2) * 32, 256, tid);
            load_tile(ld + TILE_B, Bsrc + (s + 2) * 32, 256, tid);
            CP_COMMIT();
        }
        const uint32_t st = sb + (uint32_t)(s % NSTAGE) * STAGE_PAIR;
        warp_mma_step(acc, st, st + TILE_B, wy, wx, lane);
    }

    // Epilogue: fp32 energy, float2 stores
    #pragma unroll
    for (int mf = 0; mf < 4; mf++) {
        const int m = m0 + wy * 64 + mf * 16 + (lane >> 2);
        #pragma unroll
        for (int nf = 0; nf < 4; nf++) {
            const int n = n0 + wx * 32 + nf * 8 + (lane & 3) * 2;
            float* p0 = g_att + ((size_t)b * Nn + m) * Nn + n;
            float* p1 = g_att + ((size_t)b * Nn + m + 8) * Nn + n;
            *reinterpret_cast<float2*>(p0) = make_float2(acc[mf][nf][0], acc[mf][nf][1]);
            *reinterpret_cast<float2*>(p1) = make_float2(acc[mf][nf][2], acc[mf][nf][3]);
        }
    }
}

// ---------------------------------------------------------------------------
// Kernel 3: row softmax (fp32 in -> fp16 out)
// ---------------------------------------------------------------------------
__global__ __launch_bounds__(256) void softmax_kernel()
{
    const size_t row = blockIdx.x;
    const float* p = g_att + row * (size_t)Nn;
    __half* pb = g_attb + row * (size_t)Nn;
    const int t = threadIdx.x;

    float v[16];
    {
        const float4* pr = reinterpret_cast<const float4*>(p + t * 16);
        float4 a0 = pr[0], a1 = pr[1], a2 = pr[2], a3 = pr[3];
        v[0]=a0.x; v[1]=a0.y; v[2]=a0.z; v[3]=a0.w;
        v[4]=a1.x; v[5]=a1.y; v[6]=a1.z; v[7]=a1.w;
        v[8]=a2.x; v[9]=a2.y; v[10]=a2.z; v[11]=a2.w;
        v[12]=a3.x; v[13]=a3.y; v[14]=a3.z; v[15]=a3.w;
    }
    float mx = v[0];
    #pragma unroll
    for (int i = 1; i < 16; i++) mx = fmaxf(mx, v[i]);
    #pragma unroll
    for (int o = 16; o; o >>= 1) mx = fmaxf(mx, __shfl_xor_sync(0xffffffffu, mx, o));

    __shared__ float red[8];
    __shared__ float bmax, binv;
    if ((t & 31) == 0) red[t >> 5] = mx;
    __syncthreads();
    if (t == 0) {
        float m2 = red[0];
        #pragma unroll
        for (int w = 1; w < 8; w++) m2 = fmaxf(m2, red[w]);
        bmax = m2;
    }
    __syncthreads();
    mx = bmax;

    float s = 0.0f;
    #pragma unroll
    for (int i = 0; i < 16; i++) { v[i] = fexp(v[i] - mx); s += v[i]; }
    #pragma unroll
    for (int o = 16; o; o >>= 1) s += __shfl_xor_sync(0xffffffffu, s, o);
    if ((t & 31) == 0) red[t >> 5] = s;
    __syncthreads();
    if (t == 0) {
        float s2 = 0.0f;
        #pragma unroll
        for (int w = 0; w < 8; w++) s2 += red[w];
        binv = 1.0f / s2;
    }
    __syncthreads();
    const float inv = binv;

    __half h[16];
    #pragma unroll
    for (int i = 0; i < 16; i++) h[i] = __float2half(v[i] * inv);
    float4* po = reinterpret_cast<float4*>(pb + t * 16);
    po[0] = reinterpret_cast<float4*>(h)[0];
    po[1] = reinterpret_cast<float4*>(h)[1];
}

// ---------------------------------------------------------------------------
// Kernel 4: AV via mma.sync fp16 + fused epilogue; single-barrier ring
// grid (2 ctile, 32 mtile, B), 256 threads, dynamic smem 61440
// ---------------------------------------------------------------------------
__global__ __launch_bounds__(256) void av_kernel(
    const float* __restrict__ x, const float* __restrict__ mask,
    const float* __restrict__ skin, const float* __restrict__ gamma,
    float* __restrict__ out)
{
    extern __shared__ __align__(128) char dynsm[];
    __shared__ float fmv[128];
    const int b = blockIdx.z, m0 = blockIdx.y * 128, c0 = blockIdx.x * 128;
    const int tid = threadIdx.x, wid = tid >> 5, lane = tid & 31;
    const int wy = wid >> 2, wx = wid & 3;
    const uint32_t sb = smem_u32(dynsm);

    if (tid < 128)
        fmv[tid] = mask[(size_t)b * Nn + m0 + tid] * skin[(size_t)b * Nn + m0 + tid];

    const __half* Asrc = g_attb + ((size_t)b * Nn + m0) * Nn;
    const __half* Bsrc = g_vb + ((size_t)b * Cc + c0) * Nn;

    const int NK = Nn / 32;   // 128
    #pragma unroll
    for (int s = 0; s < 2; s++) {
        uint32_t st = sb + s * STAGE_PAIR;
        load_tile(st, Asrc + s * 32, Nn, tid);
        load_tile(st + TILE_B, Bsrc + s * 32, Nn, tid);
        CP_COMMIT();
    }

    float acc[4][4][4] = {};
    #pragma unroll 1
    for (int s = 0; s < NK; s++) {
        if (s < NK - 1) cp_wait<1>(); else cp_wait<0>();
        __syncthreads();
        if (s + 2 < NK) {
            uint32_t ld = sb + (uint32_t)((s + 2) % NSTAGE) * STAGE_PAIR;
            load_tile(ld, Asrc + (s + 2) * 32, Nn, tid);
            load_tile(ld + TILE_B, Bsrc + (s + 2) * 32, Nn, tid);
            CP_COMMIT();
        }
        const uint32_t st = sb + (uint32_t)(s % NSTAGE) * STAGE_PAIR;
        warp_mma_step(acc, st, st + TILE_B, wy, wx, lane);
    }

    // Fused epilogue: out[c][m] = gamma*fm[m]*D[m][c] + x[c][m]
    const float gm = __ldg(gamma);
    #pragma unroll
    for (int mf = 0; mf < 4; mf++) {
        const int ml = wy * 64 + mf * 16 + (lane >> 2);    // local m (0..127)
        const float f0 = gm * fmv[ml];
        const float f1 = gm * fmv[ml + 8];
        #pragma unroll
        for (int nf = 0; nf < 4; nf++) {
            const int c = c0 + wx * 32 + nf * 8 + (lane & 3) * 2;
            const size_t b0i = ((size_t)b * Cc + c) * Nn + m0 + ml;
            const size_t b1i = b0i + Nn;   // c+1
            out[b0i]     = fmaf(f0, acc[mf][nf][0], x[b0i]);
            out[b1i]     = fmaf(f0, acc[mf][nf][1], x[b1i]);
            out[b0i + 8] = fmaf(f1, acc[mf][nf][2], x[b0i + 8]);
            out[b1i + 8] = fmaf(f1, acc[mf][nf][3], x[b1i + 8]);
        }
    }
}

// ---------------------------------------------------------------------------
extern "C" void kernel_launch(void* const* d_in, const int* in_sizes, int n_in,
                              void* d_out, int out_size)
{
    (void)in_sizes; (void)n_in; (void)out_size;
    const float* x     = (const float*)d_in[0];
    const float* mask  = (const float*)d_in[1];
    const float* skin  = (const float*)d_in[2];
    const float* Wq    = (const float*)d_in[3];
    const float* bq    = (const float*)d_in[4];
    const float* Wk    = (const float*)d_in[5];
    const float* bk    = (const float*)d_in[6];
    const float* Wv    = (const float*)d_in[7];
    const float* bv    = (const float*)d_in[8];
    const float* gamma = (const float*)d_in[9];
    float* out = (float*)d_out;

    cudaFuncSetAttribute(qk_kernel, cudaFuncAttributeMaxDynamicSharedMemorySize, DYN_SMEM);
    cudaFuncSetAttribute(av_kernel, cudaFuncAttributeMaxDynamicSharedMemorySize, DYN_SMEM);

    dim3 gA(4, 32, Bb);
    proj_kernel<<<gA, 256>>>(x, mask, skin, Wq, bq, Wk, bk, Wv, bv);

    dim3 gQK(32, 32, Bb);
    qk_kernel<<<gQK, 256, DYN_SMEM>>>();

    softmax_kernel<<<Bb * Nn, 256>>>();

    dim3 gAV(2, 32, Bb);
    av_kernel<<<gAV, 256, DYN_SMEM>>>(x, mask, skin, gamma, out);
}

// round 8
// speedup vs baseline: 1.1615x; 1.0187x over previous
#include <cuda_runtime.h>
#include <cuda_fp16.h>
#include <cstdint>

// Problem constants
#define Bb 4
#define Cc 256
#define C2v 128
#define Nn 4096

// ---------------------------------------------------------------------------
// Scratch (__device__ globals; allocation-free rule)
// ---------------------------------------------------------------------------
__device__ __half g_qc[(size_t)Bb * Nn * 256];   // [B][n][256] = [qh|ql]
__device__ __half g_kc[(size_t)Bb * Nn * 256];   // [B][n][256] = [kh|kh] (masked)
__device__ __half g_vb[(size_t)Bb * Cc * Nn];    // [B][c][n]  (K-major for AV)
__device__ __half g_attb[(size_t)Bb * Nn * Nn];  // P = exp(S - chunkmax), fp16
__device__ float  g_cmax[(size_t)Bb * Nn * 32];  // per-row per-chunk max
__device__ float  g_sumexp[(size_t)Bb * Nn * 32];// per-row per-chunk sum of exp
__device__ float  g_corr[(size_t)Bb * Nn * 32];  // exp(cmax-M)/Z

// ---------------------------------------------------------------------------
// Helpers
// ---------------------------------------------------------------------------
__device__ __forceinline__ uint32_t smem_u32(const void* p) {
    uint32_t a;
    asm("{ .reg .u64 t; cvta.to.shared.u64 t, %1; cvt.u32.u64 %0, t; }" : "=r"(a) : "l"(p));
    return a;
}
__device__ __forceinline__ void cp_async16(uint32_t dst, const void* src) {
    asm volatile("cp.async.cg.shared.global [%0], [%1], 16;" :: "r"(dst), "l"(src));
}
#define CP_COMMIT() asm volatile("cp.async.commit_group;" ::: "memory")
template <int N>
__device__ __forceinline__ void cp_wait() {
    asm volatile("cp.async.wait_group %0;" :: "n"(N) : "memory");
}
__device__ __forceinline__ void ldmx4(uint32_t* r, uint32_t addr) {
    asm volatile("ldmatrix.sync.aligned.m8n8.x4.shared.b16 {%0,%1,%2,%3}, [%4];"
        : "=r"(r[0]), "=r"(r[1]), "=r"(r[2]), "=r"(r[3]) : "r"(addr));
}
__device__ __forceinline__ void mma16816(float* d, const uint32_t* a, uint32_t b0, uint32_t b1) {
    asm volatile(
        "mma.sync.aligned.m16n8k16.row.col.f32.f16.f16.f32 "
        "{%0,%1,%2,%3},{%4,%5,%6,%7},{%8,%9},{%0,%1,%2,%3};"
        : "+f"(d[0]), "+f"(d[1]), "+f"(d[2]), "+f"(d[3])
        : "r"(a[0]), "r"(a[1]), "r"(a[2]), "r"(a[3]), "r"(b0), "r"(b1));
}
__device__ __forceinline__ uint32_t h2u(float c) {
    __half2 h = __float2half2_rn(c);
    return *reinterpret_cast<uint32_t*>(&h);
}
__device__ __forceinline__ uint32_t hmul2u(uint32_t a, uint32_t b) {
    __half2 x = *reinterpret_cast<__half2*>(&a);
    __half2 y = *reinterpret_cast<__half2*>(&b);
    __half2 z = __hmul2(x, y);
    return *reinterpret_cast<uint32_t*>(&z);
}

// Fast exp (FFMA-only)
__device__ __forceinline__ float fexp(float x) {
    float t = fmaxf(x * 1.4426950408889634f, -126.0f);
    float fi = floorf(t);
    float f = t - fi;
    float p = 0.0013333558f;
    p = fmaf(p, f, 0.0096181291f);
    p = fmaf(p, f, 0.0555041087f);
    p = fmaf(p, f, 0.2402265069f);
    p = fmaf(p, f, 0.6931471806f);
    p = fmaf(p, f, 1.0f);
    return p * __int_as_float(((int)fi + 127) << 23);
}

// ---------------------------------------------------------------------------
// GEMM tile geometry: 128x128 block, BK=32, 8 warps (2x4)
// smem tile: 128 rows x 32 fp16, row stride 40 halves (80B)
// 3-stage ring, single barrier per iter, loads issued before compute.
// ---------------------------------------------------------------------------
#define ROWB 80                 // bytes per smem tile row
#define TILE_B (128 * ROWB)     // 10240 per operand tile
#define STAGE_PAIR (2 * TILE_B) // 20480 per stage (A+B)
#define NSTAGE 3
#define DYN_SMEM (NSTAGE * STAGE_PAIR)        // 61440
#define DYN_SMEM_AV (DYN_SMEM + 16384)        // + corr slice [128][32] fp32

// Load one 128x32 fp16 tile (row-major src, stride elems) into smem tile.
__device__ __forceinline__ void load_tile(uint32_t dst, const __half* src,
                                          size_t stride, int tid)
{
    #pragma unroll
    for (int i = 0; i < 2; i++) {
        int idx = tid + i * 256;          // 0..511
        int row = idx >> 2, c16 = idx & 3;
        cp_async16(dst + row * ROWB + c16 * 16, src + (size_t)row * stride + c16 * 8);
    }
}

// One BK=32 compute step for a warp: acc[4][4][4] += A(64x32) * B(32x32)^T
__device__ __forceinline__ void warp_mma_step(float acc[4][4][4], uint32_t abase,
                                              uint32_t bbase, int wy, int wx, int lane)
{
    #pragma unroll
    for (int ks = 0; ks < 2; ks++) {
        uint32_t a[4][4];
        #pragma unroll
        for (int mf = 0; mf < 4; mf++) {
            int row = wy * 64 + mf * 16 + (lane & 15);
            ldmx4(a[mf], abase + row * ROWB + ks * 32 + ((lane >> 4) << 4));
        }
        uint32_t bf[2][4];
        #pragma unroll
        for (int np = 0; np < 2; np++) {
            int row = wx * 32 + np * 16 + (lane & 7) + ((lane >> 4) << 3);
            ldmx4(bf[np], bbase + row * ROWB + ks * 32 + (((lane >> 3) & 1) << 4));
        }
        #pragma unroll
        for (int mf = 0; mf < 4; mf++)
            #pragma unroll
            for (int nf = 0; nf < 4; nf++)
                mma16816(acc[mf][nf], a[mf],
                         bf[nf >> 1][(nf & 1) * 2], bf[nf >> 1][(nf & 1) * 2 + 1]);
    }
}

// Variant for AV: scale A fragments by per-row corr (half2 broadcast regs).
// ch[mf][0] applies to rows r0 (frags 0,2); ch[mf][1] to rows r0+8 (frags 1,3).
__device__ __forceinline__ void warp_mma_step_scaled(float acc[4][4][4], uint32_t abase,
                                                     uint32_t bbase, int wy, int wx,
                                                     int lane, const uint32_t ch[4][2])
{
    #pragma unroll
    for (int ks = 0; ks < 2; ks++) {
        uint32_t a[4][4];
        #pragma unroll
        for (int mf = 0; mf < 4; mf++) {
            int row = wy * 64 + mf * 16 + (lane & 15);
            ldmx4(a[mf], abase + row * ROWB + ks * 32 + ((lane >> 4) << 4));
            a[mf][0] = hmul2u(a[mf][0], ch[mf][0]);
            a[mf][1] = hmul2u(a[mf][1], ch[mf][1]);
            a[mf][2] = hmul2u(a[mf][2], ch[mf][0]);
            a[mf][3] = hmul2u(a[mf][3], ch[mf][1]);
        }
        uint32_t bf[2][4];
        #pragma unroll
        for (int np = 0; np < 2; np++) {
            int row = wx * 32 + np * 16 + (lane & 7) + ((lane >> 4) << 3);
            ldmx4(bf[np], bbase + row * ROWB + ks * 32 + (((lane >> 3) & 1) << 4));
        }
        #pragma unroll
        for (int mf = 0; mf < 4; mf++)
            #pragma unroll
            for (int nf = 0; nf < 4; nf++)
                mma16816(acc[mf][nf], a[mf],
                         bf[nf >> 1][(nf & 1) * 2], bf[nf >> 1][(nf & 1) * 2 + 1]);
    }
}

// ---------------------------------------------------------------------------
// Kernel 1: projections (SIMT fp32) -> fp16 operands (unchanged, passing)
// ---------------------------------------------------------------------------
#define BK 8
#define SSTR 132

__global__ __launch_bounds__(256) void proj_kernel(
    const float* __restrict__ x, const float* __restrict__ mask,
    const float* __restrict__ skin,
    const float* __restrict__ Wq, const float* __restrict__ bq,
    const float* __restrict__ Wk, const float* __restrict__ bk,
    const float* __restrict__ Wv, const float* __restrict__ bv)
{
    __shared__ float As[BK * SSTR];
    __shared__ float Bs[BK * SSTR];

    const int b    = blockIdx.z;
    const int m0   = blockIdx.y * 128;
    const int oblk = blockIdx.x;   // 0:q, 1:k, 2,3:v

    const float* Wp; const float* biasp; int orow0;
    if (oblk == 0)      { Wp = Wq; biasp = bq; orow0 = 0; }
    else if (oblk == 1) { Wp = Wk; biasp = bk; orow0 = 0; }
    else                { Wp = Wv; biasp = bv; orow0 = (oblk - 2) * 128; }

    const int tid = threadIdx.x;
    const int tx = tid & 15, ty = tid >> 4;
    const float* xb = x + (size_t)b * Cc * Nn;

    const int a_k = tid >> 5;
    const int a_m = (tid & 31) * 4;
    const int b_o = tid >> 1;
    const int b_kg = (tid & 1) * 4;

    float acc[8][8] = {};

    for (int k0 = 0; k0 < Cc; k0 += BK) {
        float4 av = *reinterpret_cast<const float4*>(xb + (size_t)(k0 + a_k) * Nn + m0 + a_m);
        *reinterpret_cast<float4*>(&As[a_k * SSTR + a_m]) = av;
        float4 wv = *reinterpret_cast<const float4*>(Wp + (size_t)(orow0 + b_o) * Cc + k0 + b_kg);
        Bs[(b_kg + 0) * SSTR + b_o] = wv.x;
        Bs[(b_kg + 1) * SSTR + b_o] = wv.y;
        Bs[(b_kg + 2) * SSTR + b_o] = wv.z;
        Bs[(b_kg + 3) * SSTR + b_o] = wv.w;
        __syncthreads();
        #pragma unroll
        for (int k = 0; k < BK; k++) {
            float4 a0 = *reinterpret_cast<const float4*>(&As[k * SSTR + ty * 8]);
            float4 a1 = *reinterpret_cast<const float4*>(&As[k * SSTR + ty * 8 + 4]);
            float4 b0 = *reinterpret_cast<const float4*>(&Bs[k * SSTR + tx * 8]);
            float4 b1 = *reinterpret_cast<const float4*>(&Bs[k * SSTR + tx * 8 + 4]);
            float a[8] = {a0.x, a0.y, a0.z, a0.w, a1.x, a1.y, a1.z, a1.w};
            float bb[8] = {b0.x, b0.y, b0.z, b0.w, b1.x, b1.y, b1.z, b1.w};
            #pragma unroll
            for (int i = 0; i < 8; i++)
                #pragma unroll
                for (int j = 0; j < 8; j++)
                    acc[i][j] = fmaf(a[i], bb[j], acc[i][j]);
        }
        __syncthreads();
    }

    const int obase = tx * 8;
    float bias[8];
    #pragma unroll
    for (int j = 0; j < 8; j++) bias[j] = biasp[orow0 + obase + j];

    if (oblk <= 1) {
        #pragma unroll
        for (int i = 0; i < 8; i++) {
            const int m = m0 + ty * 8 + i;
            float f = 1.0f;
            if (oblk == 1) f = (1.0f - mask[b * Nn + m]) * skin[b * Nn + m];
            __half h8[8], l8[8];
            #pragma unroll
            for (int j = 0; j < 8; j++) {
                float r = (acc[i][j] + bias[j]) * f;
                __half h = __float2half(r);
                h8[j] = h;
                l8[j] = __float2half(r - __half2float(h));
            }
            const size_t off = ((size_t)b * Nn + m) * 256 + obase;
            if (oblk == 0) {
                // qc = [qh | ql]
                *reinterpret_cast<float4*>(g_qc + off)       = *reinterpret_cast<float4*>(h8);
                *reinterpret_cast<float4*>(g_qc + off + 128) = *reinterpret_cast<float4*>(l8);
            } else {
                // kc = [kh | kh]
                *reinterpret_cast<float4*>(g_kc + off)       = *reinterpret_cast<float4*>(h8);
                *reinterpret_cast<float4*>(g_kc + off + 128) = *reinterpret_cast<float4*>(h8);
            }
        }
    } else {
        // v: [c][n] layout, 8 consecutive n per store
        #pragma unroll
        for (int j = 0; j < 8; j++) {
            const int c = orow0 + obase + j;
            __half h8[8];
            #pragma unroll
            for (int i = 0; i < 8; i++) h8[i] = __float2half(acc[i][j] + bias[j]);
            const size_t off = ((size_t)b * Cc + c) * Nn + m0 + ty * 8;
            *reinterpret_cast<float4*>(g_vb + off) = *reinterpret_cast<float4*>(h8);
        }
    }
}

// ---------------------------------------------------------------------------
// Kernel 2: QK^T + chunk-local softmax stats.
//   S = qh·kh + ql·kh (K=256 2-term split)
//   P = exp(S - chunkmax) -> g_attb fp16; cmax/sumexp -> stats arrays
// grid (32 nchunk, 32 mtile, B), 256 threads, dynamic smem 61440
// ---------------------------------------------------------------------------
__global__ __launch_bounds__(256, 2) void qk_kernel()
{
    extern __shared__ __align__(128) char dynsm[];
    const int b = blockIdx.z, m0 = blockIdx.y * 128, n0 = blockIdx.x * 128;
    const int chunk = blockIdx.x;
    const int tid = threadIdx.x, wid = tid >> 5, lane = tid & 31;
    const int wy = wid >> 2, wx = wid & 3;
    const uint32_t sb = smem_u32(dynsm);

    const __half* Asrc = g_qc + ((size_t)b * Nn + m0) * 256;
    const __half* Bsrc = g_kc + ((size_t)b * Nn + n0) * 256;

    const int NK = 256 / 32;   // 8
    #pragma unroll
    for (int s = 0; s < 2; s++) {
        uint32_t st = sb + s * STAGE_PAIR;
        load_tile(st, Asrc + s * 32, 256, tid);
        load_tile(st + TILE_B, Bsrc + s * 32, 256, tid);
        CP_COMMIT();
    }

    float acc[4][4][4] = {};
    #pragma unroll 1
    for (int s = 0; s < NK; s++) {
        if (s < NK - 1) cp_wait<1>(); else cp_wait<0>();
        __syncthreads();
        if (s + 2 < NK) {
            uint32_t ld = sb + (uint32_t)((s + 2) % NSTAGE) * STAGE_PAIR;
            load_tile(ld, Asrc + (s + 2) * 32, 256, tid);
            load_tile(ld + TILE_B, Bsrc + (s + 2) * 32, 256, tid);
            CP_COMMIT();
        }
        const uint32_t st = sb + (uint32_t)(s % NSTAGE) * STAGE_PAIR;
        warp_mma_step(acc, st, st + TILE_B, wy, wx, lane);
    }

    // ---- chunk-local softmax epilogue (smem overlay; tiles are dead) ----
    __syncthreads();
    float* scm  = reinterpret_cast<float*>(dynsm);           // [128] final chunkmax
    float* sred = reinterpret_cast<float*>(dynsm) + 128;     // [4][128] cross-warp
    __half* pst = reinterpret_cast<__half*>(dynsm + 4096);   // [128][128] P staging

    // 1) per-row max (each thread: rows rA, rA+8 per mf; cols = 8 vals)
    float rmax[4][2];
    #pragma unroll
    for (int mf = 0; mf < 4; mf++) {
        float mA = -1e30f, mB = -1e30f;
        #pragma unroll
        for (int nf = 0; nf < 4; nf++) {
            mA = fmaxf(mA, fmaxf(acc[mf][nf][0], acc[mf][nf][1]));
            mB = fmaxf(mB, fmaxf(acc[mf][nf][2], acc[mf][nf][3]));
        }
        rmax[mf][0] = mA; rmax[mf][1] = mB;
    }
    #pragma unroll
    for (int o = 1; o <= 2; o <<= 1)
        #pragma unroll
        for (int mf = 0; mf < 4; mf++) {
            rmax[mf][0] = fmaxf(rmax[mf][0], __shfl_xor_sync(0xffffffffu, rmax[mf][0], o));
            rmax[mf][1] = fmaxf(rmax[mf][1], __shfl_xor_sync(0xffffffffu, rmax[mf][1], o));
        }
    if ((lane & 3) == 0) {
        #pragma unroll
        for (int mf = 0; mf < 4; mf++) {
            int rA = wy * 64 + mf * 16 + (lane >> 2);
            sred[wx * 128 + rA]     = rmax[mf][0];
            sred[wx * 128 + rA + 8] = rmax[mf][1];
        }
    }
    __syncthreads();
    if (tid < 128) {
        float cm = fmaxf(fmaxf(sred[tid], sred[128 + tid]),
                         fmaxf(sred[256 + tid], sred[384 + tid]));
        scm[tid] = cm;
        g_cmax[((size_t)b * Nn + m0 + tid) * 32 + chunk] = cm;
    }
    __syncthreads();

    // 2) exp, stage P, row sums
    float rsum[4][2];
    #pragma unroll
    for (int mf = 0; mf < 4; mf++) {
        int rA = wy * 64 + mf * 16 + (lane >> 2);
        int rB = rA + 8;
        float cA = scm[rA], cB = scm[rB];
        float sA = 0.0f, sB = 0.0f;
        #pragma unroll
        for (int nf = 0; nf < 4; nf++) {
            float p0 = fexp(acc[mf][nf][0] - cA);
            float p1 = fexp(acc[mf][nf][1] - cA);
            float p2 = fexp(acc[mf][nf][2] - cB);
            float p3 = fexp(acc[mf][nf][3] - cB);
            sA += p0 + p1; sB += p2 + p3;
            int cl = wx * 32 + nf * 8 + (lane & 3) * 2;
            *reinterpret_cast<__half2*>(pst + rA * 128 + cl) = __floats2half2_rn(p0, p1);
            *reinterpret_cast<__half2*>(pst + rB * 128 + cl) = __floats2half2_rn(p2, p3);
        }
        rsum[mf][0] = sA; rsum[mf][1] = sB;
    }
    #pragma unroll
    for (int o = 1; o <= 2; o <<= 1)
        #pragma unroll
        for (int mf = 0; mf < 4; mf++) {
            rsum[mf][0] += __shfl_xor_sync(0xffffffffu, rsum[mf][0], o);
            rsum[mf][1] += __shfl_xor_sync(0xffffffffu, rsum[mf][1], o);
        }
    if ((lane & 3) == 0) {
        #pragma unroll
        for (int mf = 0; mf < 4; mf++) {
            int rA = wy * 64 + mf * 16 + (lane >> 2);
            sred[wx * 128 + rA]     = rsum[mf][0];
            sred[wx * 128 + rA + 8] = rsum[mf][1];
        }
    }
    __syncthreads();
    if (tid < 128) {
        float se = sred[tid] + sred[128 + tid] + sred[256 + tid] + sred[384 + tid];
        g_sumexp[((size_t)b * Nn + m0 + tid) * 32 + chunk] = se;
    }

    // 3) coalesced P write-out (pst writes covered by the barrier above)
    #pragma unroll
    for (int i = 0; i < 8; i++) {
        int f4 = tid + i * 256;           // 0..2047 float4s
        int row = f4 >> 4, c8 = (f4 & 15) * 8;
        float4 v = *reinterpret_cast<float4*>(pst + row * 128 + c8);
        *reinterpret_cast<float4*>(g_attb + ((size_t)b * Nn + m0 + row) * Nn + n0 + c8) = v;
    }
}

// ---------------------------------------------------------------------------
// Kernel 3: corr — per (row, chunk) normalization factor. One warp per row.
// ---------------------------------------------------------------------------
__global__ __launch_bounds__(256) void corr_kernel()
{
    const int wid = threadIdx.x >> 5, lane = threadIdx.x & 31;
    const size_t row = (size_t)blockIdx.x * 8 + wid;   // 0 .. Bb*Nn-1
    float cm = g_cmax[row * 32 + lane];
    float se = g_sumexp[row * 32 + lane];
    float M = cm;
    #pragma unroll
    for (int o = 16; o; o >>= 1) M = fmaxf(M, __shfl_xor_sync(0xffffffffu, M, o));
    float e = fexp(cm - M);
    float Z = se * e;
    #pragma unroll
    for (int o = 16; o; o >>= 1) Z += __shfl_xor_sync(0xffffffffu, Z, o);
    g_corr[row * 32 + lane] = e / Z;
}

// ---------------------------------------------------------------------------
// Kernel 4: AV via mma.sync fp16 with on-the-fly P normalization + epilogue
// grid (2 ctile, 32 mtile, B), 256 threads, dynamic smem 77824
// ---------------------------------------------------------------------------
__global__ __launch_bounds__(256, 2) void av_kernel(
    const float* __restrict__ x, const float* __restrict__ mask,
    const float* __restrict__ skin, const float* __restrict__ gamma,
    float* __restrict__ out)
{
    extern __shared__ __align__(128) char dynsm[];
    __shared__ float fmv[128];
    const int b = blockIdx.z, m0 = blockIdx.y * 128, c0 = blockIdx.x * 128;
    const int tid = threadIdx.x, wid = tid >> 5, lane = tid & 31;
    const int wy = wid >> 2, wx = wid & 3;
    const uint32_t sb = smem_u32(dynsm);
    float* scorr = reinterpret_cast<float*>(dynsm + DYN_SMEM);   // [128][32]

    if (tid < 128)
        fmv[tid] = mask[(size_t)b * Nn + m0 + tid] * skin[(size_t)b * Nn + m0 + tid];

    // Stage corr slice for this m-tile (contiguous 16KB, coalesced)
    {
        const float* csrc = g_corr + ((size_t)b * Nn + m0) * 32;
        #pragma unroll
        for (int i = 0; i < 4; i++) {
            int idx = (tid + i * 256) * 4;
            *reinterpret_cast<float4*>(scorr + idx) =
                *reinterpret_cast<const float4*>(csrc + idx);
        }
    }

    const __half* Asrc = g_attb + ((size_t)b * Nn + m0) * Nn;
    const __half* Bsrc = g_vb + ((size_t)b * Cc + c0) * Nn;

    const int NK = Nn / 32;   // 128
    #pragma unroll
    for (int s = 0; s < 2; s++) {
        uint32_t st = sb + s * STAGE_PAIR;
        load_tile(st, Asrc + s * 32, Nn, tid);
        load_tile(st + TILE_B, Bsrc + s * 32, Nn, tid);
        CP_COMMIT();
    }

    float acc[4][4][4] = {};
    uint32_t ch[4][2];
    #pragma unroll 1
    for (int s = 0; s < NK; s++) {
        if (s < NK - 1) cp_wait<1>(); else cp_wait<0>();
        __syncthreads();
        if (s + 2 < NK) {
            uint32_t ld = sb + (uint32_t)((s + 2) % NSTAGE) * STAGE_PAIR;
            load_tile(ld, Asrc + (s + 2) * 32, Nn, tid);
            load_tile(ld + TILE_B, Bsrc + (s + 2) * 32, Nn, tid);
            CP_COMMIT();
        }
        if ((s & 3) == 0) {
            int chunk = s >> 2;
            #pragma unroll
            for (int mf = 0; mf < 4; mf++) {
                int rA = wy * 64 + mf * 16 + (lane >> 2);
                ch[mf][0] = h2u(scorr[rA * 32 + chunk]);
                ch[mf][1] = h2u(scorr[(rA + 8) * 32 + chunk]);
            }
        }
        const uint32_t st = sb + (uint32_t)(s % NSTAGE) * STAGE_PAIR;
        warp_mma_step_scaled(acc, st, st + TILE_B, wy, wx, lane, ch);
    }

    // Fused epilogue: out[c][m] = gamma*fm[m]*D[m][c] + x[c][m]
    const float gm = __ldg(gamma);
    #pragma unroll
    for (int mf = 0; mf < 4; mf++) {
        const int ml = wy * 64 + mf * 16 + (lane >> 2);    // local m (0..127)
        const float f0 = gm * fmv[ml];
        const float f1 = gm * fmv[ml + 8];
        #pragma unroll
        for (int nf = 0; nf < 4; nf++) {
            const int c = c0 + wx * 32 + nf * 8 + (lane & 3) * 2;
            const size_t b0i = ((size_t)b * Cc + c) * Nn + m0 + ml;
            const size_t b1i = b0i + Nn;   // c+1
            out[b0i]     = fmaf(f0, acc[mf][nf][0], x[b0i]);
            out[b1i]     = fmaf(f0, acc[mf][nf][1], x[b1i]);
            out[b0i + 8] = fmaf(f1, acc[mf][nf][2], x[b0i + 8]);
            out[b1i + 8] = fmaf(f1, acc[mf][nf][3], x[b1i + 8]);
        }
    }
}

// ---------------------------------------------------------------------------
extern "C" void kernel_launch(void* const* d_in, const int* in_sizes, int n_in,
                              void* d_out, int out_size)
{
    (void)in_sizes; (void)n_in; (void)out_size;
    const float* x     = (const float*)d_in[0];
    const float* mask  = (const float*)d_in[1];
    const float* skin  = (const float*)d_in[2];
    const float* Wq    = (const float*)d_in[3];
    const float* bq    = (const float*)d_in[4];
    const float* Wk    = (const float*)d_in[5];
    const float* bk    = (const float*)d_in[6];
    const float* Wv    = (const float*)d_in[7];
    const float* bv    = (const float*)d_in[8];
    const float* gamma = (const float*)d_in[9];
    float* out = (float*)d_out;

    cudaFuncSetAttribute(qk_kernel, cudaFuncAttributeMaxDynamicSharedMemorySize, DYN_SMEM);
    cudaFuncSetAttribute(av_kernel, cudaFuncAttributeMaxDynamicSharedMemorySize, DYN_SMEM_AV);

    dim3 gA(4, 32, Bb);
    proj_kernel<<<gA, 256>>>(x, mask, skin, Wq, bq, Wk, bk, Wv, bv);

    dim3 gQK(32, 32, Bb);
    qk_kernel<<<gQK, 256, DYN_SMEM>>>();

    corr_kernel<<<(Bb * Nn) / 8, 256>>>();

    dim3 gAV(2, 32, Bb);
    av_kernel<<<gAV, 256, DYN_SMEM_AV>>>(x, mask, skin, gamma, out);
}

// round 9
// speedup vs baseline: 1.2315x; 1.0603x over previous
#include <cuda_runtime.h>
#include <cuda_fp16.h>
#include <cuda_bf16.h>
#include <cstdint>

// Problem constants
#define Bb 4
#define Cc 256
#define C2v 128
#define Nn 4096

// ---------------------------------------------------------------------------
// Scratch (__device__ globals; allocation-free rule)
// ---------------------------------------------------------------------------
__device__ __half         g_qc[(size_t)Bb * Nn * 256];   // [B][n][256] = [qh|ql]
__device__ __half         g_kc[(size_t)Bb * Nn * 256];   // [B][n][256] = [kh|kh] (masked)
__device__ __nv_bfloat16  g_vb[(size_t)Bb * Cc * Nn];    // [B][c][n]  (K-major for AV)
__device__ __nv_bfloat16  g_attb[(size_t)Bb * Nn * Nn];  // P = exp(S), bf16
__device__ float          g_sumexp[(size_t)Bb * Nn * 32];// per-row per-chunk sum of exp
__device__ float          g_zinv[(size_t)Bb * Nn];       // 1 / rowsum

// ---------------------------------------------------------------------------
// Helpers
// ---------------------------------------------------------------------------
__device__ __forceinline__ uint32_t smem_u32(const void* p) {
    uint32_t a;
    asm("{ .reg .u64 t; cvta.to.shared.u64 t, %1; cvt.u32.u64 %0, t; }" : "=r"(a) : "l"(p));
    return a;
}
__device__ __forceinline__ void cp_async16(uint32_t dst, const void* src) {
    asm volatile("cp.async.cg.shared.global [%0], [%1], 16;" :: "r"(dst), "l"(src));
}
#define CP_COMMIT() asm volatile("cp.async.commit_group;" ::: "memory")
template <int N>
__device__ __forceinline__ void cp_wait() {
    asm volatile("cp.async.wait_group %0;" :: "n"(N) : "memory");
}
__device__ __forceinline__ void ldmx4(uint32_t* r, uint32_t addr) {
    asm volatile("ldmatrix.sync.aligned.m8n8.x4.shared.b16 {%0,%1,%2,%3}, [%4];"
        : "=r"(r[0]), "=r"(r[1]), "=r"(r[2]), "=r"(r[3]) : "r"(addr));
}
__device__ __forceinline__ void mma16816(float* d, const uint32_t* a, uint32_t b0, uint32_t b1) {
    asm volatile(
        "mma.sync.aligned.m16n8k16.row.col.f32.f16.f16.f32 "
        "{%0,%1,%2,%3},{%4,%5,%6,%7},{%8,%9},{%0,%1,%2,%3};"
        : "+f"(d[0]), "+f"(d[1]), "+f"(d[2]), "+f"(d[3])
        : "r"(a[0]), "r"(a[1]), "r"(a[2]), "r"(a[3]), "r"(b0), "r"(b1));
}
__device__ __forceinline__ void mma16816bf(float* d, const uint32_t* a, uint32_t b0, uint32_t b1) {
    asm volatile(
        "mma.sync.aligned.m16n8k16.row.col.f32.bf16.bf16.f32 "
        "{%0,%1,%2,%3},{%4,%5,%6,%7},{%8,%9},{%0,%1,%2,%3};"
        : "+f"(d[0]), "+f"(d[1]), "+f"(d[2]), "+f"(d[3])
        : "r"(a[0]), "r"(a[1]), "r"(a[2]), "r"(a[3]), "r"(b0), "r"(b1));
}

// Fast exp (FFMA-only)
__device__ __forceinline__ float fexp(float x) {
    float t = fmaxf(x * 1.4426950408889634f, -126.0f);
    float fi = floorf(t);
    float f = t - fi;
    float p = 0.0013333558f;
    p = fmaf(p, f, 0.0096181291f);
    p = fmaf(p, f, 0.0555041087f);
    p = fmaf(p, f, 0.2402265069f);
    p = fmaf(p, f, 0.6931471806f);
    p = fmaf(p, f, 1.0f);
    return p * __int_as_float(((int)fi + 127) << 23);
}

// ---------------------------------------------------------------------------
// GEMM tile geometry: 128x128 block, BK=32, 8 warps (2x4)
// smem tile: 128 rows x 32 halfwords, row stride 80B; 3-stage ring.
// ---------------------------------------------------------------------------
#define ROWB 80                 // bytes per smem tile row
#define TILE_B (128 * ROWB)     // 10240 per operand tile
#define STAGE_PAIR (2 * TILE_B) // 20480 per stage (A+B)
#define NSTAGE 3
#define DYN_SMEM (NSTAGE * STAGE_PAIR)        // 61440

// Load one 128x32 16-bit tile (row-major src, stride elems) into smem tile.
__device__ __forceinline__ void load_tile(uint32_t dst, const __half* src,
                                          size_t stride, int tid)
{
    #pragma unroll
    for (int i = 0; i < 2; i++) {
        int idx = tid + i * 256;          // 0..511
        int row = idx >> 2, c16 = idx & 3;
        cp_async16(dst + row * ROWB + c16 * 16, src + (size_t)row * stride + c16 * 8);
    }
}

// One BK=32 compute step (fp16 operands)
__device__ __forceinline__ void warp_mma_step(float acc[4][4][4], uint32_t abase,
                                              uint32_t bbase, int wy, int wx, int lane)
{
    #pragma unroll
    for (int ks = 0; ks < 2; ks++) {
        uint32_t a[4][4];
        #pragma unroll
        for (int mf = 0; mf < 4; mf++) {
            int row = wy * 64 + mf * 16 + (lane & 15);
            ldmx4(a[mf], abase + row * ROWB + ks * 32 + ((lane >> 4) << 4));
        }
        uint32_t bf[2][4];
        #pragma unroll
        for (int np = 0; np < 2; np++) {
            int row = wx * 32 + np * 16 + (lane & 7) + ((lane >> 4) << 3);
            ldmx4(bf[np], bbase + row * ROWB + ks * 32 + (((lane >> 3) & 1) << 4));
        }
        #pragma unroll
        for (int mf = 0; mf < 4; mf++)
            #pragma unroll
            for (int nf = 0; nf < 4; nf++)
                mma16816(acc[mf][nf], a[mf],
                         bf[nf >> 1][(nf & 1) * 2], bf[nf >> 1][(nf & 1) * 2 + 1]);
    }
}

// Same, bf16 operands
__device__ __forceinline__ void warp_mma_step_bf(float acc[4][4][4], uint32_t abase,
                                                 uint32_t bbase, int wy, int wx, int lane)
{
    #pragma unroll
    for (int ks = 0; ks < 2; ks++) {
        uint32_t a[4][4];
        #pragma unroll
        for (int mf = 0; mf < 4; mf++) {
            int row = wy * 64 + mf * 16 + (lane & 15);
            ldmx4(a[mf], abase + row * ROWB + ks * 32 + ((lane >> 4) << 4));
        }
        uint32_t bf[2][4];
        #pragma unroll
        for (int np = 0; np < 2; np++) {
            int row = wx * 32 + np * 16 + (lane & 7) + ((lane >> 4) << 3);
            ldmx4(bf[np], bbase + row * ROWB + ks * 32 + (((lane >> 3) & 1) << 4));
        }
        #pragma unroll
        for (int mf = 0; mf < 4; mf++)
            #pragma unroll
            for (int nf = 0; nf < 4; nf++)
                mma16816bf(acc[mf][nf], a[mf],
                           bf[nf >> 1][(nf & 1) * 2], bf[nf >> 1][(nf & 1) * 2 + 1]);
    }
}

// ---------------------------------------------------------------------------
// Kernel 1: projections (SIMT fp32) -> fp16 q/k (split), bf16 v
// ---------------------------------------------------------------------------
#define BK 8
#define SSTR 132

__global__ __launch_bounds__(256) void proj_kernel(
    const float* __restrict__ x, const float* __restrict__ mask,
    const float* __restrict__ skin,
    const float* __restrict__ Wq, const float* __restrict__ bq,
    const float* __restrict__ Wk, const float* __restrict__ bk,
    const float* __restrict__ Wv, const float* __restrict__ bv)
{
    __shared__ float As[BK * SSTR];
    __shared__ float Bs[BK * SSTR];

    const int b    = blockIdx.z;
    const int m0   = blockIdx.y * 128;
    const int oblk = blockIdx.x;   // 0:q, 1:k, 2,3:v

    const float* Wp; const float* biasp; int orow0;
    if (oblk == 0)      { Wp = Wq; biasp = bq; orow0 = 0; }
    else if (oblk == 1) { Wp = Wk; biasp = bk; orow0 = 0; }
    else                { Wp = Wv; biasp = bv; orow0 = (oblk - 2) * 128; }

    const int tid = threadIdx.x;
    const int tx = tid & 15, ty = tid >> 4;
    const float* xb = x + (size_t)b * Cc * Nn;

    const int a_k = tid >> 5;
    const int a_m = (tid & 31) * 4;
    const int b_o = tid >> 1;
    const int b_kg = (tid & 1) * 4;

    float acc[8][8] = {};

    for (int k0 = 0; k0 < Cc; k0 += BK) {
        float4 av = *reinterpret_cast<const float4*>(xb + (size_t)(k0 + a_k) * Nn + m0 + a_m);
        *reinterpret_cast<float4*>(&As[a_k * SSTR + a_m]) = av;
        float4 wv = *reinterpret_cast<const float4*>(Wp + (size_t)(orow0 + b_o) * Cc + k0 + b_kg);
        Bs[(b_kg + 0) * SSTR + b_o] = wv.x;
        Bs[(b_kg + 1) * SSTR + b_o] = wv.y;
        Bs[(b_kg + 2) * SSTR + b_o] = wv.z;
        Bs[(b_kg + 3) * SSTR + b_o] = wv.w;
        __syncthreads();
        #pragma unroll
        for (int k = 0; k < BK; k++) {
            float4 a0 = *reinterpret_cast<const float4*>(&As[k * SSTR + ty * 8]);
            float4 a1 = *reinterpret_cast<const float4*>(&As[k * SSTR + ty * 8 + 4]);
            float4 b0 = *reinterpret_cast<const float4*>(&Bs[k * SSTR + tx * 8]);
            float4 b1 = *reinterpret_cast<const float4*>(&Bs[k * SSTR + tx * 8 + 4]);
            float a[8] = {a0.x, a0.y, a0.z, a0.w, a1.x, a1.y, a1.z, a1.w};
            float bb[8] = {b0.x, b0.y, b0.z, b0.w, b1.x, b1.y, b1.z, b1.w};
            #pragma unroll
            for (int i = 0; i < 8; i++)
                #pragma unroll
                for (int j = 0; j < 8; j++)
                    acc[i][j] = fmaf(a[i], bb[j], acc[i][j]);
        }
        __syncthreads();
    }

    const int obase = tx * 8;
    float bias[8];
    #pragma unroll
    for (int j = 0; j < 8; j++) bias[j] = biasp[orow0 + obase + j];

    if (oblk <= 1) {
        #pragma unroll
        for (int i = 0; i < 8; i++) {
            const int m = m0 + ty * 8 + i;
            float f = 1.0f;
            if (oblk == 1) f = (1.0f - mask[b * Nn + m]) * skin[b * Nn + m];
            __half h8[8], l8[8];
            #pragma unroll
            for (int j = 0; j < 8; j++) {
                float r = (acc[i][j] + bias[j]) * f;
                __half h = __float2half(r);
                h8[j] = h;
                l8[j] = __float2half(r - __half2float(h));
            }
            const size_t off = ((size_t)b * Nn + m) * 256 + obase;
            if (oblk == 0) {
                // qc = [qh | ql]
                *reinterpret_cast<float4*>(g_qc + off)       = *reinterpret_cast<float4*>(h8);
                *reinterpret_cast<float4*>(g_qc + off + 128) = *reinterpret_cast<float4*>(l8);
            } else {
                // kc = [kh | kh]
                *reinterpret_cast<float4*>(g_kc + off)       = *reinterpret_cast<float4*>(h8);
                *reinterpret_cast<float4*>(g_kc + off + 128) = *reinterpret_cast<float4*>(h8);
            }
        }
    } else {
        // v: [c][n] layout, bf16
        #pragma unroll
        for (int j = 0; j < 8; j++) {
            const int c = orow0 + obase + j;
            __nv_bfloat16 h8[8];
            #pragma unroll
            for (int i = 0; i < 8; i++) h8[i] = __float2bfloat16(acc[i][j] + bias[j]);
            const size_t off = ((size_t)b * Cc + c) * Nn + m0 + ty * 8;
            *reinterpret_cast<float4*>(g_vb + off) = *reinterpret_cast<float4*>(h8);
        }
    }
}

// ---------------------------------------------------------------------------
// Kernel 2: QK^T -> P = exp(S) (no max subtraction; S range ~ ±25 is safe)
//   S = qh·kh + ql·kh (K=256 2-term split)
//   P -> g_attb bf16; per-row chunk sums -> g_sumexp
// grid (32 nchunk, 32 mtile, B), 256 threads, dynamic smem 61440
// ---------------------------------------------------------------------------
__global__ __launch_bounds__(256, 2) void qk_kernel()
{
    extern __shared__ __align__(128) char dynsm[];
    const int b = blockIdx.z, m0 = blockIdx.y * 128, n0 = blockIdx.x * 128;
    const int chunk = blockIdx.x;
    const int tid = threadIdx.x, wid = tid >> 5, lane = tid & 31;
    const int wy = wid >> 2, wx = wid & 3;
    const uint32_t sb = smem_u32(dynsm);

    const __half* Asrc = g_qc + ((size_t)b * Nn + m0) * 256;
    const __half* Bsrc = g_kc + ((size_t)b * Nn + n0) * 256;

    const int NK = 256 / 32;   // 8
    #pragma unroll
    for (int s = 0; s < 2; s++) {
        uint32_t st = sb + s * STAGE_PAIR;
        load_tile(st, Asrc + s * 32, 256, tid);
        load_tile(st + TILE_B, Bsrc + s * 32, 256, tid);
        CP_COMMIT();
    }

    float acc[4][4][4] = {};
    #pragma unroll 1
    for (int s = 0; s < NK; s++) {
        if (s < NK - 1) cp_wait<1>(); else cp_wait<0>();
        __syncthreads();
        if (s + 2 < NK) {
            uint32_t ld = sb + (uint32_t)((s + 2) % NSTAGE) * STAGE_PAIR;
            load_tile(ld, Asrc + (s + 2) * 32, 256, tid);
            load_tile(ld + TILE_B, Bsrc + (s + 2) * 32, 256, tid);
            CP_COMMIT();
        }
        const uint32_t st = sb + (uint32_t)(s % NSTAGE) * STAGE_PAIR;
        warp_mma_step(acc, st, st + TILE_B, wy, wx, lane);
    }

    // ---- one-pass epilogue: exp, stage P (bf16), row sums ----
    __syncthreads();
    float* sred = reinterpret_cast<float*>(dynsm);                  // [4][128]
    __nv_bfloat16* pst = reinterpret_cast<__nv_bfloat16*>(dynsm + 4096); // [128][128]

    float rsum[4][2];
    #pragma unroll
    for (int mf = 0; mf < 4; mf++) {
        int rA = wy * 64 + mf * 16 + (lane >> 2);
        int rB = rA + 8;
        float sA = 0.0f, sB = 0.0f;
        #pragma unroll
        for (int nf = 0; nf < 4; nf++) {
            float p0 = fexp(acc[mf][nf][0]);
            float p1 = fexp(acc[mf][nf][1]);
            float p2 = fexp(acc[mf][nf][2]);
            float p3 = fexp(acc[mf][nf][3]);
            sA += p0 + p1; sB += p2 + p3;
            int cl = wx * 32 + nf * 8 + (lane & 3) * 2;
            *reinterpret_cast<__nv_bfloat162*>(pst + rA * 128 + cl) = __floats2bfloat162_rn(p0, p1);
            *reinterpret_cast<__nv_bfloat162*>(pst + rB * 128 + cl) = __floats2bfloat162_rn(p2, p3);
        }
        rsum[mf][0] = sA; rsum[mf][1] = sB;
    }
    #pragma unroll
    for (int o = 1; o <= 2; o <<= 1)
        #pragma unroll
        for (int mf = 0; mf < 4; mf++) {
            rsum[mf][0] += __shfl_xor_sync(0xffffffffu, rsum[mf][0], o);
            rsum[mf][1] += __shfl_xor_sync(0xffffffffu, rsum[mf][1], o);
        }
    if ((lane & 3) == 0) {
        #pragma unroll
        for (int mf = 0; mf < 4; mf++) {
            int rA = wy * 64 + mf * 16 + (lane >> 2);
            sred[wx * 128 + rA]     = rsum[mf][0];
            sred[wx * 128 + rA + 8] = rsum[mf][1];
        }
    }
    __syncthreads();
    if (tid < 128) {
        float se = sred[tid] + sred[128 + tid] + sred[256 + tid] + sred[384 + tid];
        g_sumexp[((size_t)b * Nn + m0 + tid) * 32 + chunk] = se;
    }

    // coalesced P write-out
    #pragma unroll
    for (int i = 0; i < 8; i++) {
        int f4 = tid + i * 256;           // 0..2047 float4s
        int row = f4 >> 4, c8 = (f4 & 15) * 8;
        float4 v = *reinterpret_cast<float4*>(pst + row * 128 + c8);
        *reinterpret_cast<float4*>(g_attb + ((size_t)b * Nn + m0 + row) * Nn + n0 + c8) = v;
    }
}

// ---------------------------------------------------------------------------
// Kernel 3: zinv[row] = 1 / sum_chunks sumexp[row][chunk]
// ---------------------------------------------------------------------------
__global__ __launch_bounds__(256) void zinv_kernel()
{
    const size_t row = (size_t)blockIdx.x * 256 + threadIdx.x;  // Bb*Nn total
    const float4* p = reinterpret_cast<const float4*>(g_sumexp + row * 32);
    float s = 0.0f;
    #pragma unroll
    for (int i = 0; i < 8; i++) {
        float4 v = p[i];
        s += (v.x + v.y) + (v.z + v.w);
    }
    g_zinv[row] = 1.0f / s;
}

// ---------------------------------------------------------------------------
// Kernel 4: AV via mma.sync bf16 (clean loop) + epilogue normalization
//   out[c][m] = gamma*fm[m]*zinv[m]*D[m][c] + x[c][m]
// grid (2 ctile, 32 mtile, B), 256 threads, dynamic smem 61440
// ---------------------------------------------------------------------------
__global__ __launch_bounds__(256, 2) void av_kernel(
    const float* __restrict__ x, const float* __restrict__ mask,
    const float* __restrict__ skin, const float* __restrict__ gamma,
    float* __restrict__ out)
{
    extern __shared__ __align__(128) char dynsm[];
    __shared__ float fmv[128];
    __shared__ float szv[128];
    const int b = blockIdx.z, m0 = blockIdx.y * 128, c0 = blockIdx.x * 128;
    const int tid = threadIdx.x, wid = tid >> 5, lane = tid & 31;
    const int wy = wid >> 2, wx = wid & 3;
    const uint32_t sb = smem_u32(dynsm);

    if (tid < 128) {
        fmv[tid] = mask[(size_t)b * Nn + m0 + tid] * skin[(size_t)b * Nn + m0 + tid];
        szv[tid] = g_zinv[(size_t)b * Nn + m0 + tid];
    }

    const __half* Asrc = reinterpret_cast<const __half*>(g_attb + ((size_t)b * Nn + m0) * Nn);
    const __half* Bsrc = reinterpret_cast<const __half*>(g_vb + ((size_t)b * Cc + c0) * Nn);

    const int NK = Nn / 32;   // 128
    #pragma unroll
    for (int s = 0; s < 2; s++) {
        uint32_t st = sb + s * STAGE_PAIR;
        load_tile(st, Asrc + s * 32, Nn, tid);
        load_tile(st + TILE_B, Bsrc + s * 32, Nn, tid);
        CP_COMMIT();
    }

    float acc[4][4][4] = {};
    #pragma unroll 1
    for (int s = 0; s < NK; s++) {
        if (s < NK - 1) cp_wait<1>(); else cp_wait<0>();
        __syncthreads();
        if (s + 2 < NK) {
            uint32_t ld = sb + (uint32_t)((s + 2) % NSTAGE) * STAGE_PAIR;
            load_tile(ld, Asrc + (s + 2) * 32, Nn, tid);
            load_tile(ld + TILE_B, Bsrc + (s + 2) * 32, Nn, tid);
            CP_COMMIT();
        }
        const uint32_t st = sb + (uint32_t)(s % NSTAGE) * STAGE_PAIR;
        warp_mma_step_bf(acc, st, st + TILE_B, wy, wx, lane);
    }

    // Fused epilogue: out[c][m] = gamma*fm[m]*zinv[m]*D[m][c] + x[c][m]
    const float gm = __ldg(gamma);
    #pragma unroll
    for (int mf = 0; mf < 4; mf++) {
        const int ml = wy * 64 + mf * 16 + (lane >> 2);    // local m (0..127)
        const float f0 = gm * fmv[ml] * szv[ml];
        const float f1 = gm * fmv[ml + 8] * szv[ml + 8];
        #pragma unroll
        for (int nf = 0; nf < 4; nf++) {
            const int c = c0 + wx * 32 + nf * 8 + (lane & 3) * 2;
            const size_t b0i = ((size_t)b * Cc + c) * Nn + m0 + ml;
            const size_t b1i = b0i + Nn;   // c+1
            out[b0i]     = fmaf(f0, acc[mf][nf][0], x[b0i]);
            out[b1i]     = fmaf(f0, acc[mf][nf][1], x[b1i]);
            out[b0i + 8] = fmaf(f1, acc[mf][nf][2], x[b0i + 8]);
            out[b1i + 8] = fmaf(f1, acc[mf][nf][3], x[b1i + 8]);
        }
    }
}

// ---------------------------------------------------------------------------
extern "C" void kernel_launch(void* const* d_in, const int* in_sizes, int n_in,
                              void* d_out, int out_size)
{
    (void)in_sizes; (void)n_in; (void)out_size;
    const float* x     = (const float*)d_in[0];
    const float* mask  = (const float*)d_in[1];
    const float* skin  = (const float*)d_in[2];
    const float* Wq    = (const float*)d_in[3];
    const float* bq    = (const float*)d_in[4];
    const float* Wk    = (const float*)d_in[5];
    const float* bk    = (const float*)d_in[6];
    const float* Wv    = (const float*)d_in[7];
    const float* bv    = (const float*)d_in[8];
    const float* gamma = (const float*)d_in[9];
    float* out = (float*)d_out;

    cudaFuncSetAttribute(qk_kernel, cudaFuncAttributeMaxDynamicSharedMemorySize, DYN_SMEM);
    cudaFuncSetAttribute(av_kernel, cudaFuncAttributeMaxDynamicSharedMemorySize, DYN_SMEM);

    dim3 gA(4, 32, Bb);
    proj_kernel<<<gA, 256>>>(x, mask, skin, Wq, bq, Wk, bk, Wv, bv);

    dim3 gQK(32, 32, Bb);
    qk_kernel<<<gQK, 256, DYN_SMEM>>>();

    zinv_kernel<<<(Bb * Nn) / 256, 256>>>();

    dim3 gAV(2, 32, Bb);
    av_kernel<<<gAV, 256, DYN_SMEM>>>(x, mask, skin, gamma, out);
}

// round 10
// speedup vs baseline: 1.4149x; 1.1489x over previous
#include <cuda_runtime.h>
#include <cuda_fp16.h>
#include <cuda_bf16.h>
#include <cstdint>

// Problem constants
#define Bb 4
#define Cc 256
#define C2v 128
#define Nn 4096

// ---------------------------------------------------------------------------
// Scratch (__device__ globals; allocation-free rule)
// ---------------------------------------------------------------------------
__device__ __half         g_xh[(size_t)Bb * Nn * 256];   // [B][n][c] fp16 hi of x
__device__ __half         g_xl[(size_t)Bb * Nn * 256];   // [B][n][c] fp16 lo of x
__device__ __half         g_wh[(size_t)512 * 256];       // [o][c]: q 0-127, k 128-255, v 256-511
__device__ __half         g_wl[(size_t)512 * 256];
__device__ __half         g_qc[(size_t)Bb * Nn * 256];   // [B][n][256] = [qh|ql]
__device__ __half         g_kc[(size_t)Bb * Nn * 256];   // [B][n][256] = [kh|kh] (masked)
__device__ __nv_bfloat16  g_vt[(size_t)Bb * Nn * Cc];    // [B][n][c] bf16 (pre-transpose)
__device__ __nv_bfloat16  g_vb[(size_t)Bb * Cc * Nn];    // [B][c][n]  (K-major for AV)
__device__ __nv_bfloat16  g_attb[(size_t)Bb * Nn * Nn];  // P = exp(S), bf16
__device__ float          g_sumexp[(size_t)Bb * Nn * 32];// per-row per-chunk sum of exp
__device__ float          g_zinv[(size_t)Bb * Nn];       // 1 / rowsum

// ---------------------------------------------------------------------------
// Helpers
// ---------------------------------------------------------------------------
__device__ __forceinline__ uint32_t smem_u32(const void* p) {
    uint32_t a;
    asm("{ .reg .u64 t; cvta.to.shared.u64 t, %1; cvt.u32.u64 %0, t; }" : "=r"(a) : "l"(p));
    return a;
}
__device__ __forceinline__ void cp_async16(uint32_t dst, const void* src) {
    asm volatile("cp.async.cg.shared.global [%0], [%1], 16;" :: "r"(dst), "l"(src));
}
#define CP_COMMIT() asm volatile("cp.async.commit_group;" ::: "memory")
template <int N>
__device__ __forceinline__ void cp_wait() {
    asm volatile("cp.async.wait_group %0;" :: "n"(N) : "memory");
}
__device__ __forceinline__ void ldmx4(uint32_t* r, uint32_t addr) {
    asm volatile("ldmatrix.sync.aligned.m8n8.x4.shared.b16 {%0,%1,%2,%3}, [%4];"
        : "=r"(r[0]), "=r"(r[1]), "=r"(r[2]), "=r"(r[3]) : "r"(addr));
}
__device__ __forceinline__ void mma16816(float* d, const uint32_t* a, uint32_t b0, uint32_t b1) {
    asm volatile(
        "mma.sync.aligned.m16n8k16.row.col.f32.f16.f16.f32 "
        "{%0,%1,%2,%3},{%4,%5,%6,%7},{%8,%9},{%0,%1,%2,%3};"
        : "+f"(d[0]), "+f"(d[1]), "+f"(d[2]), "+f"(d[3])
        : "r"(a[0]), "r"(a[1]), "r"(a[2]), "r"(a[3]), "r"(b0), "r"(b1));
}
__device__ __forceinline__ void mma16816bf(float* d, const uint32_t* a, uint32_t b0, uint32_t b1) {
    asm volatile(
        "mma.sync.aligned.m16n8k16.row.col.f32.bf16.bf16.f32 "
        "{%0,%1,%2,%3},{%4,%5,%6,%7},{%8,%9},{%0,%1,%2,%3};"
        : "+f"(d[0]), "+f"(d[1]), "+f"(d[2]), "+f"(d[3])
        : "r"(a[0]), "r"(a[1]), "r"(a[2]), "r"(a[3]), "r"(b0), "r"(b1));
}

// Fast exp (FFMA-only)
__device__ __forceinline__ float fexp(float x) {
    float t = fmaxf(x * 1.4426950408889634f, -126.0f);
    float fi = floorf(t);
    float f = t - fi;
    float p = 0.0013333558f;
    p = fmaf(p, f, 0.0096181291f);
    p = fmaf(p, f, 0.0555041087f);
    p = fmaf(p, f, 0.2402265069f);
    p = fmaf(p, f, 0.6931471806f);
    p = fmaf(p, f, 1.0f);
    return p * __int_as_float(((int)fi + 127) << 23);
}

// ---------------------------------------------------------------------------
// GEMM tile geometry: 128x128 block, BK=32, 8 warps (2x4)
// smem tile: 128 rows x 32 halfwords, row stride 80B; 3-stage ring.
// ---------------------------------------------------------------------------
#define ROWB 80                 // bytes per smem tile row
#define TILE_B (128 * ROWB)     // 10240 per operand tile
#define STAGE_PAIR (2 * TILE_B) // 20480 per stage (A+B)
#define NSTAGE 3
#define DYN_SMEM (NSTAGE * STAGE_PAIR)        // 61440

// Load one 128x32 16-bit tile (row-major src, stride elems) into smem tile.
__device__ __forceinline__ void load_tile(uint32_t dst, const __half* src,
                                          size_t stride, int tid)
{
    #pragma unroll
    for (int i = 0; i < 2; i++) {
        int idx = tid + i * 256;          // 0..511
        int row = idx >> 2, c16 = idx & 3;
        cp_async16(dst + row * ROWB + c16 * 16, src + (size_t)row * stride + c16 * 8);
    }
}

// One BK=32 compute step (fp16 operands)
__device__ __forceinline__ void warp_mma_step(float acc[4][4][4], uint32_t abase,
                                              uint32_t bbase, int wy, int wx, int lane)
{
    #pragma unroll
    for (int ks = 0; ks < 2; ks++) {
        uint32_t a[4][4];
        #pragma unroll
        for (int mf = 0; mf < 4; mf++) {
            int row = wy * 64 + mf * 16 + (lane & 15);
            ldmx4(a[mf], abase + row * ROWB + ks * 32 + ((lane >> 4) << 4));
        }
        uint32_t bf[2][4];
        #pragma unroll
        for (int np = 0; np < 2; np++) {
            int row = wx * 32 + np * 16 + (lane & 7) + ((lane >> 4) << 3);
            ldmx4(bf[np], bbase + row * ROWB + ks * 32 + (((lane >> 3) & 1) << 4));
        }
        #pragma unroll
        for (int mf = 0; mf < 4; mf++)
            #pragma unroll
            for (int nf = 0; nf < 4; nf++)
                mma16816(acc[mf][nf], a[mf],
                         bf[nf >> 1][(nf & 1) * 2], bf[nf >> 1][(nf & 1) * 2 + 1]);
    }
}

// Same, bf16 operands
__device__ __forceinline__ void warp_mma_step_bf(float acc[4][4][4], uint32_t abase,
                                                 uint32_t bbase, int wy, int wx, int lane)
{
    #pragma unroll
    for (int ks = 0; ks < 2; ks++) {
        uint32_t a[4][4];
        #pragma unroll
        for (int mf = 0; mf < 4; mf++) {
            int row = wy * 64 + mf * 16 + (lane & 15);
            ldmx4(a[mf], abase + row * ROWB + ks * 32 + ((lane >> 4) << 4));
        }
        uint32_t bf[2][4];
        #pragma unroll
        for (int np = 0; np < 2; np++) {
            int row = wx * 32 + np * 16 + (lane & 7) + ((lane >> 4) << 3);
            ldmx4(bf[np], bbase + row * ROWB + ks * 32 + (((lane >> 3) & 1) << 4));
        }
        #pragma unroll
        for (int mf = 0; mf < 4; mf++)
            #pragma unroll
            for (int nf = 0; nf < 4; nf++)
                mma16816bf(acc[mf][nf], a[mf],
                           bf[nf >> 1][(nf & 1) * 2], bf[nf >> 1][(nf & 1) * 2 + 1]);
    }
}

// ---------------------------------------------------------------------------
// Kernel 0a: xcvt — transpose-convert x [B][c][n] fp32 -> g_xh/g_xl [B][n][c] fp16
// 64x64 tiles. grid (64 ntile, 4 ctile, B), 256 threads.
// ---------------------------------------------------------------------------
__global__ __launch_bounds__(256) void xcvt_kernel(const float* __restrict__ x)
{
    __shared__ float ts[64][65];
    const int b = blockIdx.z, n0 = blockIdx.x * 64, c0 = blockIdx.y * 64;
    const int tid = threadIdx.x;

    #pragma unroll
    for (int i = 0; i < 4; i++) {
        int idx = tid + i * 256;          // 0..1023
        int r = idx >> 4, f4 = idx & 15;  // row c-local, 16B col group
        float4 v = *reinterpret_cast<const float4*>(
            x + ((size_t)b * Cc + c0 + r) * Nn + n0 + f4 * 4);
        ts[r][f4 * 4 + 0] = v.x;
        ts[r][f4 * 4 + 1] = v.y;
        ts[r][f4 * 4 + 2] = v.z;
        ts[r][f4 * 4 + 3] = v.w;
    }
    __syncthreads();

    const int nr = tid >> 2;
    #pragma unroll
    for (int i = 0; i < 2; i++) {
        int c8 = ((tid & 3) * 2 + i) * 8;
        __half h8[8], l8[8];
        #pragma unroll
        for (int j = 0; j < 8; j++) {
            float v = ts[c8 + j][nr];
            __half h = __float2half(v);
            h8[j] = h;
            l8[j] = __float2half(v - __half2float(h));
        }
        size_t off = ((size_t)b * Nn + n0 + nr) * 256 + c0 + c8;
        *reinterpret_cast<float4*>(g_xh + off) = *reinterpret_cast<float4*>(h8);
        *reinterpret_cast<float4*>(g_xl + off) = *reinterpret_cast<float4*>(l8);
    }
}

// ---------------------------------------------------------------------------
// Kernel 0b: wcvt — Wq|Wk|Wv fp32 -> g_wh/g_wl fp16 [512][256]
// grid 128, 256 threads, 4 elems/thread.
// ---------------------------------------------------------------------------
__global__ __launch_bounds__(256) void wcvt_kernel(
    const float* __restrict__ Wq, const float* __restrict__ Wk,
    const float* __restrict__ Wv)
{
    int e4 = blockIdx.x * 256 + threadIdx.x;   // 0..32767
    int row = e4 >> 6, col4 = (e4 & 63) * 4;
    const float* src = (row < 128) ? (Wq + (size_t)row * 256)
                     : (row < 256) ? (Wk + (size_t)(row - 128) * 256)
                                   : (Wv + (size_t)(row - 256) * 256);
    float4 v = *reinterpret_cast<const float4*>(src + col4);
    __half h4[4], l4[4];
    float vv[4] = {v.x, v.y, v.z, v.w};
    #pragma unroll
    for (int j = 0; j < 4; j++) {
        __half h = __float2half(vv[j]);
        h4[j] = h;
        l4[j] = __float2half(vv[j] - __half2float(h));
    }
    size_t off = (size_t)row * 256 + col4;
    *reinterpret_cast<float2*>(g_wh + off) = *reinterpret_cast<float2*>(h4);
    *reinterpret_cast<float2*>(g_wl + off) = *reinterpret_cast<float2*>(l4);
}

// ---------------------------------------------------------------------------
// Kernel 1: projections via mma.sync fp16.
//   oblk 0 (q), 1 (k): K=768 3-term split  [xh|xl|xh] x [wh|wh|wl]  (fp32-class)
//   oblk 2, 3 (v):     K=256 single term   xh x wh  (bf16 v dominates error)
// grid (4 oblk, 32 mtile, B), 256 threads, dynamic smem 61440.
// ---------------------------------------------------------------------------
__global__ __launch_bounds__(256, 2) void projmma_kernel(
    const float* __restrict__ mask, const float* __restrict__ skin,
    const float* __restrict__ bq, const float* __restrict__ bk,
    const float* __restrict__ bv)
{
    extern __shared__ __align__(128) char dynsm[];
    __shared__ float fm[128];
    const int b = blockIdx.z, m0 = blockIdx.y * 128, oblk = blockIdx.x;
    const int tid = threadIdx.x, wid = tid >> 5, lane = tid & 31;
    const int wy = wid >> 2, wx = wid & 3;
    const uint32_t sb = smem_u32(dynsm);

    const int NK = (oblk < 2) ? 24 : 8;
    const size_t orow = (size_t)oblk * 128;
    const size_t abase_off = ((size_t)b * Nn + m0) * 256;

    if (oblk == 1 && tid < 128)
        fm[tid] = (1.0f - mask[b * Nn + m0 + tid]) * skin[b * Nn + m0 + tid];

    #pragma unroll
    for (int s = 0; s < 2; s++) {
        uint32_t st = sb + s * STAGE_PAIR;
        const __half* as = g_xh + abase_off + (s & 7) * 32;       // seg 0
        const __half* bs = g_wh + orow * 256 + (s & 7) * 32;
        load_tile(st, as, 256, tid);
        load_tile(st + TILE_B, bs, 256, tid);
        CP_COMMIT();
    }

    float acc[4][4][4] = {};
    #pragma unroll 1
    for (int s = 0; s < NK; s++) {
        if (s < NK - 1) cp_wait<1>(); else cp_wait<0>();
        __syncthreads();
        if (s + 2 < NK) {
            int sp = s + 2;
            int seg = sp >> 3, col = (sp & 7) * 32;
            const __half* as = ((seg == 1) ? g_xl : g_xh) + abase_off + col;
            const __half* bs = ((seg == 2) ? g_wl : g_wh) + orow * 256 + col;
            uint32_t ld = sb + (uint32_t)(sp % NSTAGE) * STAGE_PAIR;
            load_tile(ld, as, 256, tid);
            load_tile(ld + TILE_B, bs, 256, tid);
            CP_COMMIT();
        }
        const uint32_t st = sb + (uint32_t)(s % NSTAGE) * STAGE_PAIR;
        warp_mma_step(acc, st, st + TILE_B, wy, wx, lane);
    }

    // Epilogue
    const float* biasp = (oblk == 0) ? bq : (oblk == 1) ? bk
                       : (oblk == 2) ? bv : (bv + 128);
    float bias0[4], bias1[4];
    #pragma unroll
    for (int nf = 0; nf < 4; nf++) {
        int o = wx * 32 + nf * 8 + (lane & 3) * 2;
        bias0[nf] = biasp[o];
        bias1[nf] = biasp[o + 1];
    }

    #pragma unroll
    for (int mf = 0; mf < 4; mf++) {
        const int rA = wy * 64 + mf * 16 + (lane >> 2);
        const int rB = rA + 8;
        float fA = 1.0f, fB = 1.0f;
        if (oblk == 1) { fA = fm[rA]; fB = fm[rB]; }
        #pragma unroll
        for (int nf = 0; nf < 4; nf++) {
            const int o = wx * 32 + nf * 8 + (lane & 3) * 2;
            float r0 = acc[mf][nf][0] + bias0[nf];
            float r1 = acc[mf][nf][1] + bias1[nf];
            float r2 = acc[mf][nf][2] + bias0[nf];
            float r3 = acc[mf][nf][3] + bias1[nf];
            if (oblk <= 1) {
                if (oblk == 1) { r0 *= fA; r1 *= fA; r2 *= fB; r3 *= fB; }
                __half h0 = __float2half(r0), h1 = __float2half(r1);
                __half h2 = __float2half(r2), h3 = __float2half(r3);
                __half2 hiA = __halves2half2(h0, h1);
                __half2 hiB = __halves2half2(h2, h3);
                __half2 loA, loB;
                if (oblk == 0) {
                    loA = __halves2half2(__float2half(r0 - __half2float(h0)),
                                         __float2half(r1 - __half2float(h1)));
                    loB = __halves2half2(__float2half(r2 - __half2float(h2)),
                                         __float2half(r3 - __half2float(h3)));
                } else { loA = hiA; loB = hiB; }   // kc = [kh | kh]
                __half* dst = (oblk == 0) ? g_qc : g_kc;
                size_t oa = ((size_t)b * Nn + m0 + rA) * 256 + o;
                size_t ob = ((size_t)b * Nn + m0 + rB) * 256 + o;
                *reinterpret_cast<__half2*>(dst + oa)       = hiA;
                *reinterpret_cast<__half2*>(dst + oa + 128) = loA;
                *reinterpret_cast<__half2*>(dst + ob)       = hiB;
                *reinterpret_cast<__half2*>(dst + ob + 128) = loB;
            } else {
                const int c = (oblk - 2) * 128 + o;
                size_t oa = ((size_t)b * Nn + m0 + rA) * 256 + c;
                size_t ob = ((size_t)b * Nn + m0 + rB) * 256 + c;
                *reinterpret_cast<__nv_bfloat162*>(g_vt + oa) = __floats2bfloat162_rn(r0, r1);
                *reinterpret_cast<__nv_bfloat162*>(g_vt + ob) = __floats2bfloat162_rn(r2, r3);
            }
        }
    }
}

// ---------------------------------------------------------------------------
// Kernel 1b: vtrans — g_vt [B][n][c] bf16 -> g_vb [B][c][n]
// 64x64 tiles. grid (64 ntile, 4 ctile, B), 256 threads.
// ---------------------------------------------------------------------------
__global__ __launch_bounds__(256) void vtrans_kernel()
{
    __shared__ __nv_bfloat16 ts[64][72];   // rows 144B (16B-aligned), cols padded
    const int b = blockIdx.z, n0 = blockIdx.x * 64, c0 = blockIdx.y * 64;
    const int tid = threadIdx.x;

    #pragma unroll
    for (int i = 0; i < 2; i++) {
        int idx = tid + i * 256;          // 0..511
        int r = idx >> 3, c8 = (idx & 7) * 8;   // n-local row, 8-col group
        float4 v = *reinterpret_cast<const float4*>(
            g_vt + ((size_t)b * Nn + n0 + r) * 256 + c0 + c8);
        *reinterpret_cast<float4*>(&ts[r][c8]) = v;
    }
    __syncthreads();

    const int cr = tid >> 2;
    #pragma unroll
    for (int i = 0; i < 2; i++) {
        int n8 = ((tid & 3) * 2 + i) * 8;
        __nv_bfloat16 o8[8];
        #pragma unroll
        for (int j = 0; j < 8; j++) o8[j] = ts[n8 + j][cr];
        *reinterpret_cast<float4*>(
            g_vb + ((size_t)b * Cc + c0 + cr) * Nn + n0 + n8) =
            *reinterpret_cast<float4*>(o8);
    }
}

// ---------------------------------------------------------------------------
// Kernel 2: QK^T -> P = exp(S) (no max subtraction; S range ~ ±25 is safe)
//   S = qh·kh + ql·kh (K=256 2-term split)
// grid (32 nchunk, 32 mtile, B), 256 threads, dynamic smem 61440
// ---------------------------------------------------------------------------
__global__ __launch_bounds__(256, 2) void qk_kernel()
{
    extern __shared__ __align__(128) char dynsm[];
    const int b = blockIdx.z, m0 = blockIdx.y * 128, n0 = blockIdx.x * 128;
    const int chunk = blockIdx.x;
    const int tid = threadIdx.x, wid = tid >> 5, lane = tid & 31;
    const int wy = wid >> 2, wx = wid & 3;
    const uint32_t sb = smem_u32(dynsm);

    const __half* Asrc = g_qc + ((size_t)b * Nn + m0) * 256;
    const __half* Bsrc = g_kc + ((size_t)b * Nn + n0) * 256;

    const int NK = 256 / 32;   // 8
    #pragma unroll
    for (int s = 0; s < 2; s++) {
        uint32_t st = sb + s * STAGE_PAIR;
        load_tile(st, Asrc + s * 32, 256, tid);
        load_tile(st + TILE_B, Bsrc + s * 32, 256, tid);
        CP_COMMIT();
    }

    float acc[4][4][4] = {};
    #pragma unroll 1
    for (int s = 0; s < NK; s++) {
        if (s < NK - 1) cp_wait<1>(); else cp_wait<0>();
        __syncthreads();
        if (s + 2 < NK) {
            uint32_t ld = sb + (uint32_t)((s + 2) % NSTAGE) * STAGE_PAIR;
            load_tile(ld, Asrc + (s + 2) * 32, 256, tid);
            load_tile(ld + TILE_B, Bsrc + (s + 2) * 32, 256, tid);
            CP_COMMIT();
        }
        const uint32_t st = sb + (uint32_t)(s % NSTAGE) * STAGE_PAIR;
        warp_mma_step(acc, st, st + TILE_B, wy, wx, lane);
    }

    // ---- one-pass epilogue: exp, stage P (bf16), row sums ----
    __syncthreads();
    float* sred = reinterpret_cast<float*>(dynsm);                  // [4][128]
    __nv_bfloat16* pst = reinterpret_cast<__nv_bfloat16*>(dynsm + 4096); // [128][128]

    float rsum[4][2];
    #pragma unroll
    for (int mf = 0; mf < 4; mf++) {
        int rA = wy * 64 + mf * 16 + (lane >> 2);
        int rB = rA + 8;
        float sA = 0.0f, sB = 0.0f;
        #pragma unroll
        for (int nf = 0; nf < 4; nf++) {
            float p0 = fexp(acc[mf][nf][0]);
            float p1 = fexp(acc[mf][nf][1]);
            float p2 = fexp(acc[mf][nf][2]);
            float p3 = fexp(acc[mf][nf][3]);
            sA += p0 + p1; sB += p2 + p3;
            int cl = wx * 32 + nf * 8 + (lane & 3) * 2;
            *reinterpret_cast<__nv_bfloat162*>(pst + rA * 128 + cl) = __floats2bfloat162_rn(p0, p1);
            *reinterpret_cast<__nv_bfloat162*>(pst + rB * 128 + cl) = __floats2bfloat162_rn(p2, p3);
        }
        rsum[mf][0] = sA; rsum[mf][1] = sB;
    }
    #pragma unroll
    for (int o = 1; o <= 2; o <<= 1)
        #pragma unroll
        for (int mf = 0; mf < 4; mf++) {
            rsum[mf][0] += __shfl_xor_sync(0xffffffffu, rsum[mf][0], o);
            rsum[mf][1] += __shfl_xor_sync(0xffffffffu, rsum[mf][1], o);
        }
    if ((lane & 3) == 0) {
        #pragma unroll
        for (int mf = 0; mf < 4; mf++) {
            int rA = wy * 64 + mf * 16 + (lane >> 2);
            sred[wx * 128 + rA]     = rsum[mf][0];
            sred[wx * 128 + rA + 8] = rsum[mf][1];
        }
    }
    __syncthreads();
    if (tid < 128) {
        float se = sred[tid] + sred[128 + tid] + sred[256 + tid] + sred[384 + tid];
        g_sumexp[((size_t)b * Nn + m0 + tid) * 32 + chunk] = se;
    }

    // coalesced P write-out
    #pragma unroll
    for (int i = 0; i < 8; i++) {
        int f4 = tid + i * 256;           // 0..2047 float4s
        int row = f4 >> 4, c8 = (f4 & 15) * 8;
        float4 v = *reinterpret_cast<float4*>(pst + row * 128 + c8);
        *reinterpret_cast<float4*>(g_attb + ((size_t)b * Nn + m0 + row) * Nn + n0 + c8) = v;
    }
}

// ---------------------------------------------------------------------------
// Kernel 3: zinv[row] = 1 / sum_chunks sumexp[row][chunk]
// ---------------------------------------------------------------------------
__global__ __launch_bounds__(256) void zinv_kernel()
{
    const size_t row = (size_t)blockIdx.x * 256 + threadIdx.x;  // Bb*Nn total
    const float4* p = reinterpret_cast<const float4*>(g_sumexp + row * 32);
    float s = 0.0f;
    #pragma unroll
    for (int i = 0; i < 8; i++) {
        float4 v = p[i];
        s += (v.x + v.y) + (v.z + v.w);
    }
    g_zinv[row] = 1.0f / s;
}

// ---------------------------------------------------------------------------
// Kernel 4: AV via mma.sync bf16 (clean loop) + epilogue normalization
//   out[c][m] = gamma*fm[m]*zinv[m]*D[m][c] + x[c][m]
// grid (2 ctile, 32 mtile, B), 256 threads, dynamic smem 61440
// ---------------------------------------------------------------------------
__global__ __launch_bounds__(256, 2) void av_kernel(
    const float* __restrict__ x, const float* __restrict__ mask,
    const float* __restrict__ skin, const float* __restrict__ gamma,
    float* __restrict__ out)
{
    extern __shared__ __align__(128) char dynsm[];
    __shared__ float fmv[128];
    __shared__ float szv[128];
    const int b = blockIdx.z, m0 = blockIdx.y * 128, c0 = blockIdx.x * 128;
    const int tid = threadIdx.x, wid = tid >> 5, lane = tid & 31;
    const int wy = wid >> 2, wx = wid & 3;
    const uint32_t sb = smem_u32(dynsm);

    if (tid < 128) {
        fmv[tid] = mask[(size_t)b * Nn + m0 + tid] * skin[(size_t)b * Nn + m0 + tid];
        szv[tid] = g_zinv[(size_t)b * Nn + m0 + tid];
    }

    const __half* Asrc = reinterpret_cast<const __half*>(g_attb + ((size_t)b * Nn + m0) * Nn);
    const __half* Bsrc = reinterpret_cast<const __half*>(g_vb + ((size_t)b * Cc + c0) * Nn);

    const int NK = Nn / 32;   // 128
    #pragma unroll
    for (int s = 0; s < 2; s++) {
        uint32_t st = sb + s * STAGE_PAIR;
        load_tile(st, Asrc + s * 32, Nn, tid);
        load_tile(st + TILE_B, Bsrc + s * 32, Nn, tid);
        CP_COMMIT();
    }

    float acc[4][4][4] = {};
    #pragma unroll 1
    for (int s = 0; s < NK; s++) {
        if (s < NK - 1) cp_wait<1>(); else cp_wait<0>();
        __syncthreads();
        if (s + 2 < NK) {
            uint32_t ld = sb + (uint32_t)((s + 2) % NSTAGE) * STAGE_PAIR;
            load_tile(ld, Asrc + (s + 2) * 32, Nn, tid);
            load_tile(ld + TILE_B, Bsrc + (s + 2) * 32, Nn, tid);
            CP_COMMIT();
        }
        const uint32_t st = sb + (uint32_t)(s % NSTAGE) * STAGE_PAIR;
        warp_mma_step_bf(acc, st, st + TILE_B, wy, wx, lane);
    }

    // Fused epilogue: out[c][m] = gamma*fm[m]*zinv[m]*D[m][c] + x[c][m]
    const float gm = __ldg(gamma);
    #pragma unroll
    for (int mf = 0; mf < 4; mf++) {
        const int ml = wy * 64 + mf * 16 + (lane >> 2);    // local m (0..127)
        const float f0 = gm * fmv[ml] * szv[ml];
        const float f1 = gm * fmv[ml + 8] * szv[ml + 8];
        #pragma unroll
        for (int nf = 0; nf < 4; nf++) {
            const int c = c0 + wx * 32 + nf * 8 + (lane & 3) * 2;
            const size_t b0i = ((size_t)b * Cc + c) * Nn + m0 + ml;
            const size_t b1i = b0i + Nn;   // c+1
            out[b0i]     = fmaf(f0, acc[mf][nf][0], x[b0i]);
            out[b1i]     = fmaf(f0, acc[mf][nf][1], x[b1i]);
            out[b0i + 8] = fmaf(f1, acc[mf][nf][2], x[b0i + 8]);
            out[b1i + 8] = fmaf(f1, acc[mf][nf][3], x[b1i + 8]);
        }
    }
}

// ---------------------------------------------------------------------------
extern "C" void kernel_launch(void* const* d_in, const int* in_sizes, int n_in,
                              void* d_out, int out_size)
{
    (void)in_sizes; (void)n_in; (void)out_size;
    const float* x     = (const float*)d_in[0];
    const float* mask  = (const float*)d_in[1];
    const float* skin  = (const float*)d_in[2];
    const float* Wq    = (const float*)d_in[3];
    const float* bq    = (const float*)d_in[4];
    const float* Wk    = (const float*)d_in[5];
    const float* bk    = (const float*)d_in[6];
    const float* Wv    = (const float*)d_in[7];
    const float* bv    = (const float*)d_in[8];
    const float* gamma = (const float*)d_in[9];
    float* out = (float*)d_out;

    cudaFuncSetAttribute(projmma_kernel, cudaFuncAttributeMaxDynamicSharedMemorySize, DYN_SMEM);
    cudaFuncSetAttribute(qk_kernel, cudaFuncAttributeMaxDynamicSharedMemorySize, DYN_SMEM);
    cudaFuncSetAttribute(av_kernel, cudaFuncAttributeMaxDynamicSharedMemorySize, DYN_SMEM);

    dim3 gX(64, 4, Bb);
    xcvt_kernel<<<gX, 256>>>(x);

    wcvt_kernel<<<128, 256>>>(Wq, Wk, Wv);

    dim3 gP(4, 32, Bb);
    projmma_kernel<<<gP, 256, DYN_SMEM>>>(mask, skin, bq, bk, bv);

    dim3 gV(64, 4, Bb);
    vtrans_kernel<<<gV, 256>>>();

    dim3 gQK(32, 32, Bb);
    qk_kernel<<<gQK, 256, DYN_SMEM>>>();

    zinv_kernel<<<(Bb * Nn) / 256, 256>>>();

    dim3 gAV(2, 32, Bb);
    av_kernel<<<gAV, 256, DYN_SMEM>>>(x, mask, skin, gamma, out);
}

// round 11
// speedup vs baseline: 1.7139x; 1.2113x over previous
#include <cuda_runtime.h>
#include <cuda_fp16.h>
#include <cuda_bf16.h>
#include <cstdint>

// Problem constants
#define Bb 4
#define Cc 256
#define C2v 128
#define Nn 4096

// ---------------------------------------------------------------------------
// Scratch (__device__ globals; allocation-free rule)
// ---------------------------------------------------------------------------
__device__ __half         g_xh[(size_t)Bb * Nn * 256];   // [B][n][c] fp16 hi of x
__device__ __half         g_xl[(size_t)Bb * Nn * 256];   // [B][n][c] fp16 lo of x
__device__ __half         g_wh[(size_t)512 * 256];       // [o][c]: q 0-127, k 128-255, v 256-511
__device__ __half         g_wl[(size_t)512 * 256];
__device__ __half         g_qc[(size_t)Bb * Nn * 128];   // [B][n][128] fp16 q
__device__ __half         g_kc[(size_t)Bb * Nn * 128];   // [B][n][128] fp16 masked k
__device__ __nv_bfloat16  g_vt[(size_t)Bb * Nn * Cc];    // [B][n][c] bf16 (pre-transpose)
__device__ __nv_bfloat16  g_vb[(size_t)Bb * Cc * Nn];    // [B][c][n]  (K-major for AV)
__device__ __nv_bfloat16  g_attb[(size_t)Bb * Nn * Nn];  // P = exp(S), bf16
__device__ float          g_sumexp[(size_t)Bb * Nn * 32];// per-row per-chunk sum of exp

// ---------------------------------------------------------------------------
// Helpers
// ---------------------------------------------------------------------------
__device__ __forceinline__ uint32_t smem_u32(const void* p) {
    uint32_t a;
    asm("{ .reg .u64 t; cvta.to.shared.u64 t, %1; cvt.u32.u64 %0, t; }" : "=r"(a) : "l"(p));
    return a;
}
__device__ __forceinline__ void cp_async16(uint32_t dst, const void* src) {
    asm volatile("cp.async.cg.shared.global [%0], [%1], 16;" :: "r"(dst), "l"(src));
}
#define CP_COMMIT() asm volatile("cp.async.commit_group;" ::: "memory")
template <int N>
__device__ __forceinline__ void cp_wait() {
    asm volatile("cp.async.wait_group %0;" :: "n"(N) : "memory");
}
__device__ __forceinline__ void ldmx4(uint32_t* r, uint32_t addr) {
    asm volatile("ldmatrix.sync.aligned.m8n8.x4.shared.b16 {%0,%1,%2,%3}, [%4];"
        : "=r"(r[0]), "=r"(r[1]), "=r"(r[2]), "=r"(r[3]) : "r"(addr));
}
__device__ __forceinline__ void mma16816(float* d, const uint32_t* a, uint32_t b0, uint32_t b1) {
    asm volatile(
        "mma.sync.aligned.m16n8k16.row.col.f32.f16.f16.f32 "
        "{%0,%1,%2,%3},{%4,%5,%6,%7},{%8,%9},{%0,%1,%2,%3};"
        : "+f"(d[0]), "+f"(d[1]), "+f"(d[2]), "+f"(d[3])
        : "r"(a[0]), "r"(a[1]), "r"(a[2]), "r"(a[3]), "r"(b0), "r"(b1));
}
__device__ __forceinline__ void mma16816bf(float* d, const uint32_t* a, uint32_t b0, uint32_t b1) {
    asm volatile(
        "mma.sync.aligned.m16n8k16.row.col.f32.bf16.bf16.f32 "
        "{%0,%1,%2,%3},{%4,%5,%6,%7},{%8,%9},{%0,%1,%2,%3};"
        : "+f"(d[0]), "+f"(d[1]), "+f"(d[2]), "+f"(d[3])
        : "r"(a[0]), "r"(a[1]), "r"(a[2]), "r"(a[3]), "r"(b0), "r"(b1));
}

// Fast exp (FFMA-only)
__device__ __forceinline__ float fexp(float x) {
    float t = fmaxf(x * 1.4426950408889634f, -126.0f);
    float fi = floorf(t);
    float f = t - fi;
    float p = 0.0013333558f;
    p = fmaf(p, f, 0.0096181291f);
    p = fmaf(p, f, 0.0555041087f);
    p = fmaf(p, f, 0.2402265069f);
    p = fmaf(p, f, 0.6931471806f);
    p = fmaf(p, f, 1.0f);
    return p * __int_as_float(((int)fi + 127) << 23);
}

// ---------------------------------------------------------------------------
// GEMM tile geometry: 128x128 block, BK=32, 8 warps (2x4)
// smem tile: 128 rows x 32 halfwords, row stride 80B; 3-stage ring.
// ---------------------------------------------------------------------------
#define ROWB 80                 // bytes per smem tile row
#define TILE_B (128 * ROWB)     // 10240 per operand tile
#define STAGE_PAIR (2 * TILE_B) // 20480 per stage (A+B)
#define NSTAGE 3
#define DYN_SMEM (NSTAGE * STAGE_PAIR)        // 61440

// Load one 128x32 16-bit tile (row-major src, stride elems) into smem tile.
__device__ __forceinline__ void load_tile(uint32_t dst, const __half* src,
                                          size_t stride, int tid)
{
    #pragma unroll
    for (int i = 0; i < 2; i++) {
        int idx = tid + i * 256;          // 0..511
        int row = idx >> 2, c16 = idx & 3;
        cp_async16(dst + row * ROWB + c16 * 16, src + (size_t)row * stride + c16 * 8);
    }
}

// One BK=32 compute step (fp16 operands)
__device__ __forceinline__ void warp_mma_step(float acc[4][4][4], uint32_t abase,
                                              uint32_t bbase, int wy, int wx, int lane)
{
    #pragma unroll
    for (int ks = 0; ks < 2; ks++) {
        uint32_t a[4][4];
        #pragma unroll
        for (int mf = 0; mf < 4; mf++) {
            int row = wy * 64 + mf * 16 + (lane & 15);
            ldmx4(a[mf], abase + row * ROWB + ks * 32 + ((lane >> 4) << 4));
        }
        uint32_t bf[2][4];
        #pragma unroll
        for (int np = 0; np < 2; np++) {
            int row = wx * 32 + np * 16 + (lane & 7) + ((lane >> 4) << 3);
            ldmx4(bf[np], bbase + row * ROWB + ks * 32 + (((lane >> 3) & 1) << 4));
        }
        #pragma unroll
        for (int mf = 0; mf < 4; mf++)
            #pragma unroll
            for (int nf = 0; nf < 4; nf++)
                mma16816(acc[mf][nf], a[mf],
                         bf[nf >> 1][(nf & 1) * 2], bf[nf >> 1][(nf & 1) * 2 + 1]);
    }
}

// Same, bf16 operands
__device__ __forceinline__ void warp_mma_step_bf(float acc[4][4][4], uint32_t abase,
                                                 uint32_t bbase, int wy, int wx, int lane)
{
    #pragma unroll
    for (int ks = 0; ks < 2; ks++) {
        uint32_t a[4][4];
        #pragma unroll
        for (int mf = 0; mf < 4; mf++) {
            int row = wy * 64 + mf * 16 + (lane & 15);
            ldmx4(a[mf], abase + row * ROWB + ks * 32 + ((lane >> 4) << 4));
        }
        uint32_t bf[2][4];
        #pragma unroll
        for (int np = 0; np < 2; np++) {
            int row = wx * 32 + np * 16 + (lane & 7) + ((lane >> 4) << 3);
            ldmx4(bf[np], bbase + row * ROWB + ks * 32 + (((lane >> 3) & 1) << 4));
        }
        #pragma unroll
        for (int mf = 0; mf < 4; mf++)
            #pragma unroll
            for (int nf = 0; nf < 4; nf++)
                mma16816bf(acc[mf][nf], a[mf],
                           bf[nf >> 1][(nf & 1) * 2], bf[nf >> 1][(nf & 1) * 2 + 1]);
    }
}

// ---------------------------------------------------------------------------
// Kernel 0a: xcvt — transpose-convert x [B][c][n] fp32 -> g_xh/g_xl [B][n][c] fp16
// ---------------------------------------------------------------------------
__global__ __launch_bounds__(256) void xcvt_kernel(const float* __restrict__ x)
{
    __shared__ float ts[64][65];
    const int b = blockIdx.z, n0 = blockIdx.x * 64, c0 = blockIdx.y * 64;
    const int tid = threadIdx.x;

    #pragma unroll
    for (int i = 0; i < 4; i++) {
        int idx = tid + i * 256;          // 0..1023
        int r = idx >> 4, f4 = idx & 15;  // row c-local, 16B col group
        float4 v = *reinterpret_cast<const float4*>(
            x + ((size_t)b * Cc + c0 + r) * Nn + n0 + f4 * 4);
        ts[r][f4 * 4 + 0] = v.x;
        ts[r][f4 * 4 + 1] = v.y;
        ts[r][f4 * 4 + 2] = v.z;
        ts[r][f4 * 4 + 3] = v.w;
    }
    __syncthreads();

    const int nr = tid >> 2;
    #pragma unroll
    for (int i = 0; i < 2; i++) {
        int c8 = ((tid & 3) * 2 + i) * 8;
        __half h8[8], l8[8];
        #pragma unroll
        for (int j = 0; j < 8; j++) {
            float v = ts[c8 + j][nr];
            __half h = __float2half(v);
            h8[j] = h;
            l8[j] = __float2half(v - __half2float(h));
        }
        size_t off = ((size_t)b * Nn + n0 + nr) * 256 + c0 + c8;
        *reinterpret_cast<float4*>(g_xh + off) = *reinterpret_cast<float4*>(h8);
        *reinterpret_cast<float4*>(g_xl + off) = *reinterpret_cast<float4*>(l8);
    }
}

// ---------------------------------------------------------------------------
// Kernel 0b: wcvt — Wq|Wk|Wv fp32 -> g_wh/g_wl fp16 [512][256]
// ---------------------------------------------------------------------------
__global__ __launch_bounds__(256) void wcvt_kernel(
    const float* __restrict__ Wq, const float* __restrict__ Wk,
    const float* __restrict__ Wv)
{
    int e4 = blockIdx.x * 256 + threadIdx.x;   // 0..32767
    int row = e4 >> 6, col4 = (e4 & 63) * 4;
    const float* src = (row < 128) ? (Wq + (size_t)row * 256)
                     : (row < 256) ? (Wk + (size_t)(row - 128) * 256)
                                   : (Wv + (size_t)(row - 256) * 256);
    float4 v = *reinterpret_cast<const float4*>(src + col4);
    __half h4[4], l4[4];
    float vv[4] = {v.x, v.y, v.z, v.w};
    #pragma unroll
    for (int j = 0; j < 4; j++) {
        __half h = __float2half(vv[j]);
        h4[j] = h;
        l4[j] = __float2half(vv[j] - __half2float(h));
    }
    size_t off = (size_t)row * 256 + col4;
    *reinterpret_cast<float2*>(g_wh + off) = *reinterpret_cast<float2*>(h4);
    *reinterpret_cast<float2*>(g_wl + off) = *reinterpret_cast<float2*>(l4);
}

// ---------------------------------------------------------------------------
// Kernel 1: projections via mma.sync fp16.
//   oblk 0 (q), 1 (k): K=768 3-term split (fp32-class), output single fp16
//   oblk 2, 3 (v):     K=256 single term, output bf16 [n][c]
// grid (4 oblk, 32 mtile, B), 256 threads, dynamic smem 61440.
// ---------------------------------------------------------------------------
__global__ __launch_bounds__(256, 2) void projmma_kernel(
    const float* __restrict__ mask, const float* __restrict__ skin,
    const float* __restrict__ bq, const float* __restrict__ bk,
    const float* __restrict__ bv)
{
    extern __shared__ __align__(128) char dynsm[];
    __shared__ float fm[128];
    const int b = blockIdx.z, m0 = blockIdx.y * 128, oblk = blockIdx.x;
    const int tid = threadIdx.x, wid = tid >> 5, lane = tid & 31;
    const int wy = wid >> 2, wx = wid & 3;
    const uint32_t sb = smem_u32(dynsm);

    const int NK = (oblk < 2) ? 24 : 8;
    const size_t orow = (size_t)oblk * 128;
    const size_t abase_off = ((size_t)b * Nn + m0) * 256;

    if (oblk == 1 && tid < 128)
        fm[tid] = (1.0f - mask[b * Nn + m0 + tid]) * skin[b * Nn + m0 + tid];

    #pragma unroll
    for (int s = 0; s < 2; s++) {
        uint32_t st = sb + s * STAGE_PAIR;
        const __half* as = g_xh + abase_off + (s & 7) * 32;       // seg 0
        const __half* bs = g_wh + orow * 256 + (s & 7) * 32;
        load_tile(st, as, 256, tid);
        load_tile(st + TILE_B, bs, 256, tid);
        CP_COMMIT();
    }

    float acc[4][4][4] = {};
    #pragma unroll 1
    for (int s = 0; s < NK; s++) {
        if (s < NK - 1) cp_wait<1>(); else cp_wait<0>();
        __syncthreads();
        if (s + 2 < NK) {
            int sp = s + 2;
            int seg = sp >> 3, col = (sp & 7) * 32;
            const __half* as = ((seg == 1) ? g_xl : g_xh) + abase_off + col;
            const __half* bs = ((seg == 2) ? g_wl : g_wh) + orow * 256 + col;
            uint32_t ld = sb + (uint32_t)(sp % NSTAGE) * STAGE_PAIR;
            load_tile(ld, as, 256, tid);
            load_tile(ld + TILE_B, bs, 256, tid);
            CP_COMMIT();
        }
        const uint32_t st = sb + (uint32_t)(s % NSTAGE) * STAGE_PAIR;
        warp_mma_step(acc, st, st + TILE_B, wy, wx, lane);
    }

    // Epilogue
    const float* biasp = (oblk == 0) ? bq : (oblk == 1) ? bk
                       : (oblk == 2) ? bv : (bv + 128);
    float bias0[4], bias1[4];
    #pragma unroll
    for (int nf = 0; nf < 4; nf++) {
        int o = wx * 32 + nf * 8 + (lane & 3) * 2;
        bias0[nf] = biasp[o];
        bias1[nf] = biasp[o + 1];
    }

    #pragma unroll
    for (int mf = 0; mf < 4; mf++) {
        const int rA = wy * 64 + mf * 16 + (lane >> 2);
        const int rB = rA + 8;
        float fA = 1.0f, fB = 1.0f;
        if (oblk == 1) { fA = fm[rA]; fB = fm[rB]; }
        #pragma unroll
        for (int nf = 0; nf < 4; nf++) {
            const int o = wx * 32 + nf * 8 + (lane & 3) * 2;
            float r0 = acc[mf][nf][0] + bias0[nf];
            float r1 = acc[mf][nf][1] + bias1[nf];
            float r2 = acc[mf][nf][2] + bias0[nf];
            float r3 = acc[mf][nf][3] + bias1[nf];
            if (oblk <= 1) {
                if (oblk == 1) { r0 *= fA; r1 *= fA; r2 *= fB; r3 *= fB; }
                __half2 hiA = __floats2half2_rn(r0, r1);
                __half2 hiB = __floats2half2_rn(r2, r3);
                __half* dst = (oblk == 0) ? g_qc : g_kc;
                size_t oa = ((size_t)b * Nn + m0 + rA) * 128 + o;
                size_t ob = ((size_t)b * Nn + m0 + rB) * 128 + o;
                *reinterpret_cast<__half2*>(dst + oa) = hiA;
                *reinterpret_cast<__half2*>(dst + ob) = hiB;
            } else {
                const int c = (oblk - 2) * 128 + o;
                size_t oa = ((size_t)b * Nn + m0 + rA) * 256 + c;
                size_t ob = ((size_t)b * Nn + m0 + rB) * 256 + c;
                *reinterpret_cast<__nv_bfloat162*>(g_vt + oa) = __floats2bfloat162_rn(r0, r1);
                *reinterpret_cast<__nv_bfloat162*>(g_vt + ob) = __floats2bfloat162_rn(r2, r3);
            }
        }
    }
}

// ---------------------------------------------------------------------------
// Kernel 1b: vtrans — g_vt [B][n][c] bf16 -> g_vb [B][c][n]
// ---------------------------------------------------------------------------
__global__ __launch_bounds__(256) void vtrans_kernel()
{
    __shared__ __nv_bfloat16 ts[64][72];
    const int b = blockIdx.z, n0 = blockIdx.x * 64, c0 = blockIdx.y * 64;
    const int tid = threadIdx.x;

    #pragma unroll
    for (int i = 0; i < 2; i++) {
        int idx = tid + i * 256;          // 0..511
        int r = idx >> 3, c8 = (idx & 7) * 8;
        float4 v = *reinterpret_cast<const float4*>(
            g_vt + ((size_t)b * Nn + n0 + r) * 256 + c0 + c8);
        *reinterpret_cast<float4*>(&ts[r][c8]) = v;
    }
    __syncthreads();

    const int cr = tid >> 2;
    #pragma unroll
    for (int i = 0; i < 2; i++) {
        int n8 = ((tid & 3) * 2 + i) * 8;
        __nv_bfloat16 o8[8];
        #pragma unroll
        for (int j = 0; j < 8; j++) o8[j] = ts[n8 + j][cr];
        *reinterpret_cast<float4*>(
            g_vb + ((size_t)b * Cc + c0 + cr) * Nn + n0 + n8) =
            *reinterpret_cast<float4*>(o8);
    }
}

// ---------------------------------------------------------------------------
// Kernel 2: QK^T -> P = exp(S), single fp16 term, K=128 (NK=4)
// grid (32 nchunk, 32 mtile, B), 256 threads, dynamic smem 61440
// ---------------------------------------------------------------------------
__global__ __launch_bounds__(256, 2) void qk_kernel()
{
    extern __shared__ __align__(128) char dynsm[];
    const int b = blockIdx.z, m0 = blockIdx.y * 128, n0 = blockIdx.x * 128;
    const int chunk = blockIdx.x;
    const int tid = threadIdx.x, wid = tid >> 5, lane = tid & 31;
    const int wy = wid >> 2, wx = wid & 3;
    const uint32_t sb = smem_u32(dynsm);

    const __half* Asrc = g_qc + ((size_t)b * Nn + m0) * 128;
    const __half* Bsrc = g_kc + ((size_t)b * Nn + n0) * 128;

    const int NK = 128 / 32;   // 4
    #pragma unroll
    for (int s = 0; s < 2; s++) {
        uint32_t st = sb + s * STAGE_PAIR;
        load_tile(st, Asrc + s * 32, 128, tid);
        load_tile(st + TILE_B, Bsrc + s * 32, 128, tid);
        CP_COMMIT();
    }

    float acc[4][4][4] = {};
    #pragma unroll 1
    for (int s = 0; s < NK; s++) {
        if (s < NK - 1) cp_wait<1>(); else cp_wait<0>();
        __syncthreads();
        if (s + 2 < NK) {
            uint32_t ld = sb + (uint32_t)((s + 2) % NSTAGE) * STAGE_PAIR;
            load_tile(ld, Asrc + (s + 2) * 32, 128, tid);
            load_tile(ld + TILE_B, Bsrc + (s + 2) * 32, 128, tid);
            CP_COMMIT();
        }
        const uint32_t st = sb + (uint32_t)(s % NSTAGE) * STAGE_PAIR;
        warp_mma_step(acc, st, st + TILE_B, wy, wx, lane);
    }

    // ---- one-pass epilogue: exp, stage P (bf16), row sums ----
    __syncthreads();
    float* sred = reinterpret_cast<float*>(dynsm);                  // [4][128]
    __nv_bfloat16* pst = reinterpret_cast<__nv_bfloat16*>(dynsm + 4096); // [128][128]

    float rsum[4][2];
    #pragma unroll
    for (int mf = 0; mf < 4; mf++) {
        int rA = wy * 64 + mf * 16 + (lane >> 2);
        int rB = rA + 8;
        float sA = 0.0f, sB = 0.0f;
        #pragma unroll
        for (int nf = 0; nf < 4; nf++) {
            float p0 = fexp(acc[mf][nf][0]);
            float p1 = fexp(acc[mf][nf][1]);
            float p2 = fexp(acc[mf][nf][2]);
            float p3 = fexp(acc[mf][nf][3]);
            sA += p0 + p1; sB += p2 + p3;
            int cl = wx * 32 + nf * 8 + (lane & 3) * 2;
            *reinterpret_cast<__nv_bfloat162*>(pst + rA * 128 + cl) = __floats2bfloat162_rn(p0, p1);
            *reinterpret_cast<__nv_bfloat162*>(pst + rB * 128 + cl) = __floats2bfloat162_rn(p2, p3);
        }
        rsum[mf][0] = sA; rsum[mf][1] = sB;
    }
    #pragma unroll
    for (int o = 1; o <= 2; o <<= 1)
        #pragma unroll
        for (int mf = 0; mf < 4; mf++) {
            rsum[mf][0] += __shfl_xor_sync(0xffffffffu, rsum[mf][0], o);
            rsum[mf][1] += __shfl_xor_sync(0xffffffffu, rsum[mf][1], o);
        }
    if ((lane & 3) == 0) {
        #pragma unroll
        for (int mf = 0; mf < 4; mf++) {
            int rA = wy * 64 + mf * 16 + (lane >> 2);
            sred[wx * 128 + rA]     = rsum[mf][0];
            sred[wx * 128 + rA + 8] = rsum[mf][1];
        }
    }
    __syncthreads();
    if (tid < 128) {
        float se = sred[tid] + sred[128 + tid] + sred[256 + tid] + sred[384 + tid];
        g_sumexp[((size_t)b * Nn + m0 + tid) * 32 + chunk] = se;
    }

    // coalesced P write-out
    #pragma unroll
    for (int i = 0; i < 8; i++) {
        int f4 = tid + i * 256;           // 0..2047 float4s
        int row = f4 >> 4, c8 = (f4 & 15) * 8;
        float4 v = *reinterpret_cast<float4*>(pst + row * 128 + c8);
        *reinterpret_cast<float4*>(g_attb + ((size_t)b * Nn + m0 + row) * Nn + n0 + c8) = v;
    }
}

// ---------------------------------------------------------------------------
// Kernel 4: AV via mma.sync bf16 (clean loop) + epilogue normalization
//   out[c][m] = gamma*fm[m]*zinv[m]*D[m][c] + x[c][m]; zinv computed inline
// grid (2 ctile, 32 mtile, B), 256 threads, dynamic smem 61440
// ---------------------------------------------------------------------------
__global__ __launch_bounds__(256, 2) void av_kernel(
    const float* __restrict__ x, const float* __restrict__ mask,
    const float* __restrict__ skin, const float* __restrict__ gamma,
    float* __restrict__ out)
{
    extern __shared__ __align__(128) char dynsm[];
    __shared__ float fmv[128];
    __shared__ float szv[128];
    const int b = blockIdx.z, m0 = blockIdx.y * 128, c0 = blockIdx.x * 128;
    const int tid = threadIdx.x, wid = tid >> 5, lane = tid & 31;
    const int wy = wid >> 2, wx = wid & 3;
    const uint32_t sb = smem_u32(dynsm);

    if (tid < 128) {
        fmv[tid] = mask[(size_t)b * Nn + m0 + tid] * skin[(size_t)b * Nn + m0 + tid];
        const float4* sp = reinterpret_cast<const float4*>(
            g_sumexp + ((size_t)b * Nn + m0 + tid) * 32);
        float s = 0.0f;
        #pragma unroll
        for (int i = 0; i < 8; i++) {
            float4 v = sp[i];
            s += (v.x + v.y) + (v.z + v.w);
        }
        szv[tid] = 1.0f / s;
    }

    const __half* Asrc = reinterpret_cast<const __half*>(g_attb + ((size_t)b * Nn + m0) * Nn);
    const __half* Bsrc = reinterpret_cast<const __half*>(g_vb + ((size_t)b * Cc + c0) * Nn);

    const int NK = Nn / 32;   // 128
    #pragma unroll
    for (int s = 0; s < 2; s++) {
        uint32_t st = sb + s * STAGE_PAIR;
        load_tile(st, Asrc + s * 32, Nn, tid);
        load_tile(st + TILE_B, Bsrc + s * 32, Nn, tid);
        CP_COMMIT();
    }

    float acc[4][4][4] = {};
    #pragma unroll 1
    for (int s = 0; s < NK; s++) {
        if (s < NK - 1) cp_wait<1>(); else cp_wait<0>();
        __syncthreads();
        if (s + 2 < NK) {
            uint32_t ld = sb + (uint32_t)((s + 2) % NSTAGE) * STAGE_PAIR;
            load_tile(ld, Asrc + (s + 2) * 32, Nn, tid);
            load_tile(ld + TILE_B, Bsrc + (s + 2) * 32, Nn, tid);
            CP_COMMIT();
        }
        const uint32_t st = sb + (uint32_t)(s % NSTAGE) * STAGE_PAIR;
        warp_mma_step_bf(acc, st, st + TILE_B, wy, wx, lane);
    }

    // Fused epilogue: out[c][m] = gamma*fm[m]*zinv[m]*D[m][c] + x[c][m]
    const float gm = __ldg(gamma);
    #pragma unroll
    for (int mf = 0; mf < 4; mf++) {
        const int ml = wy * 64 + mf * 16 + (lane >> 2);    // local m (0..127)
        const float f0 = gm * fmv[ml] * szv[ml];
        const float f1 = gm * fmv[ml + 8] * szv[ml + 8];
        #pragma unroll
        for (int nf = 0; nf < 4; nf++) {
            const int c = c0 + wx * 32 + nf * 8 + (lane & 3) * 2;
            const size_t b0i = ((size_t)b * Cc + c) * Nn + m0 + ml;
            const size_t b1i = b0i + Nn;   // c+1
            out[b0i]     = fmaf(f0, acc[mf][nf][0], x[b0i]);
            out[b1i]     = fmaf(f0, acc[mf][nf][1], x[b1i]);
            out[b0i + 8] = fmaf(f1, acc[mf][nf][2], x[b0i + 8]);
            out[b1i + 8] = fmaf(f1, acc[mf][nf][3], x[b1i + 8]);
        }
    }
}

// ---------------------------------------------------------------------------
extern "C" void kernel_launch(void* const* d_in, const int* in_sizes, int n_in,
                              void* d_out, int out_size)
{
    (void)in_sizes; (void)n_in; (void)out_size;
    const float* x     = (const float*)d_in[0];
    const float* mask  = (const float*)d_in[1];
    const float* skin  = (const float*)d_in[2];
    const float* Wq    = (const float*)d_in[3];
    const float* bq    = (const float*)d_in[4];
    const float* Wk    = (const float*)d_in[5];
    const float* bk    = (const float*)d_in[6];
    const float* Wv    = (const float*)d_in[7];
    const float* bv    = (const float*)d_in[8];
    const float* gamma = (const float*)d_in[9];
    float* out = (float*)d_out;

    cudaFuncSetAttribute(projmma_kernel, cudaFuncAttributeMaxDynamicSharedMemorySize, DYN_SMEM);
    cudaFuncSetAttribute(qk_kernel, cudaFuncAttributeMaxDynamicSharedMemorySize, DYN_SMEM);
    cudaFuncSetAttribute(av_kernel, cudaFuncAttributeMaxDynamicSharedMemorySize, DYN_SMEM);

    dim3 gX(64, 4, Bb);
    xcvt_kernel<<<gX, 256>>>(x);

    wcvt_kernel<<<128, 256>>>(Wq, Wk, Wv);

    dim3 gP(4, 32, Bb);
    projmma_kernel<<<gP, 256, DYN_SMEM>>>(mask, skin, bq, bk, bv);

    dim3 gV(64, 4, Bb);
    vtrans_kernel<<<gV, 256>>>();

    dim3 gQK(32, 32, Bb);
    qk_kernel<<<gQK, 256, DYN_SMEM>>>();

    dim3 gAV(2, 32, Bb);
    av_kernel<<<gAV, 256, DYN_SMEM>>>(x, mask, skin, gamma, out);
}

// round 12
// speedup vs baseline: 1.8865x; 1.1007x over previous
#include <cuda_runtime.h>
#include <cuda_fp16.h>
#include <cuda_bf16.h>
#include <cstdint>

// Problem constants
#define Bb 4
#define Cc 256
#define C2v 128
#define Nn 4096

// ---------------------------------------------------------------------------
// Scratch (__device__ globals; allocation-free rule)
// ---------------------------------------------------------------------------
__device__ __half         g_xh[(size_t)Bb * Nn * 256];   // [B][n][c] fp16 x (transposed)
__device__ __half         g_wh[(size_t)512 * 256];       // [o][c]: q 0-127, k 128-255, v 256-511
__device__ __half         g_qc[(size_t)Bb * Nn * 128];   // [B][n][128] fp16 q
__device__ __half         g_kc[(size_t)Bb * Nn * 128];   // [B][n][128] fp16 masked k
__device__ __nv_bfloat16  g_vb[(size_t)Bb * Cc * Nn];    // [B][c][n]  (K-major for AV)
__device__ __nv_bfloat16  g_attb[(size_t)Bb * Nn * Nn];  // P = exp(S), bf16
__device__ float          g_sumexp[(size_t)Bb * Nn * 32];// per-row per-chunk sum of exp

// ---------------------------------------------------------------------------
// Helpers
// ---------------------------------------------------------------------------
__device__ __forceinline__ uint32_t smem_u32(const void* p) {
    uint32_t a;
    asm("{ .reg .u64 t; cvta.to.shared.u64 t, %1; cvt.u32.u64 %0, t; }" : "=r"(a) : "l"(p));
    return a;
}
__device__ __forceinline__ void cp_async16(uint32_t dst, const void* src) {
    asm volatile("cp.async.cg.shared.global [%0], [%1], 16;" :: "r"(dst), "l"(src));
}
#define CP_COMMIT() asm volatile("cp.async.commit_group;" ::: "memory")
template <int N>
__device__ __forceinline__ void cp_wait() {
    asm volatile("cp.async.wait_group %0;" :: "n"(N) : "memory");
}
__device__ __forceinline__ void ldmx4(uint32_t* r, uint32_t addr) {
    asm volatile("ldmatrix.sync.aligned.m8n8.x4.shared.b16 {%0,%1,%2,%3}, [%4];"
        : "=r"(r[0]), "=r"(r[1]), "=r"(r[2]), "=r"(r[3]) : "r"(addr));
}
__device__ __forceinline__ void mma16816(float* d, const uint32_t* a, uint32_t b0, uint32_t b1) {
    asm volatile(
        "mma.sync.aligned.m16n8k16.row.col.f32.f16.f16.f32 "
        "{%0,%1,%2,%3},{%4,%5,%6,%7},{%8,%9},{%0,%1,%2,%3};"
        : "+f"(d[0]), "+f"(d[1]), "+f"(d[2]), "+f"(d[3])
        : "r"(a[0]), "r"(a[1]), "r"(a[2]), "r"(a[3]), "r"(b0), "r"(b1));
}
__device__ __forceinline__ void mma16816bf(float* d, const uint32_t* a, uint32_t b0, uint32_t b1) {
    asm volatile(
        "mma.sync.aligned.m16n8k16.row.col.f32.bf16.bf16.f32 "
        "{%0,%1,%2,%3},{%4,%5,%6,%7},{%8,%9},{%0,%1,%2,%3};"
        : "+f"(d[0]), "+f"(d[1]), "+f"(d[2]), "+f"(d[3])
        : "r"(a[0]), "r"(a[1]), "r"(a[2]), "r"(a[3]), "r"(b0), "r"(b1));
}

// Fast exp (FFMA-only)
__device__ __forceinline__ float fexp(float x) {
    float t = fmaxf(x * 1.4426950408889634f, -126.0f);
    float fi = floorf(t);
    float f = t - fi;
    float p = 0.0013333558f;
    p = fmaf(p, f, 0.0096181291f);
    p = fmaf(p, f, 0.0555041087f);
    p = fmaf(p, f, 0.2402265069f);
    p = fmaf(p, f, 0.6931471806f);
    p = fmaf(p, f, 1.0f);
    return p * __int_as_float(((int)fi + 127) << 23);
}

// ---------------------------------------------------------------------------
// GEMM tile geometry: 128x128 block, BK=32, 8 warps (2x4)
// smem tile: 128 rows x 32 halfwords, row stride 80B; 3-stage ring.
// ---------------------------------------------------------------------------
#define ROWB 80                 // bytes per smem tile row
#define TILE_B (128 * ROWB)     // 10240 per operand tile
#define STAGE_PAIR (2 * TILE_B) // 20480 per stage (A+B)
#define NSTAGE 3
#define DYN_SMEM (NSTAGE * STAGE_PAIR)        // 61440

// Load one 128x32 16-bit tile (row-major src, stride elems) into smem tile.
__device__ __forceinline__ void load_tile(uint32_t dst, const __half* src,
                                          size_t stride, int tid)
{
    #pragma unroll
    for (int i = 0; i < 2; i++) {
        int idx = tid + i * 256;          // 0..511
        int row = idx >> 2, c16 = idx & 3;
        cp_async16(dst + row * ROWB + c16 * 16, src + (size_t)row * stride + c16 * 8);
    }
}

// One BK=32 compute step (fp16 operands)
__device__ __forceinline__ void warp_mma_step(float acc[4][4][4], uint32_t abase,
                                              uint32_t bbase, int wy, int wx, int lane)
{
    #pragma unroll
    for (int ks = 0; ks < 2; ks++) {
        uint32_t a[4][4];
        #pragma unroll
        for (int mf = 0; mf < 4; mf++) {
            int row = wy * 64 + mf * 16 + (lane & 15);
            ldmx4(a[mf], abase + row * ROWB + ks * 32 + ((lane >> 4) << 4));
        }
        uint32_t bf[2][4];
        #pragma unroll
        for (int np = 0; np < 2; np++) {
            int row = wx * 32 + np * 16 + (lane & 7) + ((lane >> 4) << 3);
            ldmx4(bf[np], bbase + row * ROWB + ks * 32 + (((lane >> 3) & 1) << 4));
        }
        #pragma unroll
        for (int mf = 0; mf < 4; mf++)
            #pragma unroll
            for (int nf = 0; nf < 4; nf++)
                mma16816(acc[mf][nf], a[mf],
                         bf[nf >> 1][(nf & 1) * 2], bf[nf >> 1][(nf & 1) * 2 + 1]);
    }
}

// Same, bf16 operands
__device__ __forceinline__ void warp_mma_step_bf(float acc[4][4][4], uint32_t abase,
                                                 uint32_t bbase, int wy, int wx, int lane)
{
    #pragma unroll
    for (int ks = 0; ks < 2; ks++) {
        uint32_t a[4][4];
        #pragma unroll
        for (int mf = 0; mf < 4; mf++) {
            int row = wy * 64 + mf * 16 + (lane & 15);
            ldmx4(a[mf], abase + row * ROWB + ks * 32 + ((lane >> 4) << 4));
        }
        uint32_t bf[2][4];
        #pragma unroll
        for (int np = 0; np < 2; np++) {
            int row = wx * 32 + np * 16 + (lane & 7) + ((lane >> 4) << 3);
            ldmx4(bf[np], bbase + row * ROWB + ks * 32 + (((lane >> 3) & 1) << 4));
        }
        #pragma unroll
        for (int mf = 0; mf < 4; mf++)
            #pragma unroll
            for (int nf = 0; nf < 4; nf++)
                mma16816bf(acc[mf][nf], a[mf],
                           bf[nf >> 1][(nf & 1) * 2], bf[nf >> 1][(nf & 1) * 2 + 1]);
    }
}

// ---------------------------------------------------------------------------
// Kernel 0a: xcvt — transpose-convert x [B][c][n] fp32 -> g_xh [B][n][c] fp16
// ---------------------------------------------------------------------------
__global__ __launch_bounds__(256) void xcvt_kernel(const float* __restrict__ x)
{
    __shared__ float ts[64][65];
    const int b = blockIdx.z, n0 = blockIdx.x * 64, c0 = blockIdx.y * 64;
    const int tid = threadIdx.x;

    #pragma unroll
    for (int i = 0; i < 4; i++) {
        int idx = tid + i * 256;          // 0..1023
        int r = idx >> 4, f4 = idx & 15;  // row c-local, 16B col group
        float4 v = *reinterpret_cast<const float4*>(
            x + ((size_t)b * Cc + c0 + r) * Nn + n0 + f4 * 4);
        ts[r][f4 * 4 + 0] = v.x;
        ts[r][f4 * 4 + 1] = v.y;
        ts[r][f4 * 4 + 2] = v.z;
        ts[r][f4 * 4 + 3] = v.w;
    }
    __syncthreads();

    const int nr = tid >> 2;
    #pragma unroll
    for (int i = 0; i < 2; i++) {
        int c8 = ((tid & 3) * 2 + i) * 8;
        __half h8[8];
        #pragma unroll
        for (int j = 0; j < 8; j++) h8[j] = __float2half(ts[c8 + j][nr]);
        size_t off = ((size_t)b * Nn + n0 + nr) * 256 + c0 + c8;
        *reinterpret_cast<float4*>(g_xh + off) = *reinterpret_cast<float4*>(h8);
    }
}

// ---------------------------------------------------------------------------
// Kernel 0b: wcvt — Wq|Wk|Wv fp32 -> g_wh fp16 [512][256]
// ---------------------------------------------------------------------------
__global__ __launch_bounds__(256) void wcvt_kernel(
    const float* __restrict__ Wq, const float* __restrict__ Wk,
    const float* __restrict__ Wv)
{
    int e4 = blockIdx.x * 256 + threadIdx.x;   // 0..32767
    int row = e4 >> 6, col4 = (e4 & 63) * 4;
    const float* src = (row < 128) ? (Wq + (size_t)row * 256)
                     : (row < 256) ? (Wk + (size_t)(row - 128) * 256)
                                   : (Wv + (size_t)(row - 256) * 256);
    float4 v = *reinterpret_cast<const float4*>(src + col4);
    __half h4[4];
    h4[0] = __float2half(v.x); h4[1] = __float2half(v.y);
    h4[2] = __float2half(v.z); h4[3] = __float2half(v.w);
    *reinterpret_cast<float2*>(g_wh + (size_t)row * 256 + col4) =
        *reinterpret_cast<float2*>(h4);
}

// ---------------------------------------------------------------------------
// Kernel 1: projections via mma.sync fp16, single-term K=256 (NK=8).
//   oblk 0: q -> g_qc fp16 [n][128]
//   oblk 1: masked k -> g_kc fp16 [n][128]
//   oblk 2,3: v -> g_vb bf16 [c][n] via smem-bounce transpose (vtrans folded in)
// grid (4 oblk, 32 mtile, B), 256 threads, dynamic smem 61440.
// ---------------------------------------------------------------------------
#define VPAD 136   // smem v-transpose row stride (halves)

__global__ __launch_bounds__(256, 2) void projmma_kernel(
    const float* __restrict__ mask, const float* __restrict__ skin,
    const float* __restrict__ bq, const float* __restrict__ bk,
    const float* __restrict__ bv)
{
    extern __shared__ __align__(128) char dynsm[];
    __shared__ float fm[128];
    const int b = blockIdx.z, m0 = blockIdx.y * 128, oblk = blockIdx.x;
    const int tid = threadIdx.x, wid = tid >> 5, lane = tid & 31;
    const int wy = wid >> 2, wx = wid & 3;
    const uint32_t sb = smem_u32(dynsm);

    const int NK = 8;
    const __half* Asrc = g_xh + ((size_t)b * Nn + m0) * 256;
    const __half* Bsrc = g_wh + (size_t)oblk * 128 * 256;

    if (oblk == 1 && tid < 128)
        fm[tid] = (1.0f - mask[b * Nn + m0 + tid]) * skin[b * Nn + m0 + tid];

    #pragma unroll
    for (int s = 0; s < 2; s++) {
        uint32_t st = sb + s * STAGE_PAIR;
        load_tile(st, Asrc + s * 32, 256, tid);
        load_tile(st + TILE_B, Bsrc + s * 32, 256, tid);
        CP_COMMIT();
    }

    float acc[4][4][4] = {};
    #pragma unroll 1
    for (int s = 0; s < NK; s++) {
        if (s < NK - 1) cp_wait<1>(); else cp_wait<0>();
        __syncthreads();
        if (s + 2 < NK) {
            uint32_t ld = sb + (uint32_t)((s + 2) % NSTAGE) * STAGE_PAIR;
            load_tile(ld, Asrc + (s + 2) * 32, 256, tid);
            load_tile(ld + TILE_B, Bsrc + (s + 2) * 32, 256, tid);
            CP_COMMIT();
        }
        const uint32_t st = sb + (uint32_t)(s % NSTAGE) * STAGE_PAIR;
        warp_mma_step(acc, st, st + TILE_B, wy, wx, lane);
    }

    // Epilogue
    const float* biasp = (oblk == 0) ? bq : (oblk == 1) ? bk
                       : (oblk == 2) ? bv : (bv + 128);
    float bias0[4], bias1[4];
    #pragma unroll
    for (int nf = 0; nf < 4; nf++) {
        int o = wx * 32 + nf * 8 + (lane & 3) * 2;
        bias0[nf] = biasp[o];
        bias1[nf] = biasp[o + 1];
    }

    if (oblk <= 1) {
        #pragma unroll
        for (int mf = 0; mf < 4; mf++) {
            const int rA = wy * 64 + mf * 16 + (lane >> 2);
            const int rB = rA + 8;
            float fA = 1.0f, fB = 1.0f;
            if (oblk == 1) { fA = fm[rA]; fB = fm[rB]; }
            #pragma unroll
            for (int nf = 0; nf < 4; nf++) {
                const int o = wx * 32 + nf * 8 + (lane & 3) * 2;
                float r0 = (acc[mf][nf][0] + bias0[nf]) * fA;
                float r1 = (acc[mf][nf][1] + bias1[nf]) * fA;
                float r2 = (acc[mf][nf][2] + bias0[nf]) * fB;
                float r3 = (acc[mf][nf][3] + bias1[nf]) * fB;
                __half* dst = (oblk == 0) ? g_qc : g_kc;
                size_t oa = ((size_t)b * Nn + m0 + rA) * 128 + o;
                size_t ob = ((size_t)b * Nn + m0 + rB) * 128 + o;
                *reinterpret_cast<__half2*>(dst + oa) = __floats2half2_rn(r0, r1);
                *reinterpret_cast<__half2*>(dst + ob) = __floats2half2_rn(r2, r3);
            }
        }
    } else {
        // v: bounce through smem [c][n] tile (stride VPAD), then coalesced
        // writes to g_vb[c][m0+n]. vtrans folded in.
        __syncthreads();   // mainloop tiles dead; reuse dynsm
        __nv_bfloat16* vsm = reinterpret_cast<__nv_bfloat16*>(dynsm);
        #pragma unroll
        for (int mf = 0; mf < 4; mf++) {
            const int rA = wy * 64 + mf * 16 + (lane >> 2);   // n-local
            const int rB = rA + 8;
            #pragma unroll
            for (int nf = 0; nf < 4; nf++) {
                const int o = wx * 32 + nf * 8 + (lane & 3) * 2;   // c-local
                vsm[o * VPAD + rA]       = __float2bfloat16(acc[mf][nf][0] + bias0[nf]);
                vsm[(o + 1) * VPAD + rA] = __float2bfloat16(acc[mf][nf][1] + bias1[nf]);
                vsm[o * VPAD + rB]       = __float2bfloat16(acc[mf][nf][2] + bias0[nf]);
                vsm[(o + 1) * VPAD + rB] = __float2bfloat16(acc[mf][nf][3] + bias1[nf]);
            }
        }
        __syncthreads();
        const int c0r = (oblk - 2) * 128;
        #pragma unroll
        for (int i = 0; i < 8; i++) {
            int f4 = tid + i * 256;           // 0..2047
            int row = f4 >> 4, c8 = (f4 & 15) * 8;
            float4 v = *reinterpret_cast<float4*>(vsm + row * VPAD + c8);
            *reinterpret_cast<float4*>(
                g_vb + ((size_t)b * Cc + c0r + row) * Nn + m0 + c8) = v;
        }
    }
}

// ---------------------------------------------------------------------------
// Kernel 2: QK^T -> P = exp(S), single fp16 term, K=128 (NK=4)
// grid (32 nchunk, 32 mtile, B), 256 threads, dynamic smem 61440
// ---------------------------------------------------------------------------
__global__ __launch_bounds__(256, 2) void qk_kernel()
{
    extern __shared__ __align__(128) char dynsm[];
    const int b = blockIdx.z, m0 = blockIdx.y * 128, n0 = blockIdx.x * 128;
    const int chunk = blockIdx.x;
    const int tid = threadIdx.x, wid = tid >> 5, lane = tid & 31;
    const int wy = wid >> 2, wx = wid & 3;
    const uint32_t sb = smem_u32(dynsm);

    const __half* Asrc = g_qc + ((size_t)b * Nn + m0) * 128;
    const __half* Bsrc = g_kc + ((size_t)b * Nn + n0) * 128;

    const int NK = 128 / 32;   // 4
    #pragma unroll
    for (int s = 0; s < 2; s++) {
        uint32_t st = sb + s * STAGE_PAIR;
        load_tile(st, Asrc + s * 32, 128, tid);
        load_tile(st + TILE_B, Bsrc + s * 32, 128, tid);
        CP_COMMIT();
    }

    float acc[4][4][4] = {};
    #pragma unroll 1
    for (int s = 0; s < NK; s++) {
        if (s < NK - 1) cp_wait<1>(); else cp_wait<0>();
        __syncthreads();
        if (s + 2 < NK) {
            uint32_t ld = sb + (uint32_t)((s + 2) % NSTAGE) * STAGE_PAIR;
            load_tile(ld, Asrc + (s + 2) * 32, 128, tid);
            load_tile(ld + TILE_B, Bsrc + (s + 2) * 32, 128, tid);
            CP_COMMIT();
        }
        const uint32_t st = sb + (uint32_t)(s % NSTAGE) * STAGE_PAIR;
        warp_mma_step(acc, st, st + TILE_B, wy, wx, lane);
    }

    // ---- one-pass epilogue: exp, stage P (bf16), row sums ----
    __syncthreads();
    float* sred = reinterpret_cast<float*>(dynsm);                  // [4][128]
    __nv_bfloat16* pst = reinterpret_cast<__nv_bfloat16*>(dynsm + 4096); // [128][128]

    float rsum[4][2];
    #pragma unroll
    for (int mf = 0; mf < 4; mf++) {
        int rA = wy * 64 + mf * 16 + (lane >> 2);
        int rB = rA + 8;
        float sA = 0.0f, sB = 0.0f;
        #pragma unroll
        for (int nf = 0; nf < 4; nf++) {
            float p0 = fexp(acc[mf][nf][0]);
            float p1 = fexp(acc[mf][nf][1]);
            float p2 = fexp(acc[mf][nf][2]);
            float p3 = fexp(acc[mf][nf][3]);
            sA += p0 + p1; sB += p2 + p3;
            int cl = wx * 32 + nf * 8 + (lane & 3) * 2;
            *reinterpret_cast<__nv_bfloat162*>(pst + rA * 128 + cl) = __floats2bfloat162_rn(p0, p1);
            *reinterpret_cast<__nv_bfloat162*>(pst + rB * 128 + cl) = __floats2bfloat162_rn(p2, p3);
        }
        rsum[mf][0] = sA; rsum[mf][1] = sB;
    }
    #pragma unroll
    for (int o = 1; o <= 2; o <<= 1)
        #pragma unroll
        for (int mf = 0; mf < 4; mf++) {
            rsum[mf][0] += __shfl_xor_sync(0xffffffffu, rsum[mf][0], o);
            rsum[mf][1] += __shfl_xor_sync(0xffffffffu, rsum[mf][1], o);
        }
    if ((lane & 3) == 0) {
        #pragma unroll
        for (int mf = 0; mf < 4; mf++) {
            int rA = wy * 64 + mf * 16 + (lane >> 2);
            sred[wx * 128 + rA]     = rsum[mf][0];
            sred[wx * 128 + rA + 8] = rsum[mf][1];
        }
    }
    __syncthreads();
    if (tid < 128) {
        float se = sred[tid] + sred[128 + tid] + sred[256 + tid] + sred[384 + tid];
        g_sumexp[((size_t)b * Nn + m0 + tid) * 32 + chunk] = se;
    }

    // coalesced P write-out
    #pragma unroll
    for (int i = 0; i < 8; i++) {
        int f4 = tid + i * 256;           // 0..2047 float4s
        int row = f4 >> 4, c8 = (f4 & 15) * 8;
        float4 v = *reinterpret_cast<float4*>(pst + row * 128 + c8);
        *reinterpret_cast<float4*>(g_attb + ((size_t)b * Nn + m0 + row) * Nn + n0 + c8) = v;
    }
}

// ---------------------------------------------------------------------------
// Kernel 4: AV via mma.sync bf16 (clean loop) + epilogue normalization
//   out[c][m] = gamma*fm[m]*zinv[m]*D[m][c] + x[c][m]; zinv computed inline
// grid (2 ctile, 32 mtile, B), 256 threads, dynamic smem 61440
// ---------------------------------------------------------------------------
__global__ __launch_bounds__(256, 2) void av_kernel(
    const float* __restrict__ x, const float* __restrict__ mask,
    const float* __restrict__ skin, const float* __restrict__ gamma,
    float* __restrict__ out)
{
    extern __shared__ __align__(128) char dynsm[];
    __shared__ float fmv[128];
    __shared__ float szv[128];
    const int b = blockIdx.z, m0 = blockIdx.y * 128, c0 = blockIdx.x * 128;
    const int tid = threadIdx.x, wid = tid >> 5, lane = tid & 31;
    const int wy = wid >> 2, wx = wid & 3;
    const uint32_t sb = smem_u32(dynsm);

    if (tid < 128) {
        fmv[tid] = mask[(size_t)b * Nn + m0 + tid] * skin[(size_t)b * Nn + m0 + tid];
        const float4* sp = reinterpret_cast<const float4*>(
            g_sumexp + ((size_t)b * Nn + m0 + tid) * 32);
        float s = 0.0f;
        #pragma unroll
        for (int i = 0; i < 8; i++) {
            float4 v = sp[i];
            s += (v.x + v.y) + (v.z + v.w);
        }
        szv[tid] = 1.0f / s;
    }

    const __half* Asrc = reinterpret_cast<const __half*>(g_attb + ((size_t)b * Nn + m0) * Nn);
    const __half* Bsrc = reinterpret_cast<const __half*>(g_vb + ((size_t)b * Cc + c0) * Nn);

    const int NK = Nn / 32;   // 128
    #pragma unroll
    for (int s = 0; s < 2; s++) {
        uint32_t st = sb + s * STAGE_PAIR;
        load_tile(st, Asrc + s * 32, Nn, tid);
        load_tile(st + TILE_B, Bsrc + s * 32, Nn, tid);
        CP_COMMIT();
    }

    float acc[4][4][4] = {};
    #pragma unroll 1
    for (int s = 0; s < NK; s++) {
        if (s < NK - 1) cp_wait<1>(); else cp_wait<0>();
        __syncthreads();
        if (s + 2 < NK) {
            uint32_t ld = sb + (uint32_t)((s + 2) % NSTAGE) * STAGE_PAIR;
            load_tile(ld, Asrc + (s + 2) * 32, Nn, tid);
            load_tile(ld + TILE_B, Bsrc + (s + 2) * 32, Nn, tid);
            CP_COMMIT();
        }
        const uint32_t st = sb + (uint32_t)(s % NSTAGE) * STAGE_PAIR;
        warp_mma_step_bf(acc, st, st + TILE_B, wy, wx, lane);
    }

    // Fused epilogue: out[c][m] = gamma*fm[m]*zinv[m]*D[m][c] + x[c][m]
    const float gm = __ldg(gamma);
    #pragma unroll
    for (int mf = 0; mf < 4; mf++) {
        const int ml = wy * 64 + mf * 16 + (lane >> 2);    // local m (0..127)
        const float f0 = gm * fmv[ml] * szv[ml];
        const float f1 = gm * fmv[ml + 8] * szv[ml + 8];
        #pragma unroll
        for (int nf = 0; nf < 4; nf++) {
            const int c = c0 + wx * 32 + nf * 8 + (lane & 3) * 2;
            const size_t b0i = ((size_t)b * Cc + c) * Nn + m0 + ml;
            const size_t b1i = b0i + Nn;   // c+1
            out[b0i]     = fmaf(f0, acc[mf][nf][0], x[b0i]);
            out[b1i]     = fmaf(f0, acc[mf][nf][1], x[b1i]);
            out[b0i + 8] = fmaf(f1, acc[mf][nf][2], x[b0i + 8]);
            out[b1i + 8] = fmaf(f1, acc[mf][nf][3], x[b1i + 8]);
        }
    }
}

// ---------------------------------------------------------------------------
extern "C" void kernel_launch(void* const* d_in, const int* in_sizes, int n_in,
                              void* d_out, int out_size)
{
    (void)in_sizes; (void)n_in; (void)out_size;
    const float* x     = (const float*)d_in[0];
    const float* mask  = (const float*)d_in[1];
    const float* skin  = (const float*)d_in[2];
    const float* Wq    = (const float*)d_in[3];
    const float* bq    = (const float*)d_in[4];
    const float* Wk    = (const float*)d_in[5];
    const float* bk    = (const float*)d_in[6];
    const float* Wv    = (const float*)d_in[7];
    const float* bv    = (const float*)d_in[8];
    const float* gamma = (const float*)d_in[9];
    float* out = (float*)d_out;

    cudaFuncSetAttribute(projmma_kernel, cudaFuncAttributeMaxDynamicSharedMemorySize, DYN_SMEM);
    cudaFuncSetAttribute(qk_kernel, cudaFuncAttributeMaxDynamicSharedMemorySize, DYN_SMEM);
    cudaFuncSetAttribute(av_kernel, cudaFuncAttributeMaxDynamicSharedMemorySize, DYN_SMEM);

    dim3 gX(64, 4, Bb);
    xcvt_kernel<<<gX, 256>>>(x);

    wcvt_kernel<<<128, 256>>>(Wq, Wk, Wv);

    dim3 gP(4, 32, Bb);
    projmma_kernel<<<gP, 256, DYN_SMEM>>>(mask, skin, bq, bk, bv);

    dim3 gQK(32, 32, Bb);
    qk_kernel<<<gQK, 256, DYN_SMEM>>>();

    dim3 gAV(2, 32, Bb);
    av_kernel<<<gAV, 256, DYN_SMEM>>>(x, mask, skin, gamma, out);
}

// round 13
// speedup vs baseline: 1.9372x; 1.0269x over previous
#include <cuda_runtime.h>
#include <cuda_fp16.h>
#include <cuda_bf16.h>
#include <cstdint>

// Problem constants
#define Bb 4
#define Cc 256
#define C2v 128
#define Nn 4096

// ---------------------------------------------------------------------------
// Scratch (__device__ globals; allocation-free rule)
// ---------------------------------------------------------------------------
__device__ __half         g_xh[(size_t)Bb * Nn * 256];   // [B][n][c] fp16 x (transposed)
__device__ __half         g_wh[(size_t)512 * 256];       // [o][c]: q 0-127, k 128-255, v 256-511
__device__ __half         g_qc[(size_t)Bb * Nn * 128];   // [B][n][128] fp16 q
__device__ __half         g_kc[(size_t)Bb * Nn * 128];   // [B][n][128] fp16 masked k
__device__ __nv_bfloat16  g_vb[(size_t)Bb * Cc * Nn];    // [B][c][n]  (K-major for AV)
__device__ __nv_bfloat16  g_attb[(size_t)Bb * Nn * Nn];  // P = exp(S), bf16
__device__ float          g_sumexp[(size_t)Bb * Nn * 32];// per-row per-chunk sum of exp

// ---------------------------------------------------------------------------
// Helpers
// ---------------------------------------------------------------------------
__device__ __forceinline__ uint32_t smem_u32(const void* p) {
    uint32_t a;
    asm("{ .reg .u64 t; cvta.to.shared.u64 t, %1; cvt.u32.u64 %0, t; }" : "=r"(a) : "l"(p));
    return a;
}
__device__ __forceinline__ void cp_async16(uint32_t dst, const void* src) {
    asm volatile("cp.async.cg.shared.global [%0], [%1], 16;" :: "r"(dst), "l"(src));
}
#define CP_COMMIT() asm volatile("cp.async.commit_group;" ::: "memory")
template <int N>
__device__ __forceinline__ void cp_wait() {
    asm volatile("cp.async.wait_group %0;" :: "n"(N) : "memory");
}
__device__ __forceinline__ void ldmx4(uint32_t* r, uint32_t addr) {
    asm volatile("ldmatrix.sync.aligned.m8n8.x4.shared.b16 {%0,%1,%2,%3}, [%4];"
        : "=r"(r[0]), "=r"(r[1]), "=r"(r[2]), "=r"(r[3]) : "r"(addr));
}
__device__ __forceinline__ void mma16816(float* d, const uint32_t* a, uint32_t b0, uint32_t b1) {
    asm volatile(
        "mma.sync.aligned.m16n8k16.row.col.f32.f16.f16.f32 "
        "{%0,%1,%2,%3},{%4,%5,%6,%7},{%8,%9},{%0,%1,%2,%3};"
        : "+f"(d[0]), "+f"(d[1]), "+f"(d[2]), "+f"(d[3])
        : "r"(a[0]), "r"(a[1]), "r"(a[2]), "r"(a[3]), "r"(b0), "r"(b1));
}
__device__ __forceinline__ void mma16816bf(float* d, const uint32_t* a, uint32_t b0, uint32_t b1) {
    asm volatile(
        "mma.sync.aligned.m16n8k16.row.col.f32.bf16.bf16.f32 "
        "{%0,%1,%2,%3},{%4,%5,%6,%7},{%8,%9},{%0,%1,%2,%3};"
        : "+f"(d[0]), "+f"(d[1]), "+f"(d[2]), "+f"(d[3])
        : "r"(a[0]), "r"(a[1]), "r"(a[2]), "r"(a[3]), "r"(b0), "r"(b1));
}

// Fast exp: 1 FFMA + 1 MUFU (ex2.approx). Chip MUFU rate = 74 ops/cyc —
// 67M exps ≈ 17 µs, overlapped. ~2 ulp relative error (≪ fp16 logit noise).
__device__ __forceinline__ float fexp(float x) {
    return __expf(x);
}

// ---------------------------------------------------------------------------
// GEMM tile geometry: 128x128 block, BK=32, 8 warps (2x4)
// smem tile: 128 rows x 32 halfwords, row stride 80B; 3-stage ring.
// ---------------------------------------------------------------------------
#define ROWB 80                 // bytes per smem tile row
#define TILE_B (128 * ROWB)     // 10240 per operand tile
#define STAGE_PAIR (2 * TILE_B) // 20480 per stage (A+B)
#define NSTAGE 3
#define DYN_SMEM (NSTAGE * STAGE_PAIR)        // 61440

// Load one 128x32 16-bit tile (row-major src, stride elems) into smem tile.
__device__ __forceinline__ void load_tile(uint32_t dst, const __half* src,
                                          size_t stride, int tid)
{
    #pragma unroll
    for (int i = 0; i < 2; i++) {
        int idx = tid + i * 256;          // 0..511
        int row = idx >> 2, c16 = idx & 3;
        cp_async16(dst + row * ROWB + c16 * 16, src + (size_t)row * stride + c16 * 8);
    }
}

// One BK=32 compute step (fp16 operands)
__device__ __forceinline__ void warp_mma_step(float acc[4][4][4], uint32_t abase,
                                              uint32_t bbase, int wy, int wx, int lane)
{
    #pragma unroll
    for (int ks = 0; ks < 2; ks++) {
        uint32_t a[4][4];
        #pragma unroll
        for (int mf = 0; mf < 4; mf++) {
            int row = wy * 64 + mf * 16 + (lane & 15);
            ldmx4(a[mf], abase + row * ROWB + ks * 32 + ((lane >> 4) << 4));
        }
        uint32_t bf[2][4];
        #pragma unroll
        for (int np = 0; np < 2; np++) {
            int row = wx * 32 + np * 16 + (lane & 7) + ((lane >> 4) << 3);
            ldmx4(bf[np], bbase + row * ROWB + ks * 32 + (((lane >> 3) & 1) << 4));
        }
        #pragma unroll
        for (int mf = 0; mf < 4; mf++)
            #pragma unroll
            for (int nf = 0; nf < 4; nf++)
                mma16816(acc[mf][nf], a[mf],
                         bf[nf >> 1][(nf & 1) * 2], bf[nf >> 1][(nf & 1) * 2 + 1]);
    }
}

// Same, bf16 operands
__device__ __forceinline__ void warp_mma_step_bf(float acc[4][4][4], uint32_t abase,
                                                 uint32_t bbase, int wy, int wx, int lane)
{
    #pragma unroll
    for (int ks = 0; ks < 2; ks++) {
        uint32_t a[4][4];
        #pragma unroll
        for (int mf = 0; mf < 4; mf++) {
            int row = wy * 64 + mf * 16 + (lane & 15);
            ldmx4(a[mf], abase + row * ROWB + ks * 32 + ((lane >> 4) << 4));
        }
        uint32_t bf[2][4];
        #pragma unroll
        for (int np = 0; np < 2; np++) {
            int row = wx * 32 + np * 16 + (lane & 7) + ((lane >> 4) << 3);
            ldmx4(bf[np], bbase + row * ROWB + ks * 32 + (((lane >> 3) & 1) << 4));
        }
        #pragma unroll
        for (int mf = 0; mf < 4; mf++)
            #pragma unroll
            for (int nf = 0; nf < 4; nf++)
                mma16816bf(acc[mf][nf], a[mf],
                           bf[nf >> 1][(nf & 1) * 2], bf[nf >> 1][(nf & 1) * 2 + 1]);
    }
}

// ---------------------------------------------------------------------------
// Kernel 0a: xcvt — transpose-convert x [B][c][n] fp32 -> g_xh [B][n][c] fp16
// ---------------------------------------------------------------------------
__global__ __launch_bounds__(256) void xcvt_kernel(const float* __restrict__ x)
{
    __shared__ float ts[64][65];
    const int b = blockIdx.z, n0 = blockIdx.x * 64, c0 = blockIdx.y * 64;
    const int tid = threadIdx.x;

    #pragma unroll
    for (int i = 0; i < 4; i++) {
        int idx = tid + i * 256;          // 0..1023
        int r = idx >> 4, f4 = idx & 15;  // row c-local, 16B col group
        float4 v = *reinterpret_cast<const float4*>(
            x + ((size_t)b * Cc + c0 + r) * Nn + n0 + f4 * 4);
        ts[r][f4 * 4 + 0] = v.x;
        ts[r][f4 * 4 + 1] = v.y;
        ts[r][f4 * 4 + 2] = v.z;
        ts[r][f4 * 4 + 3] = v.w;
    }
    __syncthreads();

    const int nr = tid >> 2;
    #pragma unroll
    for (int i = 0; i < 2; i++) {
        int c8 = ((tid & 3) * 2 + i) * 8;
        __half h8[8];
        #pragma unroll
        for (int j = 0; j < 8; j++) h8[j] = __float2half(ts[c8 + j][nr]);
        size_t off = ((size_t)b * Nn + n0 + nr) * 256 + c0 + c8;
        *reinterpret_cast<float4*>(g_xh + off) = *reinterpret_cast<float4*>(h8);
    }
}

// ---------------------------------------------------------------------------
// Kernel 0b: wcvt — Wq|Wk|Wv fp32 -> g_wh fp16 [512][256]
// ---------------------------------------------------------------------------
__global__ __launch_bounds__(256) void wcvt_kernel(
    const float* __restrict__ Wq, const float* __restrict__ Wk,
    const float* __restrict__ Wv)
{
    int e4 = blockIdx.x * 256 + threadIdx.x;   // 0..32767
    int row = e4 >> 6, col4 = (e4 & 63) * 4;
    const float* src = (row < 128) ? (Wq + (size_t)row * 256)
                     : (row < 256) ? (Wk + (size_t)(row - 128) * 256)
                                   : (Wv + (size_t)(row - 256) * 256);
    float4 v = *reinterpret_cast<const float4*>(src + col4);
    __half h4[4];
    h4[0] = __float2half(v.x); h4[1] = __float2half(v.y);
    h4[2] = __float2half(v.z); h4[3] = __float2half(v.w);
    *reinterpret_cast<float2*>(g_wh + (size_t)row * 256 + col4) =
        *reinterpret_cast<float2*>(h4);
}

// ---------------------------------------------------------------------------
// Kernel 1: projections via mma.sync fp16, single-term K=256 (NK=8).
//   oblk 0: q -> g_qc fp16 [n][128]
//   oblk 1: masked k -> g_kc fp16 [n][128]
//   oblk 2,3: v -> g_vb bf16 [c][n] via smem-bounce transpose
// grid (4 oblk, 32 mtile, B), 256 threads, dynamic smem 61440.
// ---------------------------------------------------------------------------
#define VPAD 136   // smem v-transpose row stride (halves)

__global__ __launch_bounds__(256, 2) void projmma_kernel(
    const float* __restrict__ mask, const float* __restrict__ skin,
    const float* __restrict__ bq, const float* __restrict__ bk,
    const float* __restrict__ bv)
{
    extern __shared__ __align__(128) char dynsm[];
    __shared__ float fm[128];
    const int b = blockIdx.z, m0 = blockIdx.y * 128, oblk = blockIdx.x;
    const int tid = threadIdx.x, wid = tid >> 5, lane = tid & 31;
    const int wy = wid >> 2, wx = wid & 3;
    const uint32_t sb = smem_u32(dynsm);

    const int NK = 8;
    const __half* Asrc = g_xh + ((size_t)b * Nn + m0) * 256;
    const __half* Bsrc = g_wh + (size_t)oblk * 128 * 256;

    if (oblk == 1 && tid < 128)
        fm[tid] = (1.0f - mask[b * Nn + m0 + tid]) * skin[b * Nn + m0 + tid];

    #pragma unroll
    for (int s = 0; s < 2; s++) {
        uint32_t st = sb + s * STAGE_PAIR;
        load_tile(st, Asrc + s * 32, 256, tid);
        load_tile(st + TILE_B, Bsrc + s * 32, 256, tid);
        CP_COMMIT();
    }

    float acc[4][4][4] = {};
    #pragma unroll 1
    for (int s = 0; s < NK; s++) {
        if (s < NK - 1) cp_wait<1>(); else cp_wait<0>();
        __syncthreads();
        if (s + 2 < NK) {
            uint32_t ld = sb + (uint32_t)((s + 2) % NSTAGE) * STAGE_PAIR;
            load_tile(ld, Asrc + (s + 2) * 32, 256, tid);
            load_tile(ld + TILE_B, Bsrc + (s + 2) * 32, 256, tid);
            CP_COMMIT();
        }
        const uint32_t st = sb + (uint32_t)(s % NSTAGE) * STAGE_PAIR;
        warp_mma_step(acc, st, st + TILE_B, wy, wx, lane);
    }

    // Epilogue
    const float* biasp = (oblk == 0) ? bq : (oblk == 1) ? bk
                       : (oblk == 2) ? bv : (bv + 128);
    float bias0[4], bias1[4];
    #pragma unroll
    for (int nf = 0; nf < 4; nf++) {
        int o = wx * 32 + nf * 8 + (lane & 3) * 2;
        bias0[nf] = biasp[o];
        bias1[nf] = biasp[o + 1];
    }

    if (oblk <= 1) {
        #pragma unroll
        for (int mf = 0; mf < 4; mf++) {
            const int rA = wy * 64 + mf * 16 + (lane >> 2);
            const int rB = rA + 8;
            float fA = 1.0f, fB = 1.0f;
            if (oblk == 1) { fA = fm[rA]; fB = fm[rB]; }
            #pragma unroll
            for (int nf = 0; nf < 4; nf++) {
                const int o = wx * 32 + nf * 8 + (lane & 3) * 2;
                float r0 = (acc[mf][nf][0] + bias0[nf]) * fA;
                float r1 = (acc[mf][nf][1] + bias1[nf]) * fA;
                float r2 = (acc[mf][nf][2] + bias0[nf]) * fB;
                float r3 = (acc[mf][nf][3] + bias1[nf]) * fB;
                __half* dst = (oblk == 0) ? g_qc : g_kc;
                size_t oa = ((size_t)b * Nn + m0 + rA) * 128 + o;
                size_t ob = ((size_t)b * Nn + m0 + rB) * 128 + o;
                *reinterpret_cast<__half2*>(dst + oa) = __floats2half2_rn(r0, r1);
                *reinterpret_cast<__half2*>(dst + ob) = __floats2half2_rn(r2, r3);
            }
        }
    } else {
        // v: bounce through smem [c][n] tile, then coalesced g_vb writes.
        __syncthreads();   // mainloop tiles dead; reuse dynsm
        __nv_bfloat16* vsm = reinterpret_cast<__nv_bfloat16*>(dynsm);
        #pragma unroll
        for (int mf = 0; mf < 4; mf++) {
            const int rA = wy * 64 + mf * 16 + (lane >> 2);   // n-local
            const int rB = rA + 8;
            #pragma unroll
            for (int nf = 0; nf < 4; nf++) {
                const int o = wx * 32 + nf * 8 + (lane & 3) * 2;   // c-local
                vsm[o * VPAD + rA]       = __float2bfloat16(acc[mf][nf][0] + bias0[nf]);
                vsm[(o + 1) * VPAD + rA] = __float2bfloat16(acc[mf][nf][1] + bias1[nf]);
                vsm[o * VPAD + rB]       = __float2bfloat16(acc[mf][nf][2] + bias0[nf]);
                vsm[(o + 1) * VPAD + rB] = __float2bfloat16(acc[mf][nf][3] + bias1[nf]);
            }
        }
        __syncthreads();
        const int c0r = (oblk - 2) * 128;
        #pragma unroll
        for (int i = 0; i < 8; i++) {
            int f4 = tid + i * 256;           // 0..2047
            int row = f4 >> 4, c8 = (f4 & 15) * 8;
            float4 v = *reinterpret_cast<float4*>(vsm + row * VPAD + c8);
            *reinterpret_cast<float4*>(
                g_vb + ((size_t)b * Cc + c0r + row) * Nn + m0 + c8) = v;
        }
    }
}

// ---------------------------------------------------------------------------
// Kernel 2: QK^T -> P = exp(S), single fp16 term, K=128 (NK=4)
// grid (32 nchunk, 32 mtile, B), 256 threads, dynamic smem 61440
// ---------------------------------------------------------------------------
__global__ __launch_bounds__(256, 2) void qk_kernel()
{
    extern __shared__ __align__(128) char dynsm[];
    const int b = blockIdx.z, m0 = blockIdx.y * 128, n0 = blockIdx.x * 128;
    const int chunk = blockIdx.x;
    const int tid = threadIdx.x, wid = tid >> 5, lane = tid & 31;
    const int wy = wid >> 2, wx = wid & 3;
    const uint32_t sb = smem_u32(dynsm);

    const __half* Asrc = g_qc + ((size_t)b * Nn + m0) * 128;
    const __half* Bsrc = g_kc + ((size_t)b * Nn + n0) * 128;

    const int NK = 128 / 32;   // 4
    #pragma unroll
    for (int s = 0; s < 2; s++) {
        uint32_t st = sb + s * STAGE_PAIR;
        load_tile(st, Asrc + s * 32, 128, tid);
        load_tile(st + TILE_B, Bsrc + s * 32, 128, tid);
        CP_COMMIT();
    }

    float acc[4][4][4] = {};
    #pragma unroll 1
    for (int s = 0; s < NK; s++) {
        if (s < NK - 1) cp_wait<1>(); else cp_wait<0>();
        __syncthreads();
        if (s + 2 < NK) {
            uint32_t ld = sb + (uint32_t)((s + 2) % NSTAGE) * STAGE_PAIR;
            load_tile(ld, Asrc + (s + 2) * 32, 128, tid);
            load_tile(ld + TILE_B, Bsrc + (s + 2) * 32, 128, tid);
            CP_COMMIT();
        }
        const uint32_t st = sb + (uint32_t)(s % NSTAGE) * STAGE_PAIR;
        warp_mma_step(acc, st, st + TILE_B, wy, wx, lane);
    }

    // ---- one-pass epilogue: exp (MUFU), stage P (bf16), row sums ----
    __syncthreads();
    float* sred = reinterpret_cast<float*>(dynsm);                  // [4][128]
    __nv_bfloat16* pst = reinterpret_cast<__nv_bfloat16*>(dynsm + 4096); // [128][128]

    float rsum[4][2];
    #pragma unroll
    for (int mf = 0; mf < 4; mf++) {
        int rA = wy * 64 + mf * 16 + (lane >> 2);
        int rB = rA + 8;
        float sA = 0.0f, sB = 0.0f;
        #pragma unroll
        for (int nf = 0; nf < 4; nf++) {
            float p0 = fexp(acc[mf][nf][0]);
            float p1 = fexp(acc[mf][nf][1]);
            float p2 = fexp(acc[mf][nf][2]);
            float p3 = fexp(acc[mf][nf][3]);
            sA += p0 + p1; sB += p2 + p3;
            int cl = wx * 32 + nf * 8 + (lane & 3) * 2;
            *reinterpret_cast<__nv_bfloat162*>(pst + rA * 128 + cl) = __floats2bfloat162_rn(p0, p1);
            *reinterpret_cast<__nv_bfloat162*>(pst + rB * 128 + cl) = __floats2bfloat162_rn(p2, p3);
        }
        rsum[mf][0] = sA; rsum[mf][1] = sB;
    }
    #pragma unroll
    for (int o = 1; o <= 2; o <<= 1)
        #pragma unroll
        for (int mf = 0; mf < 4; mf++) {
            rsum[mf][0] += __shfl_xor_sync(0xffffffffu, rsum[mf][0], o);
            rsum[mf][1] += __shfl_xor_sync(0xffffffffu, rsum[mf][1], o);
        }
    if ((lane & 3) == 0) {
        #pragma unroll
        for (int mf = 0; mf < 4; mf++) {
            int rA = wy * 64 + mf * 16 + (lane >> 2);
            sred[wx * 128 + rA]     = rsum[mf][0];
            sred[wx * 128 + rA + 8] = rsum[mf][1];
        }
    }
    __syncthreads();
    if (tid < 128) {
        float se = sred[tid] + sred[128 + tid] + sred[256 + tid] + sred[384 + tid];
        g_sumexp[((size_t)b * Nn + m0 + tid) * 32 + chunk] = se;
    }

    // coalesced P write-out
    #pragma unroll
    for (int i = 0; i < 8; i++) {
        int f4 = tid + i * 256;           // 0..2047 float4s
        int row = f4 >> 4, c8 = (f4 & 15) * 8;
        float4 v = *reinterpret_cast<float4*>(pst + row * 128 + c8);
        *reinterpret_cast<float4*>(g_attb + ((size_t)b * Nn + m0 + row) * Nn + n0 + c8) = v;
    }
}

// ---------------------------------------------------------------------------
// Kernel 4: AV via mma.sync bf16 (clean loop) + epilogue normalization
//   out[c][m] = gamma*fm[m]*zinv[m]*D[m][c] + x[c][m]; zinv computed inline
// grid (2 ctile, 32 mtile, B), 256 threads, dynamic smem 61440
// ---------------------------------------------------------------------------
__global__ __launch_bounds__(256, 2) void av_kernel(
    const float* __restrict__ x, const float* __restrict__ mask,
    const float* __restrict__ skin, const float* __restrict__ gamma,
    float* __restrict__ out)
{
    extern __shared__ __align__(128) char dynsm[];
    __shared__ float fmv[128];
    __shared__ float szv[128];
    const int b = blockIdx.z, m0 = blockIdx.y * 128, c0 = blockIdx.x * 128;
    const int tid = threadIdx.x, wid = tid >> 5, lane = tid & 31;
    const int wy = wid >> 2, wx = wid & 3;
    const uint32_t sb = smem_u32(dynsm);

    if (tid < 128) {
        fmv[tid] = mask[(size_t)b * Nn + m0 + tid] * skin[(size_t)b * Nn + m0 + tid];
        const float4* sp = reinterpret_cast<const float4*>(
            g_sumexp + ((size_t)b * Nn + m0 + tid) * 32);
        float s = 0.0f;
        #pragma unroll
        for (int i = 0; i < 8; i++) {
            float4 v = sp[i];
            s += (v.x + v.y) + (v.z + v.w);
        }
        szv[tid] = 1.0f / s;
    }

    const __half* Asrc = reinterpret_cast<const __half*>(g_attb + ((size_t)b * Nn + m0) * Nn);
    const __half* Bsrc = reinterpret_cast<const __half*>(g_vb + ((size_t)b * Cc + c0) * Nn);

    const int NK = Nn / 32;   // 128
    #pragma unroll
    for (int s = 0; s < 2; s++) {
        uint32_t st = sb + s * STAGE_PAIR;
        load_tile(st, Asrc + s * 32, Nn, tid);
        load_tile(st + TILE_B, Bsrc + s * 32, Nn, tid);
        CP_COMMIT();
    }

    float acc[4][4][4] = {};
    #pragma unroll 1
    for (int s = 0; s < NK; s++) {
        if (s < NK - 1) cp_wait<1>(); else cp_wait<0>();
        __syncthreads();
        if (s + 2 < NK) {
            uint32_t ld = sb + (uint32_t)((s + 2) % NSTAGE) * STAGE_PAIR;
            load_tile(ld, Asrc + (s + 2) * 32, Nn, tid);
            load_tile(ld + TILE_B, Bsrc + (s + 2) * 32, Nn, tid);
            CP_COMMIT();
        }
        const uint32_t st = sb + (uint32_t)(s % NSTAGE) * STAGE_PAIR;
        warp_mma_step_bf(acc, st, st + TILE_B, wy, wx, lane);
    }

    // Fused epilogue: out[c][m] = gamma*fm[m]*zinv[m]*D[m][c] + x[c][m]
    const float gm = __ldg(gamma);
    #pragma unroll
    for (int mf = 0; mf < 4; mf++) {
        const int ml = wy * 64 + mf * 16 + (lane >> 2);    // local m (0..127)
        const float f0 = gm * fmv[ml] * szv[ml];
        const float f1 = gm * fmv[ml + 8] * szv[ml + 8];
        #pragma unroll
        for (int nf = 0; nf < 4; nf++) {
            const int c = c0 + wx * 32 + nf * 8 + (lane & 3) * 2;
            const size_t b0i = ((size_t)b * Cc + c) * Nn + m0 + ml;
            const size_t b1i = b0i + Nn;   // c+1
            out[b0i]     = fmaf(f0, acc[mf][nf][0], x[b0i]);
            out[b1i]     = fmaf(f0, acc[mf][nf][1], x[b1i]);
            out[b0i + 8] = fmaf(f1, acc[mf][nf][2], x[b0i + 8]);
            out[b1i + 8] = fmaf(f1, acc[mf][nf][3], x[b1i + 8]);
        }
    }
}

// ---------------------------------------------------------------------------
extern "C" void kernel_launch(void* const* d_in, const int* in_sizes, int n_in,
                              void* d_out, int out_size)
{
    (void)in_sizes; (void)n_in; (void)out_size;
    const float* x     = (const float*)d_in[0];
    const float* mask  = (const float*)d_in[1];
    const float* skin  = (const float*)d_in[2];
    const float* Wq    = (const float*)d_in[3];
    const float* bq    = (const float*)d_in[4];
    const float* Wk    = (const float*)d_in[5];
    const float* bk    = (const float*)d_in[6];
    const float* Wv    = (const float*)d_in[7];
    const float* bv    = (const float*)d_in[8];
    const float* gamma = (const float*)d_in[9];
    float* out = (float*)d_out;

    cudaFuncSetAttribute(projmma_kernel, cudaFuncAttributeMaxDynamicSharedMemorySize, DYN_SMEM);
    cudaFuncSetAttribute(qk_kernel, cudaFuncAttributeMaxDynamicSharedMemorySize, DYN_SMEM);
    cudaFuncSetAttribute(av_kernel, cudaFuncAttributeMaxDynamicSharedMemorySize, DYN_SMEM);

    dim3 gX(64, 4, Bb);
    xcvt_kernel<<<gX, 256>>>(x);

    wcvt_kernel<<<128, 256>>>(Wq, Wk, Wv);

    dim3 gP(4, 32, Bb);
    projmma_kernel<<<gP, 256, DYN_SMEM>>>(mask, skin, bq, bk, bv);

    dim3 gQK(32, 32, Bb);
    qk_kernel<<<gQK, 256, DYN_SMEM>>>();

    dim3 gAV(2, 32, Bb);
    av_kernel<<<gAV, 256, DYN_SMEM>>>(x, mask, skin, gamma, out);
}

// round 14
// speedup vs baseline: 2.1108x; 1.0896x over previous
#include <cuda_runtime.h>
#include <cuda_fp16.h>
#include <cuda_bf16.h>
#include <cstdint>

// Problem constants
#define Bb 4
#define Cc 256
#define C2v 128
#define Nn 4096

// ---------------------------------------------------------------------------
// Scratch (__device__ globals; allocation-free rule)
// ---------------------------------------------------------------------------
__device__ __half         g_xh[(size_t)Bb * Nn * 256];   // [B][n][c] fp16 x (transposed)
__device__ __half         g_wh[(size_t)512 * 256];       // [o][c]: q 0-127, k 128-255, v 256-511
__device__ __half         g_qc[(size_t)Bb * Nn * 128];   // [B][n][128] fp16 q
__device__ __half         g_kc[(size_t)Bb * Nn * 128];   // [B][n][128] fp16 masked k
__device__ __nv_bfloat16  g_vb[(size_t)Bb * Cc * Nn];    // [B][c][n]  (K-major for AV)
__device__ __nv_bfloat16  g_attb[(size_t)Bb * Nn * Nn];  // P = exp(S), bf16
__device__ float          g_sumexp[(size_t)Bb * Nn * 32];// per-row per-chunk sum of exp

// ---------------------------------------------------------------------------
// Helpers
// ---------------------------------------------------------------------------
__device__ __forceinline__ uint32_t smem_u32(const void* p) {
    uint32_t a;
    asm("{ .reg .u64 t; cvta.to.shared.u64 t, %1; cvt.u32.u64 %0, t; }" : "=r"(a) : "l"(p));
    return a;
}
__device__ __forceinline__ void cp_async16(uint32_t dst, const void* src) {
    asm volatile("cp.async.cg.shared.global [%0], [%1], 16;" :: "r"(dst), "l"(src));
}
#define CP_COMMIT() asm volatile("cp.async.commit_group;" ::: "memory")
template <int N>
__device__ __forceinline__ void cp_wait() {
    asm volatile("cp.async.wait_group %0;" :: "n"(N) : "memory");
}
__device__ __forceinline__ void ldmx4(uint32_t* r, uint32_t addr) {
    asm volatile("ldmatrix.sync.aligned.m8n8.x4.shared.b16 {%0,%1,%2,%3}, [%4];"
        : "=r"(r[0]), "=r"(r[1]), "=r"(r[2]), "=r"(r[3]) : "r"(addr));
}
__device__ __forceinline__ void mma16816(float* d, const uint32_t* a, uint32_t b0, uint32_t b1) {
    asm volatile(
        "mma.sync.aligned.m16n8k16.row.col.f32.f16.f16.f32 "
        "{%0,%1,%2,%3},{%4,%5,%6,%7},{%8,%9},{%0,%1,%2,%3};"
        : "+f"(d[0]), "+f"(d[1]), "+f"(d[2]), "+f"(d[3])
        : "r"(a[0]), "r"(a[1]), "r"(a[2]), "r"(a[3]), "r"(b0), "r"(b1));
}
__device__ __forceinline__ void mma16816bf(float* d, const uint32_t* a, uint32_t b0, uint32_t b1) {
    asm volatile(
        "mma.sync.aligned.m16n8k16.row.col.f32.bf16.bf16.f32 "
        "{%0,%1,%2,%3},{%4,%5,%6,%7},{%8,%9},{%0,%1,%2,%3};"
        : "+f"(d[0]), "+f"(d[1]), "+f"(d[2]), "+f"(d[3])
        : "r"(a[0]), "r"(a[1]), "r"(a[2]), "r"(a[3]), "r"(b0), "r"(b1));
}

// Fast exp: 1 FFMA + 1 MUFU (ex2.approx).
__device__ __forceinline__ float fexp(float x) {
    return __expf(x);
}

// ---------------------------------------------------------------------------
// GEMM tile geometry: 128x128 block, BK=32, 8 warps (2x4)
// smem tile: 128 rows x 32 halfwords, row stride 80B; 3-stage ring.
// ---------------------------------------------------------------------------
#define ROWB 80                 // bytes per smem tile row
#define TILE_B (128 * ROWB)     // 10240 per operand tile
#define STAGE_PAIR (2 * TILE_B) // 20480 per stage (A+B)
#define NSTAGE 3
#define DYN_SMEM (NSTAGE * STAGE_PAIR)        // 61440

// Load one 128x32 16-bit tile (row-major src, stride elems) into smem tile.
__device__ __forceinline__ void load_tile(uint32_t dst, const __half* src,
                                          size_t stride, int tid)
{
    #pragma unroll
    for (int i = 0; i < 2; i++) {
        int idx = tid + i * 256;          // 0..511
        int row = idx >> 2, c16 = idx & 3;
        cp_async16(dst + row * ROWB + c16 * 16, src + (size_t)row * stride + c16 * 8);
    }
}

// One BK=32 compute step (fp16 operands)
__device__ __forceinline__ void warp_mma_step(float acc[4][4][4], uint32_t abase,
                                              uint32_t bbase, int wy, int wx, int lane)
{
    #pragma unroll
    for (int ks = 0; ks < 2; ks++) {
        uint32_t a[4][4];
        #pragma unroll
        for (int mf = 0; mf < 4; mf++) {
            int row = wy * 64 + mf * 16 + (lane & 15);
            ldmx4(a[mf], abase + row * ROWB + ks * 32 + ((lane >> 4) << 4));
        }
        uint32_t bf[2][4];
        #pragma unroll
        for (int np = 0; np < 2; np++) {
            int row = wx * 32 + np * 16 + (lane & 7) + ((lane >> 4) << 3);
            ldmx4(bf[np], bbase + row * ROWB + ks * 32 + (((lane >> 3) & 1) << 4));
        }
        #pragma unroll
        for (int mf = 0; mf < 4; mf++)
            #pragma unroll
            for (int nf = 0; nf < 4; nf++)
                mma16816(acc[mf][nf], a[mf],
                         bf[nf >> 1][(nf & 1) * 2], bf[nf >> 1][(nf & 1) * 2 + 1]);
    }
}

// Same, bf16 operands
__device__ __forceinline__ void warp_mma_step_bf(float acc[4][4][4], uint32_t abase,
                                                 uint32_t bbase, int wy, int wx, int lane)
{
    #pragma unroll
    for (int ks = 0; ks < 2; ks++) {
        uint32_t a[4][4];
        #pragma unroll
        for (int mf = 0; mf < 4; mf++) {
            int row = wy * 64 + mf * 16 + (lane & 15);
            ldmx4(a[mf], abase + row * ROWB + ks * 32 + ((lane >> 4) << 4));
        }
        uint32_t bf[2][4];
        #pragma unroll
        for (int np = 0; np < 2; np++) {
            int row = wx * 32 + np * 16 + (lane & 7) + ((lane >> 4) << 3);
            ldmx4(bf[np], bbase + row * ROWB + ks * 32 + (((lane >> 3) & 1) << 4));
        }
        #pragma unroll
        for (int mf = 0; mf < 4; mf++)
            #pragma unroll
            for (int nf = 0; nf < 4; nf++)
                mma16816bf(acc[mf][nf], a[mf],
                           bf[nf >> 1][(nf & 1) * 2], bf[nf >> 1][(nf & 1) * 2 + 1]);
    }
}

// ---------------------------------------------------------------------------
// Kernel 0a: xcvt — transpose-convert x [B][c][n] fp32 -> g_xh [B][n][c] fp16
// ---------------------------------------------------------------------------
__global__ __launch_bounds__(256) void xcvt_kernel(const float* __restrict__ x)
{
    __shared__ float ts[64][65];
    const int b = blockIdx.z, n0 = blockIdx.x * 64, c0 = blockIdx.y * 64;
    const int tid = threadIdx.x;

    #pragma unroll
    for (int i = 0; i < 4; i++) {
        int idx = tid + i * 256;          // 0..1023
        int r = idx >> 4, f4 = idx & 15;  // row c-local, 16B col group
        float4 v = *reinterpret_cast<const float4*>(
            x + ((size_t)b * Cc + c0 + r) * Nn + n0 + f4 * 4);
        ts[r][f4 * 4 + 0] = v.x;
        ts[r][f4 * 4 + 1] = v.y;
        ts[r][f4 * 4 + 2] = v.z;
        ts[r][f4 * 4 + 3] = v.w;
    }
    __syncthreads();

    const int nr = tid >> 2;
    #pragma unroll
    for (int i = 0; i < 2; i++) {
        int c8 = ((tid & 3) * 2 + i) * 8;
        __half h8[8];
        #pragma unroll
        for (int j = 0; j < 8; j++) h8[j] = __float2half(ts[c8 + j][nr]);
        size_t off = ((size_t)b * Nn + n0 + nr) * 256 + c0 + c8;
        *reinterpret_cast<float4*>(g_xh + off) = *reinterpret_cast<float4*>(h8);
    }
}

// ---------------------------------------------------------------------------
// Kernel 0b: wcvt — Wq|Wk|Wv fp32 -> g_wh fp16 [512][256]
// ---------------------------------------------------------------------------
__global__ __launch_bounds__(256) void wcvt_kernel(
    const float* __restrict__ Wq, const float* __restrict__ Wk,
    const float* __restrict__ Wv)
{
    int e4 = blockIdx.x * 256 + threadIdx.x;   // 0..32767
    int row = e4 >> 6, col4 = (e4 & 63) * 4;
    const float* src = (row < 128) ? (Wq + (size_t)row * 256)
                     : (row < 256) ? (Wk + (size_t)(row - 128) * 256)
                                   : (Wv + (size_t)(row - 256) * 256);
    float4 v = *reinterpret_cast<const float4*>(src + col4);
    __half h4[4];
    h4[0] = __float2half(v.x); h4[1] = __float2half(v.y);
    h4[2] = __float2half(v.z); h4[3] = __float2half(v.w);
    *reinterpret_cast<float2*>(g_wh + (size_t)row * 256 + col4) =
        *reinterpret_cast<float2*>(h4);
}

// ---------------------------------------------------------------------------
// Kernel 1: projections via mma.sync fp16, single-term K=256 (NK=8).
//   oblk 0: q -> g_qc fp16 [n][128]
//   oblk 1: masked k -> g_kc fp16 [n][128]
//   oblk 2,3: v -> g_vb bf16 [c][n] via smem-bounce transpose
// grid (4 oblk, 32 mtile, B), 256 threads, dynamic smem 61440.
// ---------------------------------------------------------------------------
#define VPAD 136   // smem v-transpose row stride (halves)

__global__ __launch_bounds__(256, 2) void projmma_kernel(
    const float* __restrict__ mask, const float* __restrict__ skin,
    const float* __restrict__ bq, const float* __restrict__ bk,
    const float* __restrict__ bv)
{
    extern __shared__ __align__(128) char dynsm[];
    __shared__ float fm[128];
    const int b = blockIdx.z, m0 = blockIdx.y * 128, oblk = blockIdx.x;
    const int tid = threadIdx.x, wid = tid >> 5, lane = tid & 31;
    const int wy = wid >> 2, wx = wid & 3;
    const uint32_t sb = smem_u32(dynsm);

    const int NK = 8;
    const __half* Asrc = g_xh + ((size_t)b * Nn + m0) * 256;
    const __half* Bsrc = g_wh + (size_t)oblk * 128 * 256;

    if (oblk == 1 && tid < 128)
        fm[tid] = (1.0f - mask[b * Nn + m0 + tid]) * skin[b * Nn + m0 + tid];

    #pragma unroll
    for (int s = 0; s < 2; s++) {
        uint32_t st = sb + s * STAGE_PAIR;
        load_tile(st, Asrc + s * 32, 256, tid);
        load_tile(st + TILE_B, Bsrc + s * 32, 256, tid);
        CP_COMMIT();
    }

    float acc[4][4][4] = {};
    #pragma unroll 1
    for (int s = 0; s < NK; s++) {
        if (s < NK - 1) cp_wait<1>(); else cp_wait<0>();
        __syncthreads();
        if (s + 2 < NK) {
            uint32_t ld = sb + (uint32_t)((s + 2) % NSTAGE) * STAGE_PAIR;
            load_tile(ld, Asrc + (s + 2) * 32, 256, tid);
            load_tile(ld + TILE_B, Bsrc + (s + 2) * 32, 256, tid);
            CP_COMMIT();
        }
        const uint32_t st = sb + (uint32_t)(s % NSTAGE) * STAGE_PAIR;
        warp_mma_step(acc, st, st + TILE_B, wy, wx, lane);
    }

    // Epilogue
    const float* biasp = (oblk == 0) ? bq : (oblk == 1) ? bk
                       : (oblk == 2) ? bv : (bv + 128);
    float bias0[4], bias1[4];
    #pragma unroll
    for (int nf = 0; nf < 4; nf++) {
        int o = wx * 32 + nf * 8 + (lane & 3) * 2;
        bias0[nf] = biasp[o];
        bias1[nf] = biasp[o + 1];
    }

    if (oblk <= 1) {
        #pragma unroll
        for (int mf = 0; mf < 4; mf++) {
            const int rA = wy * 64 + mf * 16 + (lane >> 2);
            const int rB = rA + 8;
            float fA = 1.0f, fB = 1.0f;
            if (oblk == 1) { fA = fm[rA]; fB = fm[rB]; }
            #pragma unroll
            for (int nf = 0; nf < 4; nf++) {
                const int o = wx * 32 + nf * 8 + (lane & 3) * 2;
                float r0 = (acc[mf][nf][0] + bias0[nf]) * fA;
                float r1 = (acc[mf][nf][1] + bias1[nf]) * fA;
                float r2 = (acc[mf][nf][2] + bias0[nf]) * fB;
                float r3 = (acc[mf][nf][3] + bias1[nf]) * fB;
                __half* dst = (oblk == 0) ? g_qc : g_kc;
                size_t oa = ((size_t)b * Nn + m0 + rA) * 128 + o;
                size_t ob = ((size_t)b * Nn + m0 + rB) * 128 + o;
                *reinterpret_cast<__half2*>(dst + oa) = __floats2half2_rn(r0, r1);
                *reinterpret_cast<__half2*>(dst + ob) = __floats2half2_rn(r2, r3);
            }
        }
    } else {
        // v: bounce through smem [c][n] tile, then coalesced g_vb writes.
        __syncthreads();   // mainloop tiles dead; reuse dynsm
        __nv_bfloat16* vsm = reinterpret_cast<__nv_bfloat16*>(dynsm);
        #pragma unroll
        for (int mf = 0; mf < 4; mf++) {
            const int rA = wy * 64 + mf * 16 + (lane >> 2);   // n-local
            const int rB = rA + 8;
            #pragma unroll
            for (int nf = 0; nf < 4; nf++) {
                const int o = wx * 32 + nf * 8 + (lane & 3) * 2;   // c-local
                vsm[o * VPAD + rA]       = __float2bfloat16(acc[mf][nf][0] + bias0[nf]);
                vsm[(o + 1) * VPAD + rA] = __float2bfloat16(acc[mf][nf][1] + bias1[nf]);
                vsm[o * VPAD + rB]       = __float2bfloat16(acc[mf][nf][2] + bias0[nf]);
                vsm[(o + 1) * VPAD + rB] = __float2bfloat16(acc[mf][nf][3] + bias1[nf]);
            }
        }
        __syncthreads();
        const int c0r = (oblk - 2) * 128;
        #pragma unroll
        for (int i = 0; i < 8; i++) {
            int f4 = tid + i * 256;           // 0..2047
            int row = f4 >> 4, c8 = (f4 & 15) * 8;
            float4 v = *reinterpret_cast<float4*>(vsm + row * VPAD + c8);
            *reinterpret_cast<float4*>(
                g_vb + ((size_t)b * Cc + c0r + row) * Nn + m0 + c8) = v;
        }
    }
}

// ---------------------------------------------------------------------------
// Kernel 2: QK^T -> P = exp(S), single fp16 term, K=128 (NK=4)
// grid (32 nchunk, 32 mtile, B), 256 threads, dynamic smem 61440
// P staging stride padded to 136 halves -> conflict-free STS (was 8-way).
// ---------------------------------------------------------------------------
#define PSTR 136   // P staging row stride in halves (272B = 68 words; 4*r mod 32 distinct)

__global__ __launch_bounds__(256, 2) void qk_kernel()
{
    extern __shared__ __align__(128) char dynsm[];
    const int b = blockIdx.z, m0 = blockIdx.y * 128, n0 = blockIdx.x * 128;
    const int chunk = blockIdx.x;
    const int tid = threadIdx.x, wid = tid >> 5, lane = tid & 31;
    const int wy = wid >> 2, wx = wid & 3;
    const uint32_t sb = smem_u32(dynsm);

    const __half* Asrc = g_qc + ((size_t)b * Nn + m0) * 128;
    const __half* Bsrc = g_kc + ((size_t)b * Nn + n0) * 128;

    const int NK = 128 / 32;   // 4
    #pragma unroll
    for (int s = 0; s < 2; s++) {
        uint32_t st = sb + s * STAGE_PAIR;
        load_tile(st, Asrc + s * 32, 128, tid);
        load_tile(st + TILE_B, Bsrc + s * 32, 128, tid);
        CP_COMMIT();
    }

    float acc[4][4][4] = {};
    #pragma unroll 1
    for (int s = 0; s < NK; s++) {
        if (s < NK - 1) cp_wait<1>(); else cp_wait<0>();
        __syncthreads();
        if (s + 2 < NK) {
            uint32_t ld = sb + (uint32_t)((s + 2) % NSTAGE) * STAGE_PAIR;
            load_tile(ld, Asrc + (s + 2) * 32, 128, tid);
            load_tile(ld + TILE_B, Bsrc + (s + 2) * 32, 128, tid);
            CP_COMMIT();
        }
        const uint32_t st = sb + (uint32_t)(s % NSTAGE) * STAGE_PAIR;
        warp_mma_step(acc, st, st + TILE_B, wy, wx, lane);
    }

    // ---- one-pass epilogue: exp (MUFU), stage P (bf16), row sums ----
    __syncthreads();
    float* sred = reinterpret_cast<float*>(dynsm);                  // [4][128]
    __nv_bfloat16* pst = reinterpret_cast<__nv_bfloat16*>(dynsm + 4096); // [128][PSTR]

    float rsum[4][2];
    #pragma unroll
    for (int mf = 0; mf < 4; mf++) {
        int rA = wy * 64 + mf * 16 + (lane >> 2);
        int rB = rA + 8;
        float sA = 0.0f, sB = 0.0f;
        #pragma unroll
        for (int nf = 0; nf < 4; nf++) {
            float p0 = fexp(acc[mf][nf][0]);
            float p1 = fexp(acc[mf][nf][1]);
            float p2 = fexp(acc[mf][nf][2]);
            float p3 = fexp(acc[mf][nf][3]);
            sA += p0 + p1; sB += p2 + p3;
            int cl = wx * 32 + nf * 8 + (lane & 3) * 2;
            *reinterpret_cast<__nv_bfloat162*>(pst + rA * PSTR + cl) = __floats2bfloat162_rn(p0, p1);
            *reinterpret_cast<__nv_bfloat162*>(pst + rB * PSTR + cl) = __floats2bfloat162_rn(p2, p3);
        }
        rsum[mf][0] = sA; rsum[mf][1] = sB;
    }
    #pragma unroll
    for (int o = 1; o <= 2; o <<= 1)
        #pragma unroll
        for (int mf = 0; mf < 4; mf++) {
            rsum[mf][0] += __shfl_xor_sync(0xffffffffu, rsum[mf][0], o);
            rsum[mf][1] += __shfl_xor_sync(0xffffffffu, rsum[mf][1], o);
        }
    if ((lane & 3) == 0) {
        #pragma unroll
        for (int mf = 0; mf < 4; mf++) {
            int rA = wy * 64 + mf * 16 + (lane >> 2);
            sred[wx * 128 + rA]     = rsum[mf][0];
            sred[wx * 128 + rA + 8] = rsum[mf][1];
        }
    }
    __syncthreads();
    if (tid < 128) {
        float se = sred[tid] + sred[128 + tid] + sred[256 + tid] + sred[384 + tid];
        g_sumexp[((size_t)b * Nn + m0 + tid) * 32 + chunk] = se;
    }

    // coalesced P write-out
    #pragma unroll
    for (int i = 0; i < 8; i++) {
        int f4 = tid + i * 256;           // 0..2047 float4s
        int row = f4 >> 4, c8 = (f4 & 15) * 8;
        float4 v = *reinterpret_cast<float4*>(pst + row * PSTR + c8);
        *reinterpret_cast<float4*>(g_attb + ((size_t)b * Nn + m0 + row) * Nn + n0 + c8) = v;
    }
}

// ---------------------------------------------------------------------------
// Kernel 4: AV via mma.sync bf16 (clean loop) + epilogue normalization
//   out[c][m] = gamma*fm[m]*zinv[m]*D[m][c] + x[c][m]; zinv computed inline
// grid (2 ctile, 32 mtile, B), 256 threads, dynamic smem 61440
// ---------------------------------------------------------------------------
__global__ __launch_bounds__(256, 2) void av_kernel(
    const float* __restrict__ x, const float* __restrict__ mask,
    const float* __restrict__ skin, const float* __restrict__ gamma,
    float* __restrict__ out)
{
    extern __shared__ __align__(128) char dynsm[];
    __shared__ float fmv[128];
    __shared__ float szv[128];
    const int b = blockIdx.z, m0 = blockIdx.y * 128, c0 = blockIdx.x * 128;
    const int tid = threadIdx.x, wid = tid >> 5, lane = tid & 31;
    const int wy = wid >> 2, wx = wid & 3;
    const uint32_t sb = smem_u32(dynsm);

    if (tid < 128) {
        fmv[tid] = mask[(size_t)b * Nn + m0 + tid] * skin[(size_t)b * Nn + m0 + tid];
        const float4* sp = reinterpret_cast<const float4*>(
            g_sumexp + ((size_t)b * Nn + m0 + tid) * 32);
        float s = 0.0f;
        #pragma unroll
        for (int i = 0; i < 8; i++) {
            float4 v = sp[i];
            s += (v.x + v.y) + (v.z + v.w);
        }
        szv[tid] = 1.0f / s;
    }

    const __half* Asrc = reinterpret_cast<const __half*>(g_attb + ((size_t)b * Nn + m0) * Nn);
    const __half* Bsrc = reinterpret_cast<const __half*>(g_vb + ((size_t)b * Cc + c0) * Nn);

    const int NK = Nn / 32;   // 128
    #pragma unroll
    for (int s = 0; s < 2; s++) {
        uint32_t st = sb + s * STAGE_PAIR;
        load_tile(st, Asrc + s * 32, Nn, tid);
        load_tile(st + TILE_B, Bsrc + s * 32, Nn, tid);
        CP_COMMIT();
    }

    float acc[4][4][4] = {};
    #pragma unroll 1
    for (int s = 0; s < NK; s++) {
        if (s < NK - 1) cp_wait<1>(); else cp_wait<0>();
        __syncthreads();
        if (s + 2 < NK) {
            uint32_t ld = sb + (uint32_t)((s + 2) % NSTAGE) * STAGE_PAIR;
            load_tile(ld, Asrc + (s + 2) * 32, Nn, tid);
            load_tile(ld + TILE_B, Bsrc + (s + 2) * 32, Nn, tid);
            CP_COMMIT();
        }
        const uint32_t st = sb + (uint32_t)(s % NSTAGE) * STAGE_PAIR;
        warp_mma_step_bf(acc, st, st + TILE_B, wy, wx, lane);
    }

    // Fused epilogue: out[c][m] = gamma*fm[m]*zinv[m]*D[m][c] + x[c][m]
    const float gm = __ldg(gamma);
    #pragma unroll
    for (int mf = 0; mf < 4; mf++) {
        const int ml = wy * 64 + mf * 16 + (lane >> 2);    // local m (0..127)
        const float f0 = gm * fmv[ml] * szv[ml];
        const float f1 = gm * fmv[ml + 8] * szv[ml + 8];
        #pragma unroll
        for (int nf = 0; nf < 4; nf++) {
            const int c = c0 + wx * 32 + nf * 8 + (lane & 3) * 2;
            const size_t b0i = ((size_t)b * Cc + c) * Nn + m0 + ml;
            const size_t b1i = b0i + Nn;   // c+1
            out[b0i]     = fmaf(f0, acc[mf][nf][0], x[b0i]);
            out[b1i]     = fmaf(f0, acc[mf][nf][1], x[b1i]);
            out[b0i + 8] = fmaf(f1, acc[mf][nf][2], x[b0i + 8]);
            out[b1i + 8] = fmaf(f1, acc[mf][nf][3], x[b1i + 8]);
        }
    }
}

// ---------------------------------------------------------------------------
extern "C" void kernel_launch(void* const* d_in, const int* in_sizes, int n_in,
                              void* d_out, int out_size)
{
    (void)in_sizes; (void)n_in; (void)out_size;
    const float* x     = (const float*)d_in[0];
    const float* mask  = (const float*)d_in[1];
    const float* skin  = (const float*)d_in[2];
    const float* Wq    = (const float*)d_in[3];
    const float* bq    = (const float*)d_in[4];
    const float* Wk    = (const float*)d_in[5];
    const float* bk    = (const float*)d_in[6];
    const float* Wv    = (const float*)d_in[7];
    const float* bv    = (const float*)d_in[8];
    const float* gamma = (const float*)d_in[9];
    float* out = (float*)d_out;

    cudaFuncSetAttribute(projmma_kernel, cudaFuncAttributeMaxDynamicSharedMemorySize, DYN_SMEM);
    cudaFuncSetAttribute(qk_kernel, cudaFuncAttributeMaxDynamicSharedMemorySize, DYN_SMEM);
    cudaFuncSetAttribute(av_kernel, cudaFuncAttributeMaxDynamicSharedMemorySize, DYN_SMEM);

    dim3 gX(64, 4, Bb);
    xcvt_kernel<<<gX, 256>>>(x);

    wcvt_kernel<<<128, 256>>>(Wq, Wk, Wv);

    dim3 gP(4, 32, Bb);
    projmma_kernel<<<gP, 256, DYN_SMEM>>>(mask, skin, bq, bk, bv);

    dim3 gQK(32, 32, Bb);
    qk_kernel<<<gQK, 256, DYN_SMEM>>>();

    dim3 gAV(2, 32, Bb);
    av_kernel<<<gAV, 256, DYN_SMEM>>>(x, mask, skin, gamma, out);
}

// round 16
// speedup vs baseline: 2.1632x; 1.0248x over previous
#include <cuda_runtime.h>
#include <cuda_fp16.h>
#include <cuda_bf16.h>
#include <cstdint>

// Problem constants
#define Bb 4
#define Cc 256
#define C2v 128
#define Nn 4096

// ---------------------------------------------------------------------------
// Scratch (__device__ globals; allocation-free rule)
// ---------------------------------------------------------------------------
__device__ __half         g_xh[(size_t)Bb * Nn * 256];   // [B][n][c] fp16 x (transposed)
__device__ __half         g_wh[(size_t)512 * 256];       // [o][c]: q 0-127, k 128-255, v 256-511
__device__ __half         g_qc[(size_t)Bb * Nn * 128];   // [B][n][128] fp16 q
__device__ __half         g_kc[(size_t)Bb * Nn * 128];   // [B][n][128] fp16 masked k
__device__ __nv_bfloat16  g_vb[(size_t)Bb * Cc * Nn];    // [B][c][n]  (K-major for AV)
__device__ __nv_bfloat16  g_attb[(size_t)Bb * Nn * Nn];  // P = exp(S), bf16
__device__ float          g_sumexp[(size_t)Bb * Nn * 32];// per-row per-chunk sum of exp

// ---------------------------------------------------------------------------
// Helpers
// ---------------------------------------------------------------------------
__device__ __forceinline__ uint32_t smem_u32(const void* p) {
    uint32_t a;
    asm("{ .reg .u64 t; cvta.to.shared.u64 t, %1; cvt.u32.u64 %0, t; }" : "=r"(a) : "l"(p));
    return a;
}
__device__ __forceinline__ void cp_async16(uint32_t dst, const void* src) {
    asm volatile("cp.async.cg.shared.global [%0], [%1], 16;" :: "r"(dst), "l"(src));
}
#define CP_COMMIT() asm volatile("cp.async.commit_group;" ::: "memory")
template <int N>
__device__ __forceinline__ void cp_wait() {
    asm volatile("cp.async.wait_group %0;" :: "n"(N) : "memory");
}
__device__ __forceinline__ void ldmx4(uint32_t* r, uint32_t addr) {
    asm volatile("ldmatrix.sync.aligned.m8n8.x4.shared.b16 {%0,%1,%2,%3}, [%4];"
        : "=r"(r[0]), "=r"(r[1]), "=r"(r[2]), "=r"(r[3]) : "r"(addr));
}
__device__ __forceinline__ void mma16816(float* d, const uint32_t* a, uint32_t b0, uint32_t b1) {
    asm volatile(
        "mma.sync.aligned.m16n8k16.row.col.f32.f16.f16.f32 "
        "{%0,%1,%2,%3},{%4,%5,%6,%7},{%8,%9},{%0,%1,%2,%3};"
        : "+f"(d[0]), "+f"(d[1]), "+f"(d[2]), "+f"(d[3])
        : "r"(a[0]), "r"(a[1]), "r"(a[2]), "r"(a[3]), "r"(b0), "r"(b1));
}
__device__ __forceinline__ void mma16816bf(float* d, const uint32_t* a, uint32_t b0, uint32_t b1) {
    asm volatile(
        "mma.sync.aligned.m16n8k16.row.col.f32.bf16.bf16.f32 "
        "{%0,%1,%2,%3},{%4,%5,%6,%7},{%8,%9},{%0,%1,%2,%3};"
        : "+f"(d[0]), "+f"(d[1]), "+f"(d[2]), "+f"(d[3])
        : "r"(a[0]), "r"(a[1]), "r"(a[2]), "r"(a[3]), "r"(b0), "r"(b1));
}

// Fast exp: 1 FFMA + 1 MUFU (ex2.approx).
__device__ __forceinline__ float fexp(float x) {
    return __expf(x);
}

// ---------------------------------------------------------------------------
// GEMM tile geometry: 128x128 block, BK=32, 8 warps (2x4)
// smem tile: 128 rows x 32 halfwords, row stride 80B.
// ---------------------------------------------------------------------------
#define ROWB 80                 // bytes per smem tile row
#define TILE_B (128 * ROWB)     // 10240 per operand tile
#define STAGE_PAIR (2 * TILE_B) // 20480 per stage (A+B)
#define NSTAGE 3
#define DYN_SMEM (NSTAGE * STAGE_PAIR)        // 61440 (projmma / av)

// qk smem layout: resident A (4 k-tiles) + 3-stage B ring + sred + pst
#define QK_BOFF 40960u          // B ring base (after 4 A k-tiles)
#define QK_SRED 71680u          // 4*128 floats
#define QK_PST  73728u          // 128 x PSTR bf16
#define PSTR 136                // P staging row stride (halves), conflict-free
#define DYN_QK  108544

// Load one 128x32 16-bit tile (row-major src, stride elems) into smem tile.
__device__ __forceinline__ void load_tile(uint32_t dst, const __half* src,
                                          size_t stride, int tid)
{
    #pragma unroll
    for (int i = 0; i < 2; i++) {
        int idx = tid + i * 256;          // 0..511
        int row = idx >> 2, c16 = idx & 3;
        cp_async16(dst + row * ROWB + c16 * 16, src + (size_t)row * stride + c16 * 8);
    }
}

// One BK=32 compute step (fp16 operands)
__device__ __forceinline__ void warp_mma_step(float acc[4][4][4], uint32_t abase,
                                              uint32_t bbase, int wy, int wx, int lane)
{
    #pragma unroll
    for (int ks = 0; ks < 2; ks++) {
        uint32_t a[4][4];
        #pragma unroll
        for (int mf = 0; mf < 4; mf++) {
            int row = wy * 64 + mf * 16 + (lane & 15);
            ldmx4(a[mf], abase + row * ROWB + ks * 32 + ((lane >> 4) << 4));
        }
        uint32_t bf[2][4];
        #pragma unroll
        for (int np = 0; np < 2; np++) {
            int row = wx * 32 + np * 16 + (lane & 7) + ((lane >> 4) << 3);
            ldmx4(bf[np], bbase + row * ROWB + ks * 32 + (((lane >> 3) & 1) << 4));
        }
        #pragma unroll
        for (int mf = 0; mf < 4; mf++)
            #pragma unroll
            for (int nf = 0; nf < 4; nf++)
                mma16816(acc[mf][nf], a[mf],
                         bf[nf >> 1][(nf & 1) * 2], bf[nf >> 1][(nf & 1) * 2 + 1]);
    }
}

// Same, bf16 operands
__device__ __forceinline__ void warp_mma_step_bf(float acc[4][4][4], uint32_t abase,
                                                 uint32_t bbase, int wy, int wx, int lane)
{
    #pragma unroll
    for (int ks = 0; ks < 2; ks++) {
        uint32_t a[4][4];
        #pragma unroll
        for (int mf = 0; mf < 4; mf++) {
            int row = wy * 64 + mf * 16 + (lane & 15);
            ldmx4(a[mf], abase + row * ROWB + ks * 32 + ((lane >> 4) << 4));
        }
        uint32_t bf[2][4];
        #pragma unroll
        for (int np = 0; np < 2; np++) {
            int row = wx * 32 + np * 16 + (lane & 7) + ((lane >> 4) << 3);
            ldmx4(bf[np], bbase + row * ROWB + ks * 32 + (((lane >> 3) & 1) << 4));
        }
        #pragma unroll
        for (int mf = 0; mf < 4; mf++)
            #pragma unroll
            for (int nf = 0; nf < 4; nf++)
                mma16816bf(acc[mf][nf], a[mf],
                           bf[nf >> 1][(nf & 1) * 2], bf[nf >> 1][(nf & 1) * 2 + 1]);
    }
}

// ---------------------------------------------------------------------------
// Kernel 0a: xcvt — transpose-convert x [B][c][n] fp32 -> g_xh [B][n][c] fp16
// ---------------------------------------------------------------------------
__global__ __launch_bounds__(256) void xcvt_kernel(const float* __restrict__ x)
{
    __shared__ float ts[64][65];
    const int b = blockIdx.z, n0 = blockIdx.x * 64, c0 = blockIdx.y * 64;
    const int tid = threadIdx.x;

    #pragma unroll
    for (int i = 0; i < 4; i++) {
        int idx = tid + i * 256;          // 0..1023
        int r = idx >> 4, f4 = idx & 15;  // row c-local, 16B col group
        float4 v = *reinterpret_cast<const float4*>(
            x + ((size_t)b * Cc + c0 + r) * Nn + n0 + f4 * 4);
        ts[r][f4 * 4 + 0] = v.x;
        ts[r][f4 * 4 + 1] = v.y;
        ts[r][f4 * 4 + 2] = v.z;
        ts[r][f4 * 4 + 3] = v.w;
    }
    __syncthreads();

    const int nr = tid >> 2;
    #pragma unroll
    for (int i = 0; i < 2; i++) {
        int c8 = ((tid & 3) * 2 + i) * 8;
        __half h8[8];
        #pragma unroll
        for (int j = 0; j < 8; j++) h8[j] = __float2half(ts[c8 + j][nr]);
        size_t off = ((size_t)b * Nn + n0 + nr) * 256 + c0 + c8;
        *reinterpret_cast<float4*>(g_xh + off) = *reinterpret_cast<float4*>(h8);
    }
}

// ---------------------------------------------------------------------------
// Kernel 0b: wcvt — Wq|Wk|Wv fp32 -> g_wh fp16 [512][256]
// ---------------------------------------------------------------------------
__global__ __launch_bounds__(256) void wcvt_kernel(
    const float* __restrict__ Wq, const float* __restrict__ Wk,
    const float* __restrict__ Wv)
{
    int e4 = blockIdx.x * 256 + threadIdx.x;   // 0..32767
    int row = e4 >> 6, col4 = (e4 & 63) * 4;
    const float* src = (row < 128) ? (Wq + (size_t)row * 256)
                     : (row < 256) ? (Wk + (size_t)(row - 128) * 256)
                                   : (Wv + (size_t)(row - 256) * 256);
    float4 v = *reinterpret_cast<const float4*>(src + col4);
    __half h4[4];
    h4[0] = __float2half(v.x); h4[1] = __float2half(v.y);
    h4[2] = __float2half(v.z); h4[3] = __float2half(v.w);
    *reinterpret_cast<float2*>(g_wh + (size_t)row * 256 + col4) =
        *reinterpret_cast<float2*>(h4);
}

// ---------------------------------------------------------------------------
// Kernel 1: projections via mma.sync fp16, single-term K=256 (NK=8).
// ---------------------------------------------------------------------------
#define VPAD 136   // smem v-transpose row stride (halves)

__global__ __launch_bounds__(256, 2) void projmma_kernel(
    const float* __restrict__ mask, const float* __restrict__ skin,
    const float* __restrict__ bq, const float* __restrict__ bk,
    const float* __restrict__ bv)
{
    extern __shared__ __align__(128) char dynsm[];
    __shared__ float fm[128];
    const int b = blockIdx.z, m0 = blockIdx.y * 128, oblk = blockIdx.x;
    const int tid = threadIdx.x, wid = tid >> 5, lane = tid & 31;
    const int wy = wid >> 2, wx = wid & 3;
    const uint32_t sb = smem_u32(dynsm);

    const int NK = 8;
    const __half* Asrc = g_xh + ((size_t)b * Nn + m0) * 256;
    const __half* Bsrc = g_wh + (size_t)oblk * 128 * 256;

    if (oblk == 1 && tid < 128)
        fm[tid] = (1.0f - mask[b * Nn + m0 + tid]) * skin[b * Nn + m0 + tid];

    #pragma unroll
    for (int s = 0; s < 2; s++) {
        uint32_t st = sb + s * STAGE_PAIR;
        load_tile(st, Asrc + s * 32, 256, tid);
        load_tile(st + TILE_B, Bsrc + s * 32, 256, tid);
        CP_COMMIT();
    }

    float acc[4][4][4] = {};
    #pragma unroll 1
    for (int s = 0; s < NK; s++) {
        if (s < NK - 1) cp_wait<1>(); else cp_wait<0>();
        __syncthreads();
        if (s + 2 < NK) {
            uint32_t ld = sb + (uint32_t)((s + 2) % NSTAGE) * STAGE_PAIR;
            load_tile(ld, Asrc + (s + 2) * 32, 256, tid);
            load_tile(ld + TILE_B, Bsrc + (s + 2) * 32, 256, tid);
            CP_COMMIT();
        }
        const uint32_t st = sb + (uint32_t)(s % NSTAGE) * STAGE_PAIR;
        warp_mma_step(acc, st, st + TILE_B, wy, wx, lane);
    }

    // Epilogue
    const float* biasp = (oblk == 0) ? bq : (oblk == 1) ? bk
                       : (oblk == 2) ? bv : (bv + 128);
    float bias0[4], bias1[4];
    #pragma unroll
    for (int nf = 0; nf < 4; nf++) {
        int o = wx * 32 + nf * 8 + (lane & 3) * 2;
        bias0[nf] = biasp[o];
        bias1[nf] = biasp[o + 1];
    }

    if (oblk <= 1) {
        #pragma unroll
        for (int mf = 0; mf < 4; mf++) {
            const int rA = wy * 64 + mf * 16 + (lane >> 2);
            const int rB = rA + 8;
            float fA = 1.0f, fB = 1.0f;
            if (oblk == 1) { fA = fm[rA]; fB = fm[rB]; }
            #pragma unroll
            for (int nf = 0; nf < 4; nf++) {
                const int o = wx * 32 + nf * 8 + (lane & 3) * 2;
                float r0 = (acc[mf][nf][0] + bias0[nf]) * fA;
                float r1 = (acc[mf][nf][1] + bias1[nf]) * fA;
                float r2 = (acc[mf][nf][2] + bias0[nf]) * fB;
                float r3 = (acc[mf][nf][3] + bias1[nf]) * fB;
                __half* dst = (oblk == 0) ? g_qc : g_kc;
                size_t oa = ((size_t)b * Nn + m0 + rA) * 128 + o;
                size_t ob = ((size_t)b * Nn + m0 + rB) * 128 + o;
                *reinterpret_cast<__half2*>(dst + oa) = __floats2half2_rn(r0, r1);
                *reinterpret_cast<__half2*>(dst + ob) = __floats2half2_rn(r2, r3);
            }
        }
    } else {
        // v: bounce through smem [c][n] tile, then coalesced g_vb writes.
        __syncthreads();   // mainloop tiles dead; reuse dynsm
        __nv_bfloat16* vsm = reinterpret_cast<__nv_bfloat16*>(dynsm);
        #pragma unroll
        for (int mf = 0; mf < 4; mf++) {
            const int rA = wy * 64 + mf * 16 + (lane >> 2);   // n-local
            const int rB = rA + 8;
            #pragma unroll
            for (int nf = 0; nf < 4; nf++) {
                const int o = wx * 32 + nf * 8 + (lane & 3) * 2;   // c-local
                vsm[o * VPAD + rA]       = __float2bfloat16(acc[mf][nf][0] + bias0[nf]);
                vsm[(o + 1) * VPAD + rA] = __float2bfloat16(acc[mf][nf][1] + bias1[nf]);
                vsm[o * VPAD + rB]       = __float2bfloat16(acc[mf][nf][2] + bias0[nf]);
                vsm[(o + 1) * VPAD + rB] = __float2bfloat16(acc[mf][nf][3] + bias1[nf]);
            }
        }
        __syncthreads();
        const int c0r = (oblk - 2) * 128;
        #pragma unroll
        for (int i = 0; i < 8; i++) {
            int f4 = tid + i * 256;           // 0..2047
            int row = f4 >> 4, c8 = (f4 & 15) * 8;
            float4 v = *reinterpret_cast<float4*>(vsm + row * VPAD + c8);
            *reinterpret_cast<float4*>(
                g_vb + ((size_t)b * Cc + c0r + row) * Nn + m0 + c8) = v;
        }
    }
}

// ---------------------------------------------------------------------------
// Kernel 2: QK^T -> P = exp(S). Multi-chunk: each block does 4 n-chunks with
// a block-resident q-tile (A) and a 3-stage B ring, prefetch distance 2
// (slot (t+2)%3 != t%3 — the distance-3 variant raced). grid (8, 32, B).
// smem: A[4 k-tiles]@0 | B ring@40960 (3x10240) | sred@71680 | pst@73728.
// ---------------------------------------------------------------------------
__global__ __launch_bounds__(256, 2) void qk_kernel()
{
    extern __shared__ __align__(128) char dynsm[];
    const int b = blockIdx.z, m0 = blockIdx.y * 128;
    const int nq = blockIdx.x;                       // 0..7 (quad of chunks)
    const int tid = threadIdx.x, wid = tid >> 5, lane = tid & 31;
    const int wy = wid >> 2, wx = wid & 3;
    const uint32_t sb = smem_u32(dynsm);

    const __half* Asrc = g_qc + ((size_t)b * Nn + m0) * 128;
    const __half* Bbase = g_kc + ((size_t)b * Nn + nq * 512) * 128;

    float* sred = reinterpret_cast<float*>(dynsm + QK_SRED);
    __nv_bfloat16* pst = reinterpret_cast<__nv_bfloat16*>(dynsm + QK_PST);

    // Prologue: resident A (4 k-tiles, one group), then B for t = 0,1.
    #pragma unroll
    for (int kt = 0; kt < 4; kt++)
        load_tile(sb + (uint32_t)kt * TILE_B, Asrc + kt * 32, 128, tid);
    CP_COMMIT();
    #pragma unroll
    for (int t = 0; t < 2; t++) {
        load_tile(sb + QK_BOFF + (uint32_t)t * TILE_B,
                  Bbase + (size_t)((t >> 2) * 128) * 128 + (t & 3) * 32, 128, tid);
        CP_COMMIT();
    }

    float acc[4][4][4] = {};
    #pragma unroll 1
    for (int t = 0; t < 16; t++) {
        if (t < 15) cp_wait<1>(); else cp_wait<0>();
        __syncthreads();
        if (t + 2 < 16) {
            int tp = t + 2;
            load_tile(sb + QK_BOFF + (uint32_t)(tp % 3) * TILE_B,
                      Bbase + (size_t)((tp >> 2) * 128) * 128 + (tp & 3) * 32, 128, tid);
            CP_COMMIT();
        }
        warp_mma_step(acc, sb + (uint32_t)(t & 3) * TILE_B,
                      sb + QK_BOFF + (uint32_t)(t % 3) * TILE_B, wy, wx, lane);

        if ((t & 3) == 3) {
            // ---- epilogue for chunk (t>>2): exp, stage P, row sums, writeout ----
            const int gch = nq * 4 + (t >> 2);       // global chunk 0..31
            const int n0 = gch * 128;

            float rsum[4][2];
            #pragma unroll
            for (int mf = 0; mf < 4; mf++) {
                int rA = wy * 64 + mf * 16 + (lane >> 2);
                int rB = rA + 8;
                float sA = 0.0f, sB = 0.0f;
                #pragma unroll
                for (int nf = 0; nf < 4; nf++) {
                    float p0 = fexp(acc[mf][nf][0]);
                    float p1 = fexp(acc[mf][nf][1]);
                    float p2 = fexp(acc[mf][nf][2]);
                    float p3 = fexp(acc[mf][nf][3]);
                    sA += p0 + p1; sB += p2 + p3;
                    int cl = wx * 32 + nf * 8 + (lane & 3) * 2;
                    *reinterpret_cast<__nv_bfloat162*>(pst + rA * PSTR + cl) = __floats2bfloat162_rn(p0, p1);
                    *reinterpret_cast<__nv_bfloat162*>(pst + rB * PSTR + cl) = __floats2bfloat162_rn(p2, p3);
                }
                rsum[mf][0] = sA; rsum[mf][1] = sB;
            }
            #pragma unroll
            for (int o = 1; o <= 2; o <<= 1)
                #pragma unroll
                for (int mf = 0; mf < 4; mf++) {
                    rsum[mf][0] += __shfl_xor_sync(0xffffffffu, rsum[mf][0], o);
                    rsum[mf][1] += __shfl_xor_sync(0xffffffffu, rsum[mf][1], o);
                }
            if ((lane & 3) == 0) {
                #pragma unroll
                for (int mf = 0; mf < 4; mf++) {
                    int rA = wy * 64 + mf * 16 + (lane >> 2);
                    sred[wx * 128 + rA]     = rsum[mf][0];
                    sred[wx * 128 + rA + 8] = rsum[mf][1];
                }
            }
            __syncthreads();
            if (tid < 128) {
                float se = sred[tid] + sred[128 + tid] + sred[256 + tid] + sred[384 + tid];
                g_sumexp[((size_t)b * Nn + m0 + tid) * 32 + gch] = se;
            }
            #pragma unroll
            for (int i = 0; i < 8; i++) {
                int f4 = tid + i * 256;
                int row = f4 >> 4, c8 = (f4 & 15) * 8;
                float4 v = *reinterpret_cast<float4*>(pst + row * PSTR + c8);
                *reinterpret_cast<float4*>(
                    g_attb + ((size_t)b * Nn + m0 + row) * Nn + n0 + c8) = v;
            }
            // reset acc for next chunk
            #pragma unroll
            for (int mf = 0; mf < 4; mf++)
                #pragma unroll
                for (int nf = 0; nf < 4; nf++)
                    #pragma unroll
                    for (int k = 0; k < 4; k++) acc[mf][nf][k] = 0.0f;
        }
    }
}

// ---------------------------------------------------------------------------
// Kernel 4: AV via mma.sync bf16 (clean loop) + epilogue normalization
// grid (2 ctile, 32 mtile, B), 256 threads, dynamic smem 61440
// ---------------------------------------------------------------------------
__global__ __launch_bounds__(256, 2) void av_kernel(
    const float* __restrict__ x, const float* __restrict__ mask,
    const float* __restrict__ skin, const float* __restrict__ gamma,
    float* __restrict__ out)
{
    extern __shared__ __align__(128) char dynsm[];
    __shared__ float fmv[128];
    __shared__ float szv[128];
    const int b = blockIdx.z, m0 = blockIdx.y * 128, c0 = blockIdx.x * 128;
    const int tid = threadIdx.x, wid = tid >> 5, lane = tid & 31;
    const int wy = wid >> 2, wx = wid & 3;
    const uint32_t sb = smem_u32(dynsm);

    if (tid < 128) {
        fmv[tid] = mask[(size_t)b * Nn + m0 + tid] * skin[(size_t)b * Nn + m0 + tid];
        const float4* sp = reinterpret_cast<const float4*>(
            g_sumexp + ((size_t)b * Nn + m0 + tid) * 32);
        float s = 0.0f;
        #pragma unroll
        for (int i = 0; i < 8; i++) {
            float4 v = sp[i];
            s += (v.x + v.y) + (v.z + v.w);
        }
        szv[tid] = 1.0f / s;
    }

    const __half* Asrc = reinterpret_cast<const __half*>(g_attb + ((size_t)b * Nn + m0) * Nn);
    const __half* Bsrc = reinterpret_cast<const __half*>(g_vb + ((size_t)b * Cc + c0) * Nn);

    const int NK = Nn / 32;   // 128
    #pragma unroll
    for (int s = 0; s < 2; s++) {
        uint32_t st = sb + s * STAGE_PAIR;
        load_tile(st, Asrc + s * 32, Nn, tid);
        load_tile(st + TILE_B, Bsrc + s * 32, Nn, tid);
        CP_COMMIT();
    }

    float acc[4][4][4] = {};
    #pragma unroll 1
    for (int s = 0; s < NK; s++) {
        if (s < NK - 1) cp_wait<1>(); else cp_wait<0>();
        __syncthreads();
        if (s + 2 < NK) {
            uint32_t ld = sb + (uint32_t)((s + 2) % NSTAGE) * STAGE_PAIR;
            load_tile(ld, Asrc + (s + 2) * 32, Nn, tid);
            load_tile(ld + TILE_B, Bsrc + (s + 2) * 32, Nn, tid);
            CP_COMMIT();
        }
        const uint32_t st = sb + (uint32_t)(s % NSTAGE) * STAGE_PAIR;
        warp_mma_step_bf(acc, st, st + TILE_B, wy, wx, lane);
    }

    // Fused epilogue: out[c][m] = gamma*fm[m]*zinv[m]*D[m][c] + x[c][m]
    const float gm = __ldg(gamma);
    #pragma unroll
    for (int mf = 0; mf < 4; mf++) {
        const int ml = wy * 64 + mf * 16 + (lane >> 2);    // local m (0..127)
        const float f0 = gm * fmv[ml] * szv[ml];
        const float f1 = gm * fmv[ml + 8] * szv[ml + 8];
        #pragma unroll
        for (int nf = 0; nf < 4; nf++) {
            const int c = c0 + wx * 32 + nf * 8 + (lane & 3) * 2;
            const size_t b0i = ((size_t)b * Cc + c) * Nn + m0 + ml;
            const size_t b1i = b0i + Nn;   // c+1
            out[b0i]     = fmaf(f0, acc[mf][nf][0], x[b0i]);
            out[b1i]     = fmaf(f0, acc[mf][nf][1], x[b1i]);
            out[b0i + 8] = fmaf(f1, acc[mf][nf][2], x[b0i + 8]);
            out[b1i + 8] = fmaf(f1, acc[mf][nf][3], x[b1i + 8]);
        }
    }
}

// ---------------------------------------------------------------------------
extern "C" void kernel_launch(void* const* d_in, const int* in_sizes, int n_in,
                              void* d_out, int out_size)
{
    (void)in_sizes; (void)n_in; (void)out_size;
    const float* x     = (const float*)d_in[0];
    const float* mask  = (const float*)d_in[1];
    const float* skin  = (const float*)d_in[2];
    const float* Wq    = (const float*)d_in[3];
    const float* bq    = (const float*)d_in[4];
    const float* Wk    = (const float*)d_in[5];
    const float* bk    = (const float*)d_in[6];
    const float* Wv    = (const float*)d_in[7];
    const float* bv    = (const float*)d_in[8];
    const float* gamma = (const float*)d_in[9];
    float* out = (float*)d_out;

    cudaFuncSetAttribute(projmma_kernel, cudaFuncAttributeMaxDynamicSharedMemorySize, DYN_SMEM);
    cudaFuncSetAttribute(qk_kernel, cudaFuncAttributeMaxDynamicSharedMemorySize, DYN_QK);
    cudaFuncSetAttribute(av_kernel, cudaFuncAttributeMaxDynamicSharedMemorySize, DYN_SMEM);

    dim3 gX(64, 4, Bb);
    xcvt_kernel<<<gX, 256>>>(x);

    wcvt_kernel<<<128, 256>>>(Wq, Wk, Wv);

    dim3 gP(4, 32, Bb);
    projmma_kernel<<<gP, 256, DYN_SMEM>>>(mask, skin, bq, bk, bv);

    dim3 gQK(8, 32, Bb);
    qk_kernel<<<gQK, 256, DYN_QK>>>();

    dim3 gAV(2, 32, Bb);
    av_kernel<<<gAV, 256, DYN_SMEM>>>(x, mask, skin, gamma, out);
}